// round 5
// baseline (speedup 1.0000x reference)
#include <cuda_runtime.h>
#include <cuda_bf16.h>
#include <math.h>
#include <stdint.h>

// Problem constants
#define B  2
#define S  2048
#define D  1024
#define H  16
#define DK 64
#define M_ROWS (B * S)   // 4096
#define GK 1024
#define GN 1024

// ---------------- scratch (device globals: allocation-free) ----------------
__device__ float g_Q[M_ROWS * D];
__device__ float g_K[M_ROWS * D];
__device__ float g_V[M_ROWS * D];
__device__ float g_C[M_ROWS * D];
__device__ __nv_bfloat16 g_Ah[M_ROWS * D];   // activation hi
__device__ __nv_bfloat16 g_Al[M_ROWS * D];   // activation lo
__device__ __nv_bfloat16 g_Bh[D * D];        // W^T hi  [n][k]
__device__ __nv_bfloat16 g_Bl[D * D];        // W^T lo  [n][k]

__device__ __forceinline__ uint32_t smem_u32(const void* p) {
    uint32_t a;
    asm("{ .reg .u64 t; cvta.to.shared.u64 t, %1; cvt.u32.u64 %0, t; }"
        : "=r"(a) : "l"(p));
    return a;
}

// ---------------- split kernels (fp32 -> bf16 hi/lo) ----------------
__global__ __launch_bounds__(256) void split_act_kernel(
    const float* __restrict__ X, __nv_bfloat16* __restrict__ Xh,
    __nv_bfloat16* __restrict__ Xl, int n4)
{
    int i = blockIdx.x * 256 + threadIdx.x;
    if (i >= n4) return;
    float4 v = ((const float4*)X)[i];
    float f[4] = {v.x, v.y, v.z, v.w};
    __nv_bfloat16 h[4], l[4];
#pragma unroll
    for (int j = 0; j < 4; j++) {
        h[j] = __float2bfloat16(f[j]);
        l[j] = __float2bfloat16(f[j] - __bfloat162float(h[j]));
    }
    *(__nv_bfloat162*)&Xh[i * 4 + 0] = __nv_bfloat162(h[0], h[1]);
    *(__nv_bfloat162*)&Xh[i * 4 + 2] = __nv_bfloat162(h[2], h[3]);
    *(__nv_bfloat162*)&Xl[i * 4 + 0] = __nv_bfloat162(l[0], l[1]);
    *(__nv_bfloat162*)&Xl[i * 4 + 2] = __nv_bfloat162(l[2], l[3]);
}

// W[k][n] fp32 -> Wt_h[n][k], Wt_l[n][k] bf16  (transpose + split)
__global__ __launch_bounds__(256) void split_wt_kernel(
    const float* __restrict__ W, __nv_bfloat16* __restrict__ Wth,
    __nv_bfloat16* __restrict__ Wtl)
{
    __shared__ float t[32][33];
    int k0 = blockIdx.y * 32, n0 = blockIdx.x * 32;
    int tx = threadIdx.x & 31, ty = threadIdx.x >> 5;   // ty 0..7
#pragma unroll
    for (int i = 0; i < 4; i++)
        t[ty + i * 8][tx] = W[(size_t)(k0 + ty + i * 8) * D + n0 + tx];
    __syncthreads();
#pragma unroll
    for (int i = 0; i < 4; i++) {
        float v = t[tx][ty + i * 8];
        __nv_bfloat16 h = __float2bfloat16(v);
        __nv_bfloat16 l = __float2bfloat16(v - __bfloat162float(h));
        size_t o = (size_t)(n0 + ty + i * 8) * D + k0 + tx;
        Wth[o] = h;
        Wtl[o] = l;
    }
}

// ---------------- bf16x3 GEMM via warp-level mma.sync (portable PTX) ------
// C[M,N] = A[M,K] @ W[K,N] + bias,  B = W^T stored [n][k] (K-major).
// CTA tile 128x128, BK=32, 8 warps (4m x 2n), warp tile 32x64 (m16n8k16).
// SMEM rows of 64B data stored with 80B stride -> conflict-free ldmatrix.
#define BK 32
#define NCH (GK / BK)            // 32
#define TILE_SB (128 * 80)       // 10240 B per operand tile
#define STAGE_SB (4 * TILE_SB)   // 40960
#define GEMM_SMEM (2 * STAGE_SB) // 81920

__device__ __forceinline__ void ldsm_x4(uint32_t (&r)[4], uint32_t addr) {
    asm volatile("ldmatrix.sync.aligned.m8n8.x4.shared.b16 {%0,%1,%2,%3}, [%4];"
                 : "=r"(r[0]), "=r"(r[1]), "=r"(r[2]), "=r"(r[3]) : "r"(addr));
}
__device__ __forceinline__ void mma_bf16(float (&d)[4],
    const uint32_t (&a)[4], uint32_t b0, uint32_t b1)
{
    asm volatile(
        "mma.sync.aligned.m16n8k16.row.col.f32.bf16.bf16.f32 "
        "{%0,%1,%2,%3}, {%4,%5,%6,%7}, {%8,%9}, {%0,%1,%2,%3};"
        : "+f"(d[0]), "+f"(d[1]), "+f"(d[2]), "+f"(d[3])
        : "r"(a[0]), "r"(a[1]), "r"(a[2]), "r"(a[3]), "r"(b0), "r"(b1));
}

__global__ __launch_bounds__(256) void gemm_bf16x3_kernel(
    const __nv_bfloat16* __restrict__ Ah, const __nv_bfloat16* __restrict__ Al,
    const __nv_bfloat16* __restrict__ Bh, const __nv_bfloat16* __restrict__ Bl,
    const float* __restrict__ bias, float* __restrict__ C)
{
    extern __shared__ char smem[];
    const uint32_t sbase = smem_u32(smem);
    const int tid = threadIdx.x;
    const int lane = tid & 31;
    const int wid = tid >> 5;
    const int warp_m = wid & 3;      // 0..3 -> 32 rows each
    const int warp_n = wid >> 2;     // 0..1 -> 64 cols each
    const int m0 = blockIdx.y * 128;
    const int n0 = blockIdx.x * 128;

    const __nv_bfloat16* gt[4];
    gt[0] = Ah + (size_t)m0 * GK;
    gt[1] = Al + (size_t)m0 * GK;
    gt[2] = Bh + (size_t)n0 * GK;
    gt[3] = Bl + (size_t)n0 * GK;

    // stage loader: 4 tiles x 128 rows x 4 chunks(16B); 2 chunks/thread/tile
    auto load_stage = [&](uint32_t stoff, int kc0) {
#pragma unroll
        for (int t = 0; t < 4; t++) {
            uint32_t tb = sbase + stoff + t * TILE_SB;
            const __nv_bfloat16* g = gt[t];
#pragma unroll
            for (int j = 0; j < 2; j++) {
                int i = tid + j * 256;           // 0..511
                int row = i >> 2, c = i & 3;
                uint32_t sd = tb + row * 80 + c * 16;
                const void* gs = g + (size_t)row * GK + kc0 + c * 8;
                asm volatile("cp.async.cg.shared.global [%0], [%1], 16;"
                             :: "r"(sd), "l"(gs));
            }
        }
        asm volatile("cp.async.commit_group;");
    };

    float acc[2][8][4];
#pragma unroll
    for (int i = 0; i < 2; i++)
#pragma unroll
        for (int j = 0; j < 8; j++)
#pragma unroll
            for (int v = 0; v < 4; v++) acc[i][j][v] = 0.f;

    load_stage(0, 0);
    load_stage(STAGE_SB, BK);

    // precomputed ldmatrix lane addressing
    const int a_row = lane & 15;             // row within 16-row tile
    const int a_kc  = lane >> 4;             // 16B chunk within k16
    const int bg    = lane >> 3;             // 0..3
    const int b_row = ((bg >> 1) * 8) + (lane & 7);
    const int b_kc  = bg & 1;

    for (int ch = 0; ch < NCH; ch++) {
        if (ch < NCH - 1) asm volatile("cp.async.wait_group 1;");
        else              asm volatile("cp.async.wait_group 0;");
        __syncthreads();

        const uint32_t st = sbase + (ch & 1) * STAGE_SB;
        const uint32_t sAh = st, sAl = st + TILE_SB;
        const uint32_t sBh = st + 2 * TILE_SB, sBl = st + 3 * TILE_SB;

#pragma unroll
        for (int kc = 0; kc < 2; kc++) {   // two k16 chunks in BK=32
            uint32_t ah[2][4], al[2][4], bh[4][4], bl[4][4];
#pragma unroll
            for (int mt = 0; mt < 2; mt++) {
                uint32_t ro = (warp_m * 32 + mt * 16 + a_row) * 80
                            + (kc * 2 + a_kc) * 16;
                ldsm_x4(ah[mt], sAh + ro);
                ldsm_x4(al[mt], sAl + ro);
            }
#pragma unroll
            for (int ng = 0; ng < 4; ng++) {
                uint32_t ro = (warp_n * 64 + ng * 16 + b_row) * 80
                            + (kc * 2 + b_kc) * 16;
                ldsm_x4(bh[ng], sBh + ro);
                ldsm_x4(bl[ng], sBl + ro);
            }
#pragma unroll
            for (int mt = 0; mt < 2; mt++)
#pragma unroll
                for (int ng = 0; ng < 4; ng++) {
                    mma_bf16(acc[mt][ng * 2 + 0], ah[mt], bh[ng][0], bh[ng][1]);
                    mma_bf16(acc[mt][ng * 2 + 1], ah[mt], bh[ng][2], bh[ng][3]);
                    mma_bf16(acc[mt][ng * 2 + 0], ah[mt], bl[ng][0], bl[ng][1]);
                    mma_bf16(acc[mt][ng * 2 + 1], ah[mt], bl[ng][2], bl[ng][3]);
                    mma_bf16(acc[mt][ng * 2 + 0], al[mt], bh[ng][0], bh[ng][1]);
                    mma_bf16(acc[mt][ng * 2 + 1], al[mt], bh[ng][2], bh[ng][3]);
                }
        }
        __syncthreads();
        if (ch + 2 < NCH) load_stage((ch & 1) * STAGE_SB, (ch + 2) * BK);
    }

    // epilogue: frag layout m16n8: lane -> (row = lane>>2 (+8), col = (lane&3)*2)
    const int grp = lane >> 2, tg = lane & 3;
#pragma unroll
    for (int mt = 0; mt < 2; mt++) {
        int r0 = m0 + warp_m * 32 + mt * 16 + grp;
#pragma unroll
        for (int nt = 0; nt < 8; nt++) {
            int c = n0 + warp_n * 64 + nt * 8 + tg * 2;
            float2 b2 = *(const float2*)&bias[c];
            float2 o0, o1;
            o0.x = acc[mt][nt][0] + b2.x;
            o0.y = acc[mt][nt][1] + b2.y;
            o1.x = acc[mt][nt][2] + b2.x;
            o1.y = acc[mt][nt][3] + b2.y;
            *(float2*)&C[(size_t)r0 * GN + c] = o0;
            *(float2*)&C[(size_t)(r0 + 8) * GN + c] = o1;
        }
    }
}

// ---------------- Attention: tiled flash, 64x64 score tile / block -------
#define QTILE 64
#define PAD   68

__global__ __launch_bounds__(256) void attention_kernel(
    const float* __restrict__ Q, const float* __restrict__ K,
    const float* __restrict__ V, const int* __restrict__ mask,
    float* __restrict__ Ctx)
{
    extern __shared__ float sm[];
    float* Qt  = sm;
    float* KPt = Qt + QTILE * PAD;
    float* Vs  = KPt + QTILE * PAD;
    int*   ms  = (int*)(Vs + QTILE * PAD);

    const int b  = blockIdx.z;
    const int h  = blockIdx.y;
    const int q0 = blockIdx.x * QTILE;
    const int tid = threadIdx.x;
    const int tx = tid & 15;
    const int ty = tid >> 4;
    const int dg  = tid & 15;
    const int row = tid >> 4;

#pragma unroll
    for (int i = 0; i < 4; i++) {
        int r = row + i * 16;
        float4 qv = *(const float4*)&Q[((size_t)b * S + q0 + r) * D + h * DK + dg * 4];
        Qt[(dg * 4 + 0) * PAD + r] = qv.x;
        Qt[(dg * 4 + 1) * PAD + r] = qv.y;
        Qt[(dg * 4 + 2) * PAD + r] = qv.z;
        Qt[(dg * 4 + 3) * PAD + r] = qv.w;
    }

    float acc[4][4];
#pragma unroll
    for (int i = 0; i < 4; i++)
#pragma unroll
        for (int j = 0; j < 4; j++) acc[i][j] = 0.f;
    float mrow[4] = {-1e30f, -1e30f, -1e30f, -1e30f};
    float lrow[4] = {0.f, 0.f, 0.f, 0.f};
    const float scale = 0.125f;

    for (int kk = 0; kk < S; kk += QTILE) {
        __syncthreads();
#pragma unroll
        for (int i = 0; i < 4; i++) {
            int r = row + i * 16;
            size_t g = ((size_t)b * S + kk + r) * D + h * DK + dg * 4;
            float4 kv = *(const float4*)&K[g];
            KPt[(dg * 4 + 0) * PAD + r] = kv.x;
            KPt[(dg * 4 + 1) * PAD + r] = kv.y;
            KPt[(dg * 4 + 2) * PAD + r] = kv.z;
            KPt[(dg * 4 + 3) * PAD + r] = kv.w;
            *(float4*)&Vs[r * PAD + dg * 4] = *(const float4*)&V[g];
        }
        if (tid < QTILE) ms[tid] = mask[(size_t)b * S + kk + tid];
        __syncthreads();

        float s[4][4];
#pragma unroll
        for (int i = 0; i < 4; i++)
#pragma unroll
            for (int j = 0; j < 4; j++) s[i][j] = 0.f;

#pragma unroll
        for (int d = 0; d < QTILE; d++) {
            float4 a = *(const float4*)&Qt[d * PAD + ty * 4];
            float4 bf = *(const float4*)&KPt[d * PAD + tx * 4];
            float af[4] = {a.x, a.y, a.z, a.w};
            float bfr[4] = {bf.x, bf.y, bf.z, bf.w};
#pragma unroll
            for (int i = 0; i < 4; i++)
#pragma unroll
                for (int j = 0; j < 4; j++)
                    s[i][j] += af[i] * bfr[j];
        }

        bool cmask[4];
#pragma unroll
        for (int j = 0; j < 4; j++) cmask[j] = (ms[tx * 4 + j] != 0);

        float corr[4];
#pragma unroll
        for (int i = 0; i < 4; i++) {
            float rmax = -1e30f;
#pragma unroll
            for (int j = 0; j < 4; j++) {
                float se = cmask[j] ? -1e30f : s[i][j] * scale;
                s[i][j] = se;
                rmax = fmaxf(rmax, se);
            }
#pragma unroll
            for (int off = 1; off < 16; off <<= 1)
                rmax = fmaxf(rmax, __shfl_xor_sync(0xffffffffu, rmax, off));

            float mnew = fmaxf(mrow[i], rmax);
            corr[i] = __expf(mrow[i] - mnew);
            float rsum = 0.f;
#pragma unroll
            for (int j = 0; j < 4; j++) {
                float p = cmask[j] ? 0.f : __expf(s[i][j] - mnew);
                s[i][j] = p;
                rsum += p;
            }
#pragma unroll
            for (int off = 1; off < 16; off <<= 1)
                rsum += __shfl_xor_sync(0xffffffffu, rsum, off);

            lrow[i] = lrow[i] * corr[i] + rsum;
            mrow[i] = mnew;
#pragma unroll
            for (int j = 0; j < 4; j++) acc[i][j] *= corr[i];
        }

        __syncthreads();
#pragma unroll
        for (int j = 0; j < 4; j++) {
            float4 pv = make_float4(s[0][j], s[1][j], s[2][j], s[3][j]);
            *(float4*)&KPt[(tx * 4 + j) * PAD + ty * 4] = pv;
        }
        __syncthreads();

#pragma unroll
        for (int c = 0; c < QTILE; c++) {
            float4 a = *(const float4*)&KPt[c * PAD + ty * 4];
            float4 bf = *(const float4*)&Vs[c * PAD + tx * 4];
            float af[4] = {a.x, a.y, a.z, a.w};
            float bfr[4] = {bf.x, bf.y, bf.z, bf.w};
#pragma unroll
            for (int i = 0; i < 4; i++)
#pragma unroll
                for (int j = 0; j < 4; j++)
                    acc[i][j] += af[i] * bfr[j];
        }
    }

#pragma unroll
    for (int i = 0; i < 4; i++) {
        float inv = (lrow[i] > 0.f) ? (1.f / lrow[i]) : 0.f;
        int r = q0 + ty * 4 + i;
        float4 o;
        o.x = acc[i][0] * inv;
        o.y = acc[i][1] * inv;
        o.z = acc[i][2] * inv;
        o.w = acc[i][3] * inv;
        *(float4*)&Ctx[((size_t)b * S + r) * D + h * DK + tx * 4] = o;
    }
}

// ---------------- launch ----------------
extern "C" void kernel_launch(void* const* d_in, const int* in_sizes, int n_in,
                              void* d_out, int out_size)
{
    const float* query = (const float*)d_in[0];
    const float* key   = (const float*)d_in[1];
    const float* value = (const float*)d_in[2];
    const int*   mask  = (const int*)d_in[3];
    const float* Wq = (const float*)d_in[4];
    const float* bq = (const float*)d_in[5];
    const float* Wk = (const float*)d_in[6];
    const float* bk = (const float*)d_in[7];
    const float* Wv = (const float*)d_in[8];
    const float* bv = (const float*)d_in[9];
    const float* Wo = (const float*)d_in[10];
    const float* bo = (const float*)d_in[11];
    float* out = (float*)d_out;

    float *qbuf, *kbuf, *vbuf, *cbuf;
    __nv_bfloat16 *ah, *al, *bh, *bl;
    cudaGetSymbolAddress((void**)&qbuf, g_Q);
    cudaGetSymbolAddress((void**)&kbuf, g_K);
    cudaGetSymbolAddress((void**)&vbuf, g_V);
    cudaGetSymbolAddress((void**)&cbuf, g_C);
    cudaGetSymbolAddress((void**)&ah, g_Ah);
    cudaGetSymbolAddress((void**)&al, g_Al);
    cudaGetSymbolAddress((void**)&bh, g_Bh);
    cudaGetSymbolAddress((void**)&bl, g_Bl);

    const int attn_smem = (3 * QTILE * PAD) * 4 + QTILE * 4;
    static int attr_set = 0;
    if (!attr_set) {
        cudaFuncSetAttribute(attention_kernel,
                             cudaFuncAttributeMaxDynamicSharedMemorySize, attn_smem);
        cudaFuncSetAttribute(gemm_bf16x3_kernel,
                             cudaFuncAttributeMaxDynamicSharedMemorySize, GEMM_SMEM);
        attr_set = 1;
    }

    const int n4_act = M_ROWS * D / 4;
    dim3 sa_grid((n4_act + 255) / 256);
    dim3 sw_grid(D / 32, D / 32);
    dim3 gemm_grid(GN / 128, M_ROWS / 128);   // (8, 32)

    // Q projection
    split_act_kernel<<<sa_grid, 256>>>(query, ah, al, n4_act);
    split_wt_kernel<<<sw_grid, 256>>>(Wq, bh, bl);
    gemm_bf16x3_kernel<<<gemm_grid, 256, GEMM_SMEM>>>(ah, al, bh, bl, bq, qbuf);
    // K projection
    split_act_kernel<<<sa_grid, 256>>>(key, ah, al, n4_act);
    split_wt_kernel<<<sw_grid, 256>>>(Wk, bh, bl);
    gemm_bf16x3_kernel<<<gemm_grid, 256, GEMM_SMEM>>>(ah, al, bh, bl, bk, kbuf);
    // V projection
    split_act_kernel<<<sa_grid, 256>>>(value, ah, al, n4_act);
    split_wt_kernel<<<sw_grid, 256>>>(Wv, bh, bl);
    gemm_bf16x3_kernel<<<gemm_grid, 256, GEMM_SMEM>>>(ah, al, bh, bl, bv, vbuf);

    // Attention
    dim3 attn_grid(S / QTILE, H, B);
    attention_kernel<<<attn_grid, 256, attn_smem>>>(qbuf, kbuf, vbuf, mask, cbuf);

    // Output projection
    split_act_kernel<<<sa_grid, 256>>>(cbuf, ah, al, n4_act);
    split_wt_kernel<<<sw_grid, 256>>>(Wo, bh, bl);
    gemm_bf16x3_kernel<<<gemm_grid, 256, GEMM_SMEM>>>(ah, al, bh, bl, bo, out);
}

// round 6
// speedup vs baseline: 1.5780x; 1.5780x over previous
#include <cuda_runtime.h>
#include <cuda_bf16.h>
#include <math.h>
#include <stdint.h>

// Problem constants
#define B  2
#define S  2048
#define D  1024
#define H  16
#define DK 64
#define M_ROWS (B * S)   // 4096
#define GK 1024
#define GN 1024

// ---------------- scratch (device globals: allocation-free) ----------------
__device__ float g_Q[M_ROWS * D];
__device__ float g_K[M_ROWS * D];
__device__ float g_V[M_ROWS * D];
__device__ float g_C[M_ROWS * D];
// per-projection activation hi/lo (q,k,v,c)
__device__ __nv_bfloat16 g_Ah[4][M_ROWS * D];
__device__ __nv_bfloat16 g_Al[4][M_ROWS * D];
// per-weight W^T hi/lo [n][k] (q,k,v,o)
__device__ __nv_bfloat16 g_Bh[4][D * D];
__device__ __nv_bfloat16 g_Bl[4][D * D];

__device__ __forceinline__ uint32_t smem_u32(const void* p) {
    uint32_t a;
    asm("{ .reg .u64 t; cvta.to.shared.u64 t, %1; cvt.u32.u64 %0, t; }"
        : "=r"(a) : "l"(p));
    return a;
}

// ---------------- split kernels (fp32 -> bf16 hi/lo) ----------------
__global__ __launch_bounds__(256) void split_act_kernel(
    const float* __restrict__ X, __nv_bfloat16* __restrict__ Xh,
    __nv_bfloat16* __restrict__ Xl, int n4)
{
    int i = blockIdx.x * 256 + threadIdx.x;
    if (i >= n4) return;
    float4 v = ((const float4*)X)[i];
    float f[4] = {v.x, v.y, v.z, v.w};
    __nv_bfloat16 h[4], l[4];
#pragma unroll
    for (int j = 0; j < 4; j++) {
        h[j] = __float2bfloat16(f[j]);
        l[j] = __float2bfloat16(f[j] - __bfloat162float(h[j]));
    }
    *(__nv_bfloat162*)&Xh[i * 4 + 0] = __nv_bfloat162(h[0], h[1]);
    *(__nv_bfloat162*)&Xh[i * 4 + 2] = __nv_bfloat162(h[2], h[3]);
    *(__nv_bfloat162*)&Xl[i * 4 + 0] = __nv_bfloat162(l[0], l[1]);
    *(__nv_bfloat162*)&Xl[i * 4 + 2] = __nv_bfloat162(l[2], l[3]);
}

// W[k][n] fp32 -> Wt_h[n][k], Wt_l[n][k] bf16  (transpose + split)
__global__ __launch_bounds__(256) void split_wt_kernel(
    const float* __restrict__ W, __nv_bfloat16* __restrict__ Wth,
    __nv_bfloat16* __restrict__ Wtl)
{
    __shared__ float t[32][33];
    int k0 = blockIdx.y * 32, n0 = blockIdx.x * 32;
    int tx = threadIdx.x & 31, ty = threadIdx.x >> 5;   // ty 0..7
#pragma unroll
    for (int i = 0; i < 4; i++)
        t[ty + i * 8][tx] = W[(size_t)(k0 + ty + i * 8) * D + n0 + tx];
    __syncthreads();
#pragma unroll
    for (int i = 0; i < 4; i++) {
        float v = t[tx][ty + i * 8];
        __nv_bfloat16 h = __float2bfloat16(v);
        __nv_bfloat16 l = __float2bfloat16(v - __bfloat162float(h));
        size_t o = (size_t)(n0 + ty + i * 8) * D + k0 + tx;
        Wth[o] = h;
        Wtl[o] = l;
    }
}

// ---------------- bf16x3 GEMM via warp-level mma.sync ------
// C[M,N] = A[M,K] @ W[K,N] + bias,  B = W^T stored [n][k] (K-major).
// CTA tile 128x64, BK=32, 8 warps (4m x 2n), warp tile 32x32 (m16n8k16).
// 3-stage cp.async pipeline. SMEM rows 64B data @ 80B stride (conflict-free ldsm).
#define BK 32
#define NCH (GK / BK)            // 32
#define OFF_AL 10240             // 128*80
#define OFF_BH 20480
#define OFF_BL 25600             // 20480 + 64*80
#define STAGE_SB 30720           // 128*80*2 + 64*80*2
#define GEMM_SMEM (3 * STAGE_SB) // 92160

__device__ __forceinline__ void ldsm_x4(uint32_t (&r)[4], uint32_t addr) {
    asm volatile("ldmatrix.sync.aligned.m8n8.x4.shared.b16 {%0,%1,%2,%3}, [%4];"
                 : "=r"(r[0]), "=r"(r[1]), "=r"(r[2]), "=r"(r[3]) : "r"(addr));
}
__device__ __forceinline__ void mma_bf16(float (&d)[4],
    const uint32_t (&a)[4], uint32_t b0, uint32_t b1)
{
    asm volatile(
        "mma.sync.aligned.m16n8k16.row.col.f32.bf16.bf16.f32 "
        "{%0,%1,%2,%3}, {%4,%5,%6,%7}, {%8,%9}, {%0,%1,%2,%3};"
        : "+f"(d[0]), "+f"(d[1]), "+f"(d[2]), "+f"(d[3])
        : "r"(a[0]), "r"(a[1]), "r"(a[2]), "r"(a[3]), "r"(b0), "r"(b1));
}
__device__ __forceinline__ void cpa16(uint32_t sd, const void* gs) {
    asm volatile("cp.async.cg.shared.global [%0], [%1], 16;" :: "r"(sd), "l"(gs));
}

__global__ __launch_bounds__(256, 2) void gemm_bf16x3_kernel(
    const __nv_bfloat16* __restrict__ Ah, const __nv_bfloat16* __restrict__ Al,
    const __nv_bfloat16* __restrict__ Bh, const __nv_bfloat16* __restrict__ Bl,
    const float* __restrict__ bias, float* __restrict__ C)
{
    extern __shared__ char smem[];
    const uint32_t sbase = smem_u32(smem);
    const int tid = threadIdx.x;
    const int lane = tid & 31;
    const int wid = tid >> 5;
    const int warp_m = wid & 3;      // 4 x 32 rows
    const int warp_n = wid >> 2;     // 2 x 32 cols
    const int m0 = blockIdx.y * 128;
    const int n0 = blockIdx.x * 64;

    const __nv_bfloat16* gAh = Ah + (size_t)m0 * GK;
    const __nv_bfloat16* gAl = Al + (size_t)m0 * GK;
    const __nv_bfloat16* gBh = Bh + (size_t)n0 * GK;
    const __nv_bfloat16* gBl = Bl + (size_t)n0 * GK;

    const int lrow = tid >> 2;       // 0..63
    const int lc   = tid & 3;        // 16B chunk

    auto load_stage = [&](int stg, int k0) {
        uint32_t sb = sbase + stg * STAGE_SB;
#pragma unroll
        for (int j = 0; j < 2; j++) {
            int row = lrow + j * 64;
            uint32_t so = row * 80 + lc * 16;
            size_t go = (size_t)row * GK + k0 + lc * 8;
            cpa16(sb + so,          gAh + go);
            cpa16(sb + OFF_AL + so, gAl + go);
        }
        {
            uint32_t so = lrow * 80 + lc * 16;
            size_t go = (size_t)lrow * GK + k0 + lc * 8;
            cpa16(sb + OFF_BH + so, gBh + go);
            cpa16(sb + OFF_BL + so, gBl + go);
        }
        asm volatile("cp.async.commit_group;");
    };

    float acc[2][4][4];
#pragma unroll
    for (int i = 0; i < 2; i++)
#pragma unroll
        for (int j = 0; j < 4; j++)
#pragma unroll
            for (int v = 0; v < 4; v++) acc[i][j][v] = 0.f;

    load_stage(0, 0);
    load_stage(1, BK);

    // ldmatrix lane addressing
    const int a_row = lane & 15;
    const int a_kc  = lane >> 4;
    const int bg    = lane >> 3;
    const int b_row = ((bg >> 1) * 8) + (lane & 7);
    const int b_kc  = bg & 1;

    int stg = 0;
    for (int ch = 0; ch < NCH; ch++) {
        if (ch < NCH - 1) asm volatile("cp.async.wait_group 1;");
        else              asm volatile("cp.async.wait_group 0;");
        __syncthreads();

        // prefetch chunk ch+2 before compute (3-stage: safe, writes stage (ch+2)%3)
        if (ch + 2 < NCH) {
            int ns = stg + 2; if (ns >= 3) ns -= 3;
            load_stage(ns, (ch + 2) * BK);
        }

        const uint32_t st = sbase + stg * STAGE_SB;
#pragma unroll
        for (int kc = 0; kc < 2; kc++) {
            uint32_t a_h[2][4], a_l[2][4], b_h[2][4], b_l[2][4];
#pragma unroll
            for (int mt = 0; mt < 2; mt++) {
                uint32_t ro = (warp_m * 32 + mt * 16 + a_row) * 80
                            + (kc * 2 + a_kc) * 16;
                ldsm_x4(a_h[mt], st + ro);
                ldsm_x4(a_l[mt], st + OFF_AL + ro);
            }
#pragma unroll
            for (int ng = 0; ng < 2; ng++) {
                uint32_t ro = (warp_n * 32 + ng * 16 + b_row) * 80
                            + (kc * 2 + b_kc) * 16;
                ldsm_x4(b_h[ng], st + OFF_BH + ro);
                ldsm_x4(b_l[ng], st + OFF_BL + ro);
            }
            // pass 1: Ah*Bh
#pragma unroll
            for (int mt = 0; mt < 2; mt++)
#pragma unroll
                for (int ng = 0; ng < 2; ng++) {
                    mma_bf16(acc[mt][ng * 2 + 0], a_h[mt], b_h[ng][0], b_h[ng][1]);
                    mma_bf16(acc[mt][ng * 2 + 1], a_h[mt], b_h[ng][2], b_h[ng][3]);
                }
            // pass 2: Ah*Bl
#pragma unroll
            for (int mt = 0; mt < 2; mt++)
#pragma unroll
                for (int ng = 0; ng < 2; ng++) {
                    mma_bf16(acc[mt][ng * 2 + 0], a_h[mt], b_l[ng][0], b_l[ng][1]);
                    mma_bf16(acc[mt][ng * 2 + 1], a_h[mt], b_l[ng][2], b_l[ng][3]);
                }
            // pass 3: Al*Bh
#pragma unroll
            for (int mt = 0; mt < 2; mt++)
#pragma unroll
                for (int ng = 0; ng < 2; ng++) {
                    mma_bf16(acc[mt][ng * 2 + 0], a_l[mt], b_h[ng][0], b_h[ng][1]);
                    mma_bf16(acc[mt][ng * 2 + 1], a_l[mt], b_h[ng][2], b_h[ng][3]);
                }
        }
        __syncthreads();
        if (++stg == 3) stg = 0;
    }

    // epilogue
    const int grp = lane >> 2, tg = lane & 3;
#pragma unroll
    for (int mt = 0; mt < 2; mt++) {
        int r0 = m0 + warp_m * 32 + mt * 16 + grp;
#pragma unroll
        for (int nt = 0; nt < 4; nt++) {
            int c = n0 + warp_n * 32 + nt * 8 + tg * 2;
            float2 b2 = *(const float2*)&bias[c];
            float2 o0, o1;
            o0.x = acc[mt][nt][0] + b2.x;
            o0.y = acc[mt][nt][1] + b2.y;
            o1.x = acc[mt][nt][2] + b2.x;
            o1.y = acc[mt][nt][3] + b2.y;
            *(float2*)&C[(size_t)r0 * GN + c] = o0;
            *(float2*)&C[(size_t)(r0 + 8) * GN + c] = o1;
        }
    }
}

// ---------------- Attention: tiled flash, 64x64 score tile / block -------
#define QTILE 64
#define PAD   68

__global__ __launch_bounds__(256) void attention_kernel(
    const float* __restrict__ Q, const float* __restrict__ K,
    const float* __restrict__ V, const int* __restrict__ mask,
    float* __restrict__ Ctx)
{
    extern __shared__ float sm[];
    float* Qt  = sm;
    float* KPt = Qt + QTILE * PAD;
    float* Vs  = KPt + QTILE * PAD;
    int*   ms  = (int*)(Vs + QTILE * PAD);

    const int b  = blockIdx.z;
    const int h  = blockIdx.y;
    const int q0 = blockIdx.x * QTILE;
    const int tid = threadIdx.x;
    const int tx = tid & 15;
    const int ty = tid >> 4;
    const int dg  = tid & 15;
    const int row = tid >> 4;

#pragma unroll
    for (int i = 0; i < 4; i++) {
        int r = row + i * 16;
        float4 qv = *(const float4*)&Q[((size_t)b * S + q0 + r) * D + h * DK + dg * 4];
        Qt[(dg * 4 + 0) * PAD + r] = qv.x;
        Qt[(dg * 4 + 1) * PAD + r] = qv.y;
        Qt[(dg * 4 + 2) * PAD + r] = qv.z;
        Qt[(dg * 4 + 3) * PAD + r] = qv.w;
    }

    float acc[4][4];
#pragma unroll
    for (int i = 0; i < 4; i++)
#pragma unroll
        for (int j = 0; j < 4; j++) acc[i][j] = 0.f;
    float mrow[4] = {-1e30f, -1e30f, -1e30f, -1e30f};
    float lrow[4] = {0.f, 0.f, 0.f, 0.f};
    const float scale = 0.125f;

    for (int kk = 0; kk < S; kk += QTILE) {
        __syncthreads();
#pragma unroll
        for (int i = 0; i < 4; i++) {
            int r = row + i * 16;
            size_t g = ((size_t)b * S + kk + r) * D + h * DK + dg * 4;
            float4 kv = *(const float4*)&K[g];
            KPt[(dg * 4 + 0) * PAD + r] = kv.x;
            KPt[(dg * 4 + 1) * PAD + r] = kv.y;
            KPt[(dg * 4 + 2) * PAD + r] = kv.z;
            KPt[(dg * 4 + 3) * PAD + r] = kv.w;
            *(float4*)&Vs[r * PAD + dg * 4] = *(const float4*)&V[g];
        }
        if (tid < QTILE) ms[tid] = mask[(size_t)b * S + kk + tid];
        __syncthreads();

        float s[4][4];
#pragma unroll
        for (int i = 0; i < 4; i++)
#pragma unroll
            for (int j = 0; j < 4; j++) s[i][j] = 0.f;

#pragma unroll
        for (int d = 0; d < QTILE; d++) {
            float4 a = *(const float4*)&Qt[d * PAD + ty * 4];
            float4 bf = *(const float4*)&KPt[d * PAD + tx * 4];
            float af[4] = {a.x, a.y, a.z, a.w};
            float bfr[4] = {bf.x, bf.y, bf.z, bf.w};
#pragma unroll
            for (int i = 0; i < 4; i++)
#pragma unroll
                for (int j = 0; j < 4; j++)
                    s[i][j] += af[i] * bfr[j];
        }

        bool cmask[4];
#pragma unroll
        for (int j = 0; j < 4; j++) cmask[j] = (ms[tx * 4 + j] != 0);

        float corr[4];
#pragma unroll
        for (int i = 0; i < 4; i++) {
            float rmax = -1e30f;
#pragma unroll
            for (int j = 0; j < 4; j++) {
                float se = cmask[j] ? -1e30f : s[i][j] * scale;
                s[i][j] = se;
                rmax = fmaxf(rmax, se);
            }
#pragma unroll
            for (int off = 1; off < 16; off <<= 1)
                rmax = fmaxf(rmax, __shfl_xor_sync(0xffffffffu, rmax, off));

            float mnew = fmaxf(mrow[i], rmax);
            corr[i] = __expf(mrow[i] - mnew);
            float rsum = 0.f;
#pragma unroll
            for (int j = 0; j < 4; j++) {
                float p = cmask[j] ? 0.f : __expf(s[i][j] - mnew);
                s[i][j] = p;
                rsum += p;
            }
#pragma unroll
            for (int off = 1; off < 16; off <<= 1)
                rsum += __shfl_xor_sync(0xffffffffu, rsum, off);

            lrow[i] = lrow[i] * corr[i] + rsum;
            mrow[i] = mnew;
#pragma unroll
            for (int j = 0; j < 4; j++) acc[i][j] *= corr[i];
        }

        __syncthreads();
#pragma unroll
        for (int j = 0; j < 4; j++) {
            float4 pv = make_float4(s[0][j], s[1][j], s[2][j], s[3][j]);
            *(float4*)&KPt[(tx * 4 + j) * PAD + ty * 4] = pv;
        }
        __syncthreads();

#pragma unroll
        for (int c = 0; c < QTILE; c++) {
            float4 a = *(const float4*)&KPt[c * PAD + ty * 4];
            float4 bf = *(const float4*)&Vs[c * PAD + tx * 4];
            float af[4] = {a.x, a.y, a.z, a.w};
            float bfr[4] = {bf.x, bf.y, bf.z, bf.w};
#pragma unroll
            for (int i = 0; i < 4; i++)
#pragma unroll
                for (int j = 0; j < 4; j++)
                    acc[i][j] += af[i] * bfr[j];
        }
    }

#pragma unroll
    for (int i = 0; i < 4; i++) {
        float inv = (lrow[i] > 0.f) ? (1.f / lrow[i]) : 0.f;
        int r = q0 + ty * 4 + i;
        float4 o;
        o.x = acc[i][0] * inv;
        o.y = acc[i][1] * inv;
        o.z = acc[i][2] * inv;
        o.w = acc[i][3] * inv;
        *(float4*)&Ctx[((size_t)b * S + r) * D + h * DK + tx * 4] = o;
    }
}

// ---------------- launch ----------------
extern "C" void kernel_launch(void* const* d_in, const int* in_sizes, int n_in,
                              void* d_out, int out_size)
{
    const float* query = (const float*)d_in[0];
    const float* key   = (const float*)d_in[1];
    const float* value = (const float*)d_in[2];
    const int*   mask  = (const int*)d_in[3];
    const float* Wq = (const float*)d_in[4];
    const float* bq = (const float*)d_in[5];
    const float* Wk = (const float*)d_in[6];
    const float* bk = (const float*)d_in[7];
    const float* Wv = (const float*)d_in[8];
    const float* bv = (const float*)d_in[9];
    const float* Wo = (const float*)d_in[10];
    const float* bo = (const float*)d_in[11];
    float* out = (float*)d_out;

    float *qbuf, *kbuf, *vbuf, *cbuf;
    __nv_bfloat16 (*ah)[M_ROWS * D], (*al)[M_ROWS * D];
    __nv_bfloat16 (*bh)[D * D], (*bl)[D * D];
    cudaGetSymbolAddress((void**)&qbuf, g_Q);
    cudaGetSymbolAddress((void**)&kbuf, g_K);
    cudaGetSymbolAddress((void**)&vbuf, g_V);
    cudaGetSymbolAddress((void**)&cbuf, g_C);
    cudaGetSymbolAddress((void**)&ah, g_Ah);
    cudaGetSymbolAddress((void**)&al, g_Al);
    cudaGetSymbolAddress((void**)&bh, g_Bh);
    cudaGetSymbolAddress((void**)&bl, g_Bl);

    const int attn_smem = (3 * QTILE * PAD) * 4 + QTILE * 4;
    static int attr_set = 0;
    if (!attr_set) {
        cudaFuncSetAttribute(attention_kernel,
                             cudaFuncAttributeMaxDynamicSharedMemorySize, attn_smem);
        cudaFuncSetAttribute(gemm_bf16x3_kernel,
                             cudaFuncAttributeMaxDynamicSharedMemorySize, GEMM_SMEM);
        attr_set = 1;
    }

    const int n4_act = M_ROWS * D / 4;
    dim3 sa_grid((n4_act + 255) / 256);
    dim3 sw_grid(D / 32, D / 32);
    dim3 gemm_grid(GN / 64, M_ROWS / 128);   // (16, 32) = 512 CTAs

    // Launch order chosen so launch index 5 is a GEMM (ncu -s 5 -c 1).
    split_act_kernel<<<sa_grid, 256>>>(query, ah[0], al[0], n4_act);  // 0
    split_wt_kernel<<<sw_grid, 256>>>(Wq, bh[0], bl[0]);              // 1
    split_act_kernel<<<sa_grid, 256>>>(key, ah[1], al[1], n4_act);    // 2
    split_wt_kernel<<<sw_grid, 256>>>(Wk, bh[1], bl[1]);              // 3
    split_act_kernel<<<sa_grid, 256>>>(value, ah[2], al[2], n4_act);  // 4
    gemm_bf16x3_kernel<<<gemm_grid, 256, GEMM_SMEM>>>(                // 5 <- ncu
        ah[0], al[0], bh[0], bl[0], bq, qbuf);
    split_wt_kernel<<<sw_grid, 256>>>(Wv, bh[2], bl[2]);              // 6
    gemm_bf16x3_kernel<<<gemm_grid, 256, GEMM_SMEM>>>(                // 7
        ah[1], al[1], bh[1], bl[1], bk, kbuf);
    gemm_bf16x3_kernel<<<gemm_grid, 256, GEMM_SMEM>>>(                // 8
        ah[2], al[2], bh[2], bl[2], bv, vbuf);

    dim3 attn_grid(S / QTILE, H, B);
    attention_kernel<<<attn_grid, 256, attn_smem>>>(qbuf, kbuf, vbuf, mask, cbuf); // 9

    split_act_kernel<<<sa_grid, 256>>>(cbuf, ah[3], al[3], n4_act);   // 10
    split_wt_kernel<<<sw_grid, 256>>>(Wo, bh[3], bl[3]);              // 11
    gemm_bf16x3_kernel<<<gemm_grid, 256, GEMM_SMEM>>>(                // 12
        ah[3], al[3], bh[3], bl[3], bo, out);
}

// round 7
// speedup vs baseline: 2.7189x; 1.7230x over previous
#include <cuda_runtime.h>
#include <cuda_bf16.h>
#include <math.h>
#include <stdint.h>

// Problem constants
#define B  2
#define S  2048
#define D  1024
#define H  16
#define DK 64
#define M_ROWS (B * S)   // 4096
#define GK 1024
#define GN 1024

// ---------------- scratch (device globals: allocation-free) ----------------
__device__ float g_Q[M_ROWS * D];
__device__ float g_K[M_ROWS * D];
__device__ float g_V[M_ROWS * D];
__device__ float g_C[M_ROWS * D];
// per-projection activation hi/lo (0=q,1=k,2=v,3=ctx)
__device__ __nv_bfloat16 g_Ah[4][M_ROWS * D];
__device__ __nv_bfloat16 g_Al[4][M_ROWS * D];
// per-weight W^T hi/lo [n][k] (q,k,v,o)
__device__ __nv_bfloat16 g_Bh[4][D * D];
__device__ __nv_bfloat16 g_Bl[4][D * D];

__device__ __forceinline__ uint32_t smem_u32(const void* p) {
    uint32_t a;
    asm("{ .reg .u64 t; cvta.to.shared.u64 t, %1; cvt.u32.u64 %0, t; }"
        : "=r"(a) : "l"(p));
    return a;
}
__device__ __forceinline__ void ldsm_x4(uint32_t (&r)[4], uint32_t addr) {
    asm volatile("ldmatrix.sync.aligned.m8n8.x4.shared.b16 {%0,%1,%2,%3}, [%4];"
                 : "=r"(r[0]), "=r"(r[1]), "=r"(r[2]), "=r"(r[3]) : "r"(addr));
}
__device__ __forceinline__ void ldsm_x4_t(uint32_t (&r)[4], uint32_t addr) {
    asm volatile("ldmatrix.sync.aligned.m8n8.x4.trans.shared.b16 {%0,%1,%2,%3}, [%4];"
                 : "=r"(r[0]), "=r"(r[1]), "=r"(r[2]), "=r"(r[3]) : "r"(addr));
}
__device__ __forceinline__ void mma_bf16(float (&d)[4],
    const uint32_t (&a)[4], uint32_t b0, uint32_t b1)
{
    asm volatile(
        "mma.sync.aligned.m16n8k16.row.col.f32.bf16.bf16.f32 "
        "{%0,%1,%2,%3}, {%4,%5,%6,%7}, {%8,%9}, {%0,%1,%2,%3};"
        : "+f"(d[0]), "+f"(d[1]), "+f"(d[2]), "+f"(d[3])
        : "r"(a[0]), "r"(a[1]), "r"(a[2]), "r"(a[3]), "r"(b0), "r"(b1));
}
__device__ __forceinline__ void cpa16(uint32_t sd, const void* gs) {
    asm volatile("cp.async.cg.shared.global [%0], [%1], 16;" :: "r"(sd), "l"(gs));
}
__device__ __forceinline__ void split2(float f0, float f1, uint32_t& hi, uint32_t& lo) {
    __nv_bfloat16 h0 = __float2bfloat16(f0), h1 = __float2bfloat16(f1);
    __nv_bfloat16 l0 = __float2bfloat16(f0 - __bfloat162float(h0));
    __nv_bfloat16 l1 = __float2bfloat16(f1 - __bfloat162float(h1));
    hi = (uint32_t)*(uint16_t*)&h0 | ((uint32_t)*(uint16_t*)&h1 << 16);
    lo = (uint32_t)*(uint16_t*)&l0 | ((uint32_t)*(uint16_t*)&l1 << 16);
}

// ---------------- split kernels (fp32 -> bf16 hi/lo) ----------------
__global__ __launch_bounds__(256) void split_act_kernel(
    const float* __restrict__ X, __nv_bfloat16* __restrict__ Xh,
    __nv_bfloat16* __restrict__ Xl, int n4)
{
    int i = blockIdx.x * 256 + threadIdx.x;
    if (i >= n4) return;
    float4 v = ((const float4*)X)[i];
    float f[4] = {v.x, v.y, v.z, v.w};
    __nv_bfloat16 h[4], l[4];
#pragma unroll
    for (int j = 0; j < 4; j++) {
        h[j] = __float2bfloat16(f[j]);
        l[j] = __float2bfloat16(f[j] - __bfloat162float(h[j]));
    }
    *(__nv_bfloat162*)&Xh[i * 4 + 0] = __nv_bfloat162(h[0], h[1]);
    *(__nv_bfloat162*)&Xh[i * 4 + 2] = __nv_bfloat162(h[2], h[3]);
    *(__nv_bfloat162*)&Xl[i * 4 + 0] = __nv_bfloat162(l[0], l[1]);
    *(__nv_bfloat162*)&Xl[i * 4 + 2] = __nv_bfloat162(l[2], l[3]);
}

__global__ __launch_bounds__(256) void split_wt_kernel(
    const float* __restrict__ W, __nv_bfloat16* __restrict__ Wth,
    __nv_bfloat16* __restrict__ Wtl)
{
    __shared__ float t[32][33];
    int k0 = blockIdx.y * 32, n0 = blockIdx.x * 32;
    int tx = threadIdx.x & 31, ty = threadIdx.x >> 5;
#pragma unroll
    for (int i = 0; i < 4; i++)
        t[ty + i * 8][tx] = W[(size_t)(k0 + ty + i * 8) * D + n0 + tx];
    __syncthreads();
#pragma unroll
    for (int i = 0; i < 4; i++) {
        float v = t[tx][ty + i * 8];
        __nv_bfloat16 h = __float2bfloat16(v);
        __nv_bfloat16 l = __float2bfloat16(v - __bfloat162float(h));
        size_t o = (size_t)(n0 + ty + i * 8) * D + k0 + tx;
        Wth[o] = h;
        Wtl[o] = l;
    }
}

// ---------------- bf16x3 GEMM via warp-level mma.sync (R6, unchanged) ------
#define BK 32
#define NCH (GK / BK)
#define OFF_AL 10240
#define OFF_BH 20480
#define OFF_BL 25600
#define STAGE_SB 30720
#define GEMM_SMEM (3 * STAGE_SB)

__global__ __launch_bounds__(256, 2) void gemm_bf16x3_kernel(
    const __nv_bfloat16* __restrict__ Ah, const __nv_bfloat16* __restrict__ Al,
    const __nv_bfloat16* __restrict__ Bh, const __nv_bfloat16* __restrict__ Bl,
    const float* __restrict__ bias, float* __restrict__ C)
{
    extern __shared__ char smem[];
    const uint32_t sbase = smem_u32(smem);
    const int tid = threadIdx.x;
    const int lane = tid & 31;
    const int wid = tid >> 5;
    const int warp_m = wid & 3;
    const int warp_n = wid >> 2;
    const int m0 = blockIdx.y * 128;
    const int n0 = blockIdx.x * 64;

    const __nv_bfloat16* gAh = Ah + (size_t)m0 * GK;
    const __nv_bfloat16* gAl = Al + (size_t)m0 * GK;
    const __nv_bfloat16* gBh = Bh + (size_t)n0 * GK;
    const __nv_bfloat16* gBl = Bl + (size_t)n0 * GK;

    const int lrow = tid >> 2;
    const int lc   = tid & 3;

    auto load_stage = [&](int stg, int k0) {
        uint32_t sb = sbase + stg * STAGE_SB;
#pragma unroll
        for (int j = 0; j < 2; j++) {
            int row = lrow + j * 64;
            uint32_t so = row * 80 + lc * 16;
            size_t go = (size_t)row * GK + k0 + lc * 8;
            cpa16(sb + so,          gAh + go);
            cpa16(sb + OFF_AL + so, gAl + go);
        }
        {
            uint32_t so = lrow * 80 + lc * 16;
            size_t go = (size_t)lrow * GK + k0 + lc * 8;
            cpa16(sb + OFF_BH + so, gBh + go);
            cpa16(sb + OFF_BL + so, gBl + go);
        }
        asm volatile("cp.async.commit_group;");
    };

    float acc[2][4][4];
#pragma unroll
    for (int i = 0; i < 2; i++)
#pragma unroll
        for (int j = 0; j < 4; j++)
#pragma unroll
            for (int v = 0; v < 4; v++) acc[i][j][v] = 0.f;

    load_stage(0, 0);
    load_stage(1, BK);

    const int a_row = lane & 15;
    const int a_kc  = lane >> 4;
    const int bg    = lane >> 3;
    const int b_row = ((bg >> 1) * 8) + (lane & 7);
    const int b_kc  = bg & 1;

    int stg = 0;
    for (int ch = 0; ch < NCH; ch++) {
        if (ch < NCH - 1) asm volatile("cp.async.wait_group 1;");
        else              asm volatile("cp.async.wait_group 0;");
        __syncthreads();
        if (ch + 2 < NCH) {
            int ns = stg + 2; if (ns >= 3) ns -= 3;
            load_stage(ns, (ch + 2) * BK);
        }
        const uint32_t st = sbase + stg * STAGE_SB;
#pragma unroll
        for (int kc = 0; kc < 2; kc++) {
            uint32_t a_h[2][4], a_l[2][4], b_h[2][4], b_l[2][4];
#pragma unroll
            for (int mt = 0; mt < 2; mt++) {
                uint32_t ro = (warp_m * 32 + mt * 16 + a_row) * 80
                            + (kc * 2 + a_kc) * 16;
                ldsm_x4(a_h[mt], st + ro);
                ldsm_x4(a_l[mt], st + OFF_AL + ro);
            }
#pragma unroll
            for (int ng = 0; ng < 2; ng++) {
                uint32_t ro = (warp_n * 32 + ng * 16 + b_row) * 80
                            + (kc * 2 + b_kc) * 16;
                ldsm_x4(b_h[ng], st + OFF_BH + ro);
                ldsm_x4(b_l[ng], st + OFF_BL + ro);
            }
#pragma unroll
            for (int mt = 0; mt < 2; mt++)
#pragma unroll
                for (int ng = 0; ng < 2; ng++) {
                    mma_bf16(acc[mt][ng * 2 + 0], a_h[mt], b_h[ng][0], b_h[ng][1]);
                    mma_bf16(acc[mt][ng * 2 + 1], a_h[mt], b_h[ng][2], b_h[ng][3]);
                }
#pragma unroll
            for (int mt = 0; mt < 2; mt++)
#pragma unroll
                for (int ng = 0; ng < 2; ng++) {
                    mma_bf16(acc[mt][ng * 2 + 0], a_h[mt], b_l[ng][0], b_l[ng][1]);
                    mma_bf16(acc[mt][ng * 2 + 1], a_h[mt], b_l[ng][2], b_l[ng][3]);
                }
#pragma unroll
            for (int mt = 0; mt < 2; mt++)
#pragma unroll
                for (int ng = 0; ng < 2; ng++) {
                    mma_bf16(acc[mt][ng * 2 + 0], a_l[mt], b_h[ng][0], b_h[ng][1]);
                    mma_bf16(acc[mt][ng * 2 + 1], a_l[mt], b_h[ng][2], b_h[ng][3]);
                }
        }
        __syncthreads();
        if (++stg == 3) stg = 0;
    }

    const int grp = lane >> 2, tg = lane & 3;
#pragma unroll
    for (int mt = 0; mt < 2; mt++) {
        int r0 = m0 + warp_m * 32 + mt * 16 + grp;
#pragma unroll
        for (int nt = 0; nt < 4; nt++) {
            int c = n0 + warp_n * 32 + nt * 8 + tg * 2;
            float2 b2 = *(const float2*)&bias[c];
            float2 o0, o1;
            o0.x = acc[mt][nt][0] + b2.x;
            o0.y = acc[mt][nt][1] + b2.y;
            o1.x = acc[mt][nt][2] + b2.x;
            o1.y = acc[mt][nt][3] + b2.y;
            *(float2*)&C[(size_t)r0 * GN + c] = o0;
            *(float2*)&C[(size_t)(r0 + 8) * GN + c] = o1;
        }
    }
}

// ---------------- Attention via HMMA bf16x3 (flash, fragment softmax) -----
// grid (S/128, H, B), 256 thr (8 warps x 16 q-rows). 64-key chunks, 3 stages.
// smem per stage: Kh,Kl,Vh,Vl tiles 64x(64bf16) rows @144B stride = 4*9216.
#define ASTG 36864
#define AT_VH 18432
#define AT_VL 27648
#define AMS (3 * ASTG)
#define ATTN_SMEM (3 * ASTG + 3 * 256)   // 111360

__global__ __launch_bounds__(256) void attn_mma_kernel(
    const __nv_bfloat16* __restrict__ Qh, const __nv_bfloat16* __restrict__ Ql,
    const __nv_bfloat16* __restrict__ Kh, const __nv_bfloat16* __restrict__ Kl,
    const __nv_bfloat16* __restrict__ Vh, const __nv_bfloat16* __restrict__ Vl,
    const int* __restrict__ mask, float* __restrict__ Ctx)
{
    extern __shared__ char smem[];
    const uint32_t sb = smem_u32(smem);
    const int tid = threadIdx.x, lane = tid & 31, wid = tid >> 5;
    const int b = blockIdx.z, h = blockIdx.y, q0 = blockIdx.x * 128;

    // ---- stage Q tile (hi/lo) into smem once, ldsm to fragments ----
#pragma unroll
    for (int t = 0; t < 8; t++) {
        int idx = tid + t * 256;          // 0..2047
        int half = idx >> 10;             // 0 hi, 1 lo
        int c = idx & 1023;
        int row = c >> 3, ch = c & 7;
        const __nv_bfloat16* src = (half ? Ql : Qh)
            + (size_t)(b * S + q0 + row) * D + h * DK + ch * 8;
        *(uint4*)(smem + half * 18432 + row * 144 + ch * 16) = *(const uint4*)src;
    }
    __syncthreads();
    uint32_t qfh[4][4], qfl[4][4];
    {
        int r = wid * 16 + (lane & 15);
        int hc = lane >> 4;
#pragma unroll
        for (int c = 0; c < 4; c++) {
            ldsm_x4(qfh[c], sb + r * 144 + (c * 2 + hc) * 16);
            ldsm_x4(qfl[c], sb + 18432 + r * 144 + (c * 2 + hc) * 16);
        }
    }
    __syncthreads();

    const __nv_bfloat16* ksrc0 = Kh; const __nv_bfloat16* ksrc1 = Kl;
    const __nv_bfloat16* ksrc2 = Vh; const __nv_bfloat16* ksrc3 = Vl;

    auto load_stage = [&](int stg, int kk) {
        uint32_t base = sb + stg * ASTG;
#pragma unroll
        for (int t = 0; t < 8; t++) {
            int idx = tid + t * 256;       // 0..2047
            int tile = idx >> 9;           // 0..3
            int c = idx & 511;
            int row = c >> 3, ch = c & 7;
            const __nv_bfloat16* g =
                (tile == 0 ? ksrc0 : tile == 1 ? ksrc1 : tile == 2 ? ksrc2 : ksrc3)
                + (size_t)(b * S + kk + row) * D + h * DK + ch * 8;
            cpa16(base + tile * 9216 + row * 144 + ch * 16, g);
        }
        if (tid < 16)
            cpa16(sb + AMS + stg * 256 + tid * 16,
                  mask + (size_t)b * S + kk + tid * 4);
        asm volatile("cp.async.commit_group;");
    };

    float acc[8][4];
#pragma unroll
    for (int j = 0; j < 8; j++)
#pragma unroll
        for (int v = 0; v < 4; v++) acc[j][v] = 0.f;
    float m0r = -1e30f, m1r = -1e30f, l0r = 0.f, l1r = 0.f;
    const float scale = 0.125f;

    load_stage(0, 0);
    load_stage(1, 64);

    const int bg    = lane >> 3;
    const int b_row = ((bg >> 1) * 8) + (lane & 7);
    const int b_kc  = bg & 1;
    const int tr    = lane & 15;      // trans-ldsm row
    const int tc    = lane >> 4;      // trans-ldsm col half

    int stg = 0;
    for (int it = 0; it < 32; it++) {
        if (it < 31) asm volatile("cp.async.wait_group 1;");
        else         asm volatile("cp.async.wait_group 0;");
        __syncthreads();
        if (it + 2 < 32) {
            int ns = stg + 2; if (ns >= 3) ns -= 3;
            load_stage(ns, (it + 2) * 64);
        }
        const uint32_t st = sb + stg * ASTG;
        const int* msp = (const int*)(smem + AMS + stg * 256);

        // ---- QK^T (bf16x3) -> s fragments ----
        float s[8][4];
#pragma unroll
        for (int j = 0; j < 8; j++)
#pragma unroll
            for (int v = 0; v < 4; v++) s[j][v] = 0.f;
#pragma unroll
        for (int c = 0; c < 4; c++) {
#pragma unroll
            for (int np = 0; np < 4; np++) {
                uint32_t kbh[4], kbl[4];
                uint32_t ro = (np * 16 + b_row) * 144 + (c * 2 + b_kc) * 16;
                ldsm_x4(kbh, st + ro);
                ldsm_x4(kbl, st + 9216 + ro);
                mma_bf16(s[np * 2 + 0], qfh[c], kbh[0], kbh[1]);
                mma_bf16(s[np * 2 + 1], qfh[c], kbh[2], kbh[3]);
                mma_bf16(s[np * 2 + 0], qfh[c], kbl[0], kbl[1]);
                mma_bf16(s[np * 2 + 1], qfh[c], kbl[2], kbl[3]);
                mma_bf16(s[np * 2 + 0], qfl[c], kbh[0], kbh[1]);
                mma_bf16(s[np * 2 + 1], qfl[c], kbh[2], kbh[3]);
            }
        }

        // ---- online softmax on fragments ----
        float mx0 = -1e30f, mx1 = -1e30f;
#pragma unroll
        for (int nt = 0; nt < 8; nt++) {
            int j0 = nt * 8 + (lane & 3) * 2;
            bool k0m = (msp[j0] != 0), k1m = (msp[j0 + 1] != 0);
            s[nt][0] = k0m ? -1e30f : s[nt][0] * scale;
            s[nt][1] = k1m ? -1e30f : s[nt][1] * scale;
            s[nt][2] = k0m ? -1e30f : s[nt][2] * scale;
            s[nt][3] = k1m ? -1e30f : s[nt][3] * scale;
            mx0 = fmaxf(mx0, fmaxf(s[nt][0], s[nt][1]));
            mx1 = fmaxf(mx1, fmaxf(s[nt][2], s[nt][3]));
        }
#pragma unroll
        for (int off = 1; off < 4; off <<= 1) {
            mx0 = fmaxf(mx0, __shfl_xor_sync(0xffffffffu, mx0, off));
            mx1 = fmaxf(mx1, __shfl_xor_sync(0xffffffffu, mx1, off));
        }
        float mn0 = fmaxf(m0r, mx0), mn1 = fmaxf(m1r, mx1);
        float cr0 = __expf(m0r - mn0), cr1 = __expf(m1r - mn1);
        float sum0 = 0.f, sum1 = 0.f;
#pragma unroll
        for (int nt = 0; nt < 8; nt++) {
            float p0 = (s[nt][0] > -5e29f) ? __expf(s[nt][0] - mn0) : 0.f;
            float p1 = (s[nt][1] > -5e29f) ? __expf(s[nt][1] - mn0) : 0.f;
            float p2 = (s[nt][2] > -5e29f) ? __expf(s[nt][2] - mn1) : 0.f;
            float p3 = (s[nt][3] > -5e29f) ? __expf(s[nt][3] - mn1) : 0.f;
            s[nt][0] = p0; s[nt][1] = p1; s[nt][2] = p2; s[nt][3] = p3;
            sum0 += p0 + p1;
            sum1 += p2 + p3;
        }
#pragma unroll
        for (int off = 1; off < 4; off <<= 1) {
            sum0 += __shfl_xor_sync(0xffffffffu, sum0, off);
            sum1 += __shfl_xor_sync(0xffffffffu, sum1, off);
        }
        l0r = l0r * cr0 + sum0;
        l1r = l1r * cr1 + sum1;
        m0r = mn0; m1r = mn1;
#pragma unroll
        for (int nt = 0; nt < 8; nt++) {
            acc[nt][0] *= cr0; acc[nt][1] *= cr0;
            acc[nt][2] *= cr1; acc[nt][3] *= cr1;
        }

        // ---- P fragments (C-frag == A-frag layout), hi/lo split ----
        uint32_t pah[4][4], pal[4][4];
#pragma unroll
        for (int c = 0; c < 4; c++) {
            split2(s[2 * c][0],     s[2 * c][1],     pah[c][0], pal[c][0]);
            split2(s[2 * c][2],     s[2 * c][3],     pah[c][1], pal[c][1]);
            split2(s[2 * c + 1][0], s[2 * c + 1][1], pah[c][2], pal[c][2]);
            split2(s[2 * c + 1][2], s[2 * c + 1][3], pah[c][3], pal[c][3]);
        }

        // ---- PV (bf16x3) with trans-ldsm on V ----
#pragma unroll
        for (int c = 0; c < 4; c++) {
#pragma unroll
            for (int np = 0; np < 4; np++) {
                uint32_t vbh[4], vbl[4];
                uint32_t ro = (c * 16 + tr) * 144 + np * 32 + tc * 16;
                ldsm_x4_t(vbh, st + AT_VH + ro);
                ldsm_x4_t(vbl, st + AT_VL + ro);
                mma_bf16(acc[np * 2 + 0], pah[c], vbh[0], vbh[1]);
                mma_bf16(acc[np * 2 + 1], pah[c], vbh[2], vbh[3]);
                mma_bf16(acc[np * 2 + 0], pah[c], vbl[0], vbl[1]);
                mma_bf16(acc[np * 2 + 1], pah[c], vbl[2], vbl[3]);
                mma_bf16(acc[np * 2 + 0], pal[c], vbh[0], vbh[1]);
                mma_bf16(acc[np * 2 + 1], pal[c], vbh[2], vbh[3]);
            }
        }
        __syncthreads();
        if (++stg == 3) stg = 0;
    }

    // ---- epilogue ----
    float inv0 = (l0r > 0.f) ? (1.f / l0r) : 0.f;
    float inv1 = (l1r > 0.f) ? (1.f / l1r) : 0.f;
    int r0 = q0 + wid * 16 + (lane >> 2);
#pragma unroll
    for (int nt = 0; nt < 8; nt++) {
        int c = h * DK + nt * 8 + (lane & 3) * 2;
        float2 o0, o1;
        o0.x = acc[nt][0] * inv0; o0.y = acc[nt][1] * inv0;
        o1.x = acc[nt][2] * inv1; o1.y = acc[nt][3] * inv1;
        *(float2*)&Ctx[(size_t)(b * S + r0) * D + c] = o0;
        *(float2*)&Ctx[(size_t)(b * S + r0 + 8) * D + c] = o1;
    }
}

// ---------------- launch ----------------
extern "C" void kernel_launch(void* const* d_in, const int* in_sizes, int n_in,
                              void* d_out, int out_size)
{
    const float* query = (const float*)d_in[0];
    const float* key   = (const float*)d_in[1];
    const float* value = (const float*)d_in[2];
    const int*   mask  = (const int*)d_in[3];
    const float* Wq = (const float*)d_in[4];
    const float* bq = (const float*)d_in[5];
    const float* Wk = (const float*)d_in[6];
    const float* bk = (const float*)d_in[7];
    const float* Wv = (const float*)d_in[8];
    const float* bv = (const float*)d_in[9];
    const float* Wo = (const float*)d_in[10];
    const float* bo = (const float*)d_in[11];
    float* out = (float*)d_out;

    float *qbuf, *kbuf, *vbuf, *cbuf;
    __nv_bfloat16 (*ah)[M_ROWS * D], (*al)[M_ROWS * D];
    __nv_bfloat16 (*bh)[D * D], (*bl)[D * D];
    cudaGetSymbolAddress((void**)&qbuf, g_Q);
    cudaGetSymbolAddress((void**)&kbuf, g_K);
    cudaGetSymbolAddress((void**)&vbuf, g_V);
    cudaGetSymbolAddress((void**)&cbuf, g_C);
    cudaGetSymbolAddress((void**)&ah, g_Ah);
    cudaGetSymbolAddress((void**)&al, g_Al);
    cudaGetSymbolAddress((void**)&bh, g_Bh);
    cudaGetSymbolAddress((void**)&bl, g_Bl);

    static int attr_set = 0;
    if (!attr_set) {
        cudaFuncSetAttribute(gemm_bf16x3_kernel,
                             cudaFuncAttributeMaxDynamicSharedMemorySize, GEMM_SMEM);
        cudaFuncSetAttribute(attn_mma_kernel,
                             cudaFuncAttributeMaxDynamicSharedMemorySize, ATTN_SMEM);
        attr_set = 1;
    }

    const int n4_act = M_ROWS * D / 4;
    dim3 sa_grid((n4_act + 255) / 256);
    dim3 sw_grid(D / 32, D / 32);
    dim3 gemm_grid(GN / 64, M_ROWS / 128);

    // projections
    split_act_kernel<<<sa_grid, 256>>>(query, ah[0], al[0], n4_act);
    split_wt_kernel<<<sw_grid, 256>>>(Wq, bh[0], bl[0]);
    gemm_bf16x3_kernel<<<gemm_grid, 256, GEMM_SMEM>>>(ah[0], al[0], bh[0], bl[0], bq, qbuf);
    split_act_kernel<<<sa_grid, 256>>>(key, ah[1], al[1], n4_act);
    split_wt_kernel<<<sw_grid, 256>>>(Wk, bh[1], bl[1]);
    gemm_bf16x3_kernel<<<gemm_grid, 256, GEMM_SMEM>>>(ah[1], al[1], bh[1], bl[1], bk, kbuf);
    split_act_kernel<<<sa_grid, 256>>>(value, ah[2], al[2], n4_act);
    split_wt_kernel<<<sw_grid, 256>>>(Wv, bh[2], bl[2]);
    gemm_bf16x3_kernel<<<gemm_grid, 256, GEMM_SMEM>>>(ah[2], al[2], bh[2], bl[2], bv, vbuf);

    // re-split projected q/k/v to bf16 hi/lo (overwrite input splits)
    split_act_kernel<<<sa_grid, 256>>>(qbuf, ah[0], al[0], n4_act);
    split_act_kernel<<<sa_grid, 256>>>(kbuf, ah[1], al[1], n4_act);
    split_act_kernel<<<sa_grid, 256>>>(vbuf, ah[2], al[2], n4_act);

    // attention (HMMA)
    dim3 attn_grid(S / 128, H, B);
    attn_mma_kernel<<<attn_grid, 256, ATTN_SMEM>>>(
        ah[0], al[0], ah[1], al[1], ah[2], al[2], mask, cbuf);

    // output projection
    split_act_kernel<<<sa_grid, 256>>>(cbuf, ah[3], al[3], n4_act);
    split_wt_kernel<<<sw_grid, 256>>>(Wo, bh[3], bl[3]);
    gemm_bf16x3_kernel<<<gemm_grid, 256, GEMM_SMEM>>>(ah[3], al[3], bh[3], bl[3], bo, out);
}

// round 8
// speedup vs baseline: 2.8693x; 1.0553x over previous
#include <cuda_runtime.h>
#include <cuda_bf16.h>
#include <math.h>
#include <stdint.h>

// Problem constants
#define B  2
#define S  2048
#define D  1024
#define H  16
#define DK 64
#define M_ROWS (B * S)   // 4096
#define GK 1024
#define GN 1024
#define SZA (M_ROWS * D)

// ---------------- scratch (device globals: allocation-free) ----------------
// activation hi/lo slots: 0..2 = split inputs (q,k,v); 3..5 = projected q,k,v;
// 6 = attention context
__device__ __nv_bfloat16 g_Ah[7][SZA];
__device__ __nv_bfloat16 g_Al[7][SZA];
// weight W^T hi/lo [n][k], slots q,k,v,o
__device__ __nv_bfloat16 g_Bh[4][D * D];
__device__ __nv_bfloat16 g_Bl[4][D * D];

struct FPtr3 { const float* p[3]; };
struct FPtr4 { const float* p[4]; };

__device__ __forceinline__ uint32_t smem_u32(const void* p) {
    uint32_t a;
    asm("{ .reg .u64 t; cvta.to.shared.u64 t, %1; cvt.u32.u64 %0, t; }"
        : "=r"(a) : "l"(p));
    return a;
}
__device__ __forceinline__ void ldsm_x4(uint32_t (&r)[4], uint32_t addr) {
    asm volatile("ldmatrix.sync.aligned.m8n8.x4.shared.b16 {%0,%1,%2,%3}, [%4];"
                 : "=r"(r[0]), "=r"(r[1]), "=r"(r[2]), "=r"(r[3]) : "r"(addr));
}
__device__ __forceinline__ void ldsm_x4_t(uint32_t (&r)[4], uint32_t addr) {
    asm volatile("ldmatrix.sync.aligned.m8n8.x4.trans.shared.b16 {%0,%1,%2,%3}, [%4];"
                 : "=r"(r[0]), "=r"(r[1]), "=r"(r[2]), "=r"(r[3]) : "r"(addr));
}
__device__ __forceinline__ void mma_bf16(float (&d)[4],
    const uint32_t (&a)[4], uint32_t b0, uint32_t b1)
{
    asm volatile(
        "mma.sync.aligned.m16n8k16.row.col.f32.bf16.bf16.f32 "
        "{%0,%1,%2,%3}, {%4,%5,%6,%7}, {%8,%9}, {%0,%1,%2,%3};"
        : "+f"(d[0]), "+f"(d[1]), "+f"(d[2]), "+f"(d[3])
        : "r"(a[0]), "r"(a[1]), "r"(a[2]), "r"(a[3]), "r"(b0), "r"(b1));
}
__device__ __forceinline__ void cpa16(uint32_t sd, const void* gs) {
    asm volatile("cp.async.cg.shared.global [%0], [%1], 16;" :: "r"(sd), "l"(gs));
}
__device__ __forceinline__ void split2(float f0, float f1, uint32_t& hi, uint32_t& lo) {
    __nv_bfloat16 h0 = __float2bfloat16(f0), h1 = __float2bfloat16(f1);
    __nv_bfloat16 l0 = __float2bfloat16(f0 - __bfloat162float(h0));
    __nv_bfloat16 l1 = __float2bfloat16(f1 - __bfloat162float(h1));
    hi = (uint32_t)*(uint16_t*)&h0 | ((uint32_t)*(uint16_t*)&h1 << 16);
    lo = (uint32_t)*(uint16_t*)&l0 | ((uint32_t)*(uint16_t*)&l1 << 16);
}

// ---------------- batched split kernels ----------------
// inputs (q,k,v) -> slots 0..2; grid (n4/256, 3)
__global__ __launch_bounds__(256) void split_act3_kernel(
    FPtr3 X, __nv_bfloat16* __restrict__ XhB, __nv_bfloat16* __restrict__ XlB, int n4)
{
    int z = blockIdx.y;
    int i = blockIdx.x * 256 + threadIdx.x;
    if (i >= n4) return;
    float4 v = ((const float4*)X.p[z])[i];
    __nv_bfloat16* Xh = XhB + (size_t)z * SZA;
    __nv_bfloat16* Xl = XlB + (size_t)z * SZA;
    float f[4] = {v.x, v.y, v.z, v.w};
    __nv_bfloat16 h[4], l[4];
#pragma unroll
    for (int j = 0; j < 4; j++) {
        h[j] = __float2bfloat16(f[j]);
        l[j] = __float2bfloat16(f[j] - __bfloat162float(h[j]));
    }
    *(__nv_bfloat162*)&Xh[i * 4 + 0] = __nv_bfloat162(h[0], h[1]);
    *(__nv_bfloat162*)&Xh[i * 4 + 2] = __nv_bfloat162(h[2], h[3]);
    *(__nv_bfloat162*)&Xl[i * 4 + 0] = __nv_bfloat162(l[0], l[1]);
    *(__nv_bfloat162*)&Xl[i * 4 + 2] = __nv_bfloat162(l[2], l[3]);
}

// W[k][n] fp32 -> Wt hi/lo [n][k]; grid (32, 32, 4)
__global__ __launch_bounds__(256) void split_wt4_kernel(
    FPtr4 W, __nv_bfloat16* __restrict__ WthB, __nv_bfloat16* __restrict__ WtlB)
{
    __shared__ float t[32][33];
    int z = blockIdx.z;
    int k0 = blockIdx.y * 32, n0 = blockIdx.x * 32;
    int tx = threadIdx.x & 31, ty = threadIdx.x >> 5;
    const float* Wp = W.p[z];
    __nv_bfloat16* Wth = WthB + (size_t)z * D * D;
    __nv_bfloat16* Wtl = WtlB + (size_t)z * D * D;
#pragma unroll
    for (int i = 0; i < 4; i++)
        t[ty + i * 8][tx] = Wp[(size_t)(k0 + ty + i * 8) * D + n0 + tx];
    __syncthreads();
#pragma unroll
    for (int i = 0; i < 4; i++) {
        float v = t[tx][ty + i * 8];
        __nv_bfloat16 h = __float2bfloat16(v);
        __nv_bfloat16 l = __float2bfloat16(v - __bfloat162float(h));
        size_t o = (size_t)(n0 + ty + i * 8) * D + k0 + tx;
        Wth[o] = h;
        Wtl[o] = l;
    }
}

// ---------------- bf16x3 GEMM body (shared by qkv + oproj kernels) --------
#define BK 32
#define NCH (GK / BK)
#define OFF_AL 10240
#define OFF_BH 20480
#define OFF_BL 25600
#define STAGE_SB 30720
#define GEMM_SMEM (3 * STAGE_SB)

__device__ __forceinline__ void gemm_body(
    const __nv_bfloat16* __restrict__ Ah, const __nv_bfloat16* __restrict__ Al,
    const __nv_bfloat16* __restrict__ Bh, const __nv_bfloat16* __restrict__ Bl,
    const float* __restrict__ bias, float* __restrict__ C,
    __nv_bfloat16* __restrict__ Ch, __nv_bfloat16* __restrict__ Cl,
    char* smem)
{
    const uint32_t sbase = smem_u32(smem);
    const int tid = threadIdx.x;
    const int lane = tid & 31;
    const int wid = tid >> 5;
    const int warp_m = wid & 3;
    const int warp_n = wid >> 2;
    const int m0 = blockIdx.y * 128;
    const int n0 = blockIdx.x * 64;

    const __nv_bfloat16* gAh = Ah + (size_t)m0 * GK;
    const __nv_bfloat16* gAl = Al + (size_t)m0 * GK;
    const __nv_bfloat16* gBh = Bh + (size_t)n0 * GK;
    const __nv_bfloat16* gBl = Bl + (size_t)n0 * GK;

    const int lrow = tid >> 2;
    const int lc   = tid & 3;

    auto load_stage = [&](int stg, int k0) {
        uint32_t sb = sbase + stg * STAGE_SB;
#pragma unroll
        for (int j = 0; j < 2; j++) {
            int row = lrow + j * 64;
            uint32_t so = row * 80 + lc * 16;
            size_t go = (size_t)row * GK + k0 + lc * 8;
            cpa16(sb + so,          gAh + go);
            cpa16(sb + OFF_AL + so, gAl + go);
        }
        {
            uint32_t so = lrow * 80 + lc * 16;
            size_t go = (size_t)lrow * GK + k0 + lc * 8;
            cpa16(sb + OFF_BH + so, gBh + go);
            cpa16(sb + OFF_BL + so, gBl + go);
        }
        asm volatile("cp.async.commit_group;");
    };

    float acc[2][4][4];
#pragma unroll
    for (int i = 0; i < 2; i++)
#pragma unroll
        for (int j = 0; j < 4; j++)
#pragma unroll
            for (int v = 0; v < 4; v++) acc[i][j][v] = 0.f;

    load_stage(0, 0);
    load_stage(1, BK);

    const int a_row = lane & 15;
    const int a_kc  = lane >> 4;
    const int bg    = lane >> 3;
    const int b_row = ((bg >> 1) * 8) + (lane & 7);
    const int b_kc  = bg & 1;

    int stg = 0;
    for (int ch = 0; ch < NCH; ch++) {
        if (ch < NCH - 1) asm volatile("cp.async.wait_group 1;");
        else              asm volatile("cp.async.wait_group 0;");
        __syncthreads();
        if (ch + 2 < NCH) {
            int ns = stg + 2; if (ns >= 3) ns -= 3;
            load_stage(ns, (ch + 2) * BK);
        }
        const uint32_t st = sbase + stg * STAGE_SB;
#pragma unroll
        for (int kc = 0; kc < 2; kc++) {
            uint32_t a_h[2][4], a_l[2][4], b_h[2][4], b_l[2][4];
#pragma unroll
            for (int mt = 0; mt < 2; mt++) {
                uint32_t ro = (warp_m * 32 + mt * 16 + a_row) * 80
                            + (kc * 2 + a_kc) * 16;
                ldsm_x4(a_h[mt], st + ro);
                ldsm_x4(a_l[mt], st + OFF_AL + ro);
            }
#pragma unroll
            for (int ng = 0; ng < 2; ng++) {
                uint32_t ro = (warp_n * 32 + ng * 16 + b_row) * 80
                            + (kc * 2 + b_kc) * 16;
                ldsm_x4(b_h[ng], st + OFF_BH + ro);
                ldsm_x4(b_l[ng], st + OFF_BL + ro);
            }
#pragma unroll
            for (int mt = 0; mt < 2; mt++)
#pragma unroll
                for (int ng = 0; ng < 2; ng++) {
                    mma_bf16(acc[mt][ng * 2 + 0], a_h[mt], b_h[ng][0], b_h[ng][1]);
                    mma_bf16(acc[mt][ng * 2 + 1], a_h[mt], b_h[ng][2], b_h[ng][3]);
                }
#pragma unroll
            for (int mt = 0; mt < 2; mt++)
#pragma unroll
                for (int ng = 0; ng < 2; ng++) {
                    mma_bf16(acc[mt][ng * 2 + 0], a_h[mt], b_l[ng][0], b_l[ng][1]);
                    mma_bf16(acc[mt][ng * 2 + 1], a_h[mt], b_l[ng][2], b_l[ng][3]);
                }
#pragma unroll
            for (int mt = 0; mt < 2; mt++)
#pragma unroll
                for (int ng = 0; ng < 2; ng++) {
                    mma_bf16(acc[mt][ng * 2 + 0], a_l[mt], b_h[ng][0], b_h[ng][1]);
                    mma_bf16(acc[mt][ng * 2 + 1], a_l[mt], b_h[ng][2], b_h[ng][3]);
                }
        }
        __syncthreads();
        if (++stg == 3) stg = 0;
    }

    const int grp = lane >> 2, tg = lane & 3;
#pragma unroll
    for (int mt = 0; mt < 2; mt++) {
        int r0 = m0 + warp_m * 32 + mt * 16 + grp;
#pragma unroll
        for (int nt = 0; nt < 4; nt++) {
            int c = n0 + warp_n * 32 + nt * 8 + tg * 2;
            float2 b2 = *(const float2*)&bias[c];
            float o00 = acc[mt][nt][0] + b2.x;
            float o01 = acc[mt][nt][1] + b2.y;
            float o10 = acc[mt][nt][2] + b2.x;
            float o11 = acc[mt][nt][3] + b2.y;
            if (C) {
                *(float2*)&C[(size_t)r0 * GN + c] = make_float2(o00, o01);
                *(float2*)&C[(size_t)(r0 + 8) * GN + c] = make_float2(o10, o11);
            } else {
                uint32_t h0, l0, h1, l1;
                split2(o00, o01, h0, l0);
                split2(o10, o11, h1, l1);
                *(uint32_t*)&Ch[(size_t)r0 * GN + c] = h0;
                *(uint32_t*)&Cl[(size_t)r0 * GN + c] = l0;
                *(uint32_t*)&Ch[(size_t)(r0 + 8) * GN + c] = h1;
                *(uint32_t*)&Cl[(size_t)(r0 + 8) * GN + c] = l1;
            }
        }
    }
}

struct QKVBias { const float* p[3]; };

// batched Q/K/V projection: grid (16, 32, 3); bf16 hi/lo outputs only
__global__ __launch_bounds__(256, 2) void qkv_gemm_kernel(
    const __nv_bfloat16* __restrict__ AhB, const __nv_bfloat16* __restrict__ AlB,
    const __nv_bfloat16* __restrict__ BhB, const __nv_bfloat16* __restrict__ BlB,
    QKVBias bias,
    __nv_bfloat16* __restrict__ ChB, __nv_bfloat16* __restrict__ ClB)
{
    extern __shared__ char smem[];
    const int z = blockIdx.z;
    gemm_body(AhB + (size_t)z * SZA, AlB + (size_t)z * SZA,
              BhB + (size_t)z * D * D, BlB + (size_t)z * D * D,
              bias.p[z], nullptr,
              ChB + (size_t)z * SZA, ClB + (size_t)z * SZA, smem);
}

// output projection: fp32 out
__global__ __launch_bounds__(256, 2) void oproj_gemm_kernel(
    const __nv_bfloat16* __restrict__ Ah, const __nv_bfloat16* __restrict__ Al,
    const __nv_bfloat16* __restrict__ Bh, const __nv_bfloat16* __restrict__ Bl,
    const float* __restrict__ bias, float* __restrict__ C)
{
    extern __shared__ char smem[];
    gemm_body(Ah, Al, Bh, Bl, bias, C, nullptr, nullptr, smem);
}

// ---------------- Attention via HMMA bf16x3 (flash, fragment softmax) -----
#define ASTG 36864
#define AT_VH 18432
#define AT_VL 27648
#define AMS (3 * ASTG)
#define ATTN_SMEM (3 * ASTG + 3 * 256)   // 111360

__global__ __launch_bounds__(256) void attn_mma_kernel(
    const __nv_bfloat16* __restrict__ Qh, const __nv_bfloat16* __restrict__ Ql,
    const __nv_bfloat16* __restrict__ Kh, const __nv_bfloat16* __restrict__ Kl,
    const __nv_bfloat16* __restrict__ Vh, const __nv_bfloat16* __restrict__ Vl,
    const int* __restrict__ mask,
    __nv_bfloat16* __restrict__ Ch, __nv_bfloat16* __restrict__ Cl)
{
    extern __shared__ char smem[];
    const uint32_t sb = smem_u32(smem);
    const int tid = threadIdx.x, lane = tid & 31, wid = tid >> 5;
    const int b = blockIdx.z, h = blockIdx.y, q0 = blockIdx.x * 128;

    // ---- stage Q tile (hi/lo) into smem once, ldsm to fragments ----
#pragma unroll
    for (int t = 0; t < 8; t++) {
        int idx = tid + t * 256;
        int half = idx >> 10;
        int c = idx & 1023;
        int row = c >> 3, ch = c & 7;
        const __nv_bfloat16* src = (half ? Ql : Qh)
            + (size_t)(b * S + q0 + row) * D + h * DK + ch * 8;
        *(uint4*)(smem + half * 18432 + row * 144 + ch * 16) = *(const uint4*)src;
    }
    __syncthreads();
    uint32_t qfh[4][4], qfl[4][4];
    {
        int r = wid * 16 + (lane & 15);
        int hc = lane >> 4;
#pragma unroll
        for (int c = 0; c < 4; c++) {
            ldsm_x4(qfh[c], sb + r * 144 + (c * 2 + hc) * 16);
            ldsm_x4(qfl[c], sb + 18432 + r * 144 + (c * 2 + hc) * 16);
        }
    }
    __syncthreads();

    auto load_stage = [&](int stg, int kk) {
        uint32_t base = sb + stg * ASTG;
#pragma unroll
        for (int t = 0; t < 8; t++) {
            int idx = tid + t * 256;
            int tile = idx >> 9;
            int c = idx & 511;
            int row = c >> 3, ch = c & 7;
            const __nv_bfloat16* g =
                (tile == 0 ? Kh : tile == 1 ? Kl : tile == 2 ? Vh : Vl)
                + (size_t)(b * S + kk + row) * D + h * DK + ch * 8;
            cpa16(base + tile * 9216 + row * 144 + ch * 16, g);
        }
        if (tid < 16)
            cpa16(sb + AMS + stg * 256 + tid * 16,
                  mask + (size_t)b * S + kk + tid * 4);
        asm volatile("cp.async.commit_group;");
    };

    float acc[8][4];
#pragma unroll
    for (int j = 0; j < 8; j++)
#pragma unroll
        for (int v = 0; v < 4; v++) acc[j][v] = 0.f;
    float m0r = -1e30f, m1r = -1e30f, l0r = 0.f, l1r = 0.f;
    const float scale = 0.125f;

    load_stage(0, 0);
    load_stage(1, 64);

    const int bg    = lane >> 3;
    const int b_row = ((bg >> 1) * 8) + (lane & 7);
    const int b_kc  = bg & 1;
    const int tr    = lane & 15;
    const int tc    = lane >> 4;

    int stg = 0;
    for (int it = 0; it < 32; it++) {
        if (it < 31) asm volatile("cp.async.wait_group 1;");
        else         asm volatile("cp.async.wait_group 0;");
        __syncthreads();
        if (it + 2 < 32) {
            int ns = stg + 2; if (ns >= 3) ns -= 3;
            load_stage(ns, (it + 2) * 64);
        }
        const uint32_t st = sb + stg * ASTG;
        const int* msp = (const int*)(smem + AMS + stg * 256);

        float s[8][4];
#pragma unroll
        for (int j = 0; j < 8; j++)
#pragma unroll
            for (int v = 0; v < 4; v++) s[j][v] = 0.f;
#pragma unroll
        for (int c = 0; c < 4; c++) {
#pragma unroll
            for (int np = 0; np < 4; np++) {
                uint32_t kbh[4], kbl[4];
                uint32_t ro = (np * 16 + b_row) * 144 + (c * 2 + b_kc) * 16;
                ldsm_x4(kbh, st + ro);
                ldsm_x4(kbl, st + 9216 + ro);
                mma_bf16(s[np * 2 + 0], qfh[c], kbh[0], kbh[1]);
                mma_bf16(s[np * 2 + 1], qfh[c], kbh[2], kbh[3]);
                mma_bf16(s[np * 2 + 0], qfh[c], kbl[0], kbl[1]);
                mma_bf16(s[np * 2 + 1], qfh[c], kbl[2], kbl[3]);
                mma_bf16(s[np * 2 + 0], qfl[c], kbh[0], kbh[1]);
                mma_bf16(s[np * 2 + 1], qfl[c], kbh[2], kbh[3]);
            }
        }

        float mx0 = -1e30f, mx1 = -1e30f;
#pragma unroll
        for (int nt = 0; nt < 8; nt++) {
            int j0 = nt * 8 + (lane & 3) * 2;
            bool k0m = (msp[j0] != 0), k1m = (msp[j0 + 1] != 0);
            s[nt][0] = k0m ? -1e30f : s[nt][0] * scale;
            s[nt][1] = k1m ? -1e30f : s[nt][1] * scale;
            s[nt][2] = k0m ? -1e30f : s[nt][2] * scale;
            s[nt][3] = k1m ? -1e30f : s[nt][3] * scale;
            mx0 = fmaxf(mx0, fmaxf(s[nt][0], s[nt][1]));
            mx1 = fmaxf(mx1, fmaxf(s[nt][2], s[nt][3]));
        }
#pragma unroll
        for (int off = 1; off < 4; off <<= 1) {
            mx0 = fmaxf(mx0, __shfl_xor_sync(0xffffffffu, mx0, off));
            mx1 = fmaxf(mx1, __shfl_xor_sync(0xffffffffu, mx1, off));
        }
        float mn0 = fmaxf(m0r, mx0), mn1 = fmaxf(m1r, mx1);
        float cr0 = __expf(m0r - mn0), cr1 = __expf(m1r - mn1);
        float sum0 = 0.f, sum1 = 0.f;
#pragma unroll
        for (int nt = 0; nt < 8; nt++) {
            float p0 = (s[nt][0] > -5e29f) ? __expf(s[nt][0] - mn0) : 0.f;
            float p1 = (s[nt][1] > -5e29f) ? __expf(s[nt][1] - mn0) : 0.f;
            float p2 = (s[nt][2] > -5e29f) ? __expf(s[nt][2] - mn1) : 0.f;
            float p3 = (s[nt][3] > -5e29f) ? __expf(s[nt][3] - mn1) : 0.f;
            s[nt][0] = p0; s[nt][1] = p1; s[nt][2] = p2; s[nt][3] = p3;
            sum0 += p0 + p1;
            sum1 += p2 + p3;
        }
#pragma unroll
        for (int off = 1; off < 4; off <<= 1) {
            sum0 += __shfl_xor_sync(0xffffffffu, sum0, off);
            sum1 += __shfl_xor_sync(0xffffffffu, sum1, off);
        }
        l0r = l0r * cr0 + sum0;
        l1r = l1r * cr1 + sum1;
        m0r = mn0; m1r = mn1;
#pragma unroll
        for (int nt = 0; nt < 8; nt++) {
            acc[nt][0] *= cr0; acc[nt][1] *= cr0;
            acc[nt][2] *= cr1; acc[nt][3] *= cr1;
        }

        uint32_t pah[4][4], pal[4][4];
#pragma unroll
        for (int c = 0; c < 4; c++) {
            split2(s[2 * c][0],     s[2 * c][1],     pah[c][0], pal[c][0]);
            split2(s[2 * c][2],     s[2 * c][3],     pah[c][1], pal[c][1]);
            split2(s[2 * c + 1][0], s[2 * c + 1][1], pah[c][2], pal[c][2]);
            split2(s[2 * c + 1][2], s[2 * c + 1][3], pah[c][3], pal[c][3]);
        }

#pragma unroll
        for (int c = 0; c < 4; c++) {
#pragma unroll
            for (int np = 0; np < 4; np++) {
                uint32_t vbh[4], vbl[4];
                uint32_t ro = (c * 16 + tr) * 144 + np * 32 + tc * 16;
                ldsm_x4_t(vbh, st + AT_VH + ro);
                ldsm_x4_t(vbl, st + AT_VL + ro);
                mma_bf16(acc[np * 2 + 0], pah[c], vbh[0], vbh[1]);
                mma_bf16(acc[np * 2 + 1], pah[c], vbh[2], vbh[3]);
                mma_bf16(acc[np * 2 + 0], pah[c], vbl[0], vbl[1]);
                mma_bf16(acc[np * 2 + 1], pah[c], vbl[2], vbl[3]);
                mma_bf16(acc[np * 2 + 0], pal[c], vbh[0], vbh[1]);
                mma_bf16(acc[np * 2 + 1], pal[c], vbh[2], vbh[3]);
            }
        }
        __syncthreads();
        if (++stg == 3) stg = 0;
    }

    // ---- epilogue: write context as bf16 hi/lo directly ----
    float inv0 = (l0r > 0.f) ? (1.f / l0r) : 0.f;
    float inv1 = (l1r > 0.f) ? (1.f / l1r) : 0.f;
    int r0 = q0 + wid * 16 + (lane >> 2);
#pragma unroll
    for (int nt = 0; nt < 8; nt++) {
        int c = h * DK + nt * 8 + (lane & 3) * 2;
        uint32_t h0, l0, h1, l1;
        split2(acc[nt][0] * inv0, acc[nt][1] * inv0, h0, l0);
        split2(acc[nt][2] * inv1, acc[nt][3] * inv1, h1, l1);
        size_t o0 = (size_t)(b * S + r0) * D + c;
        size_t o1 = (size_t)(b * S + r0 + 8) * D + c;
        *(uint32_t*)&Ch[o0] = h0;
        *(uint32_t*)&Cl[o0] = l0;
        *(uint32_t*)&Ch[o1] = h1;
        *(uint32_t*)&Cl[o1] = l1;
    }
}

// ---------------- launch ----------------
extern "C" void kernel_launch(void* const* d_in, const int* in_sizes, int n_in,
                              void* d_out, int out_size)
{
    const float* query = (const float*)d_in[0];
    const float* key   = (const float*)d_in[1];
    const float* value = (const float*)d_in[2];
    const int*   mask  = (const int*)d_in[3];
    const float* Wq = (const float*)d_in[4];
    const float* bq = (const float*)d_in[5];
    const float* Wk = (const float*)d_in[6];
    const float* bk = (const float*)d_in[7];
    const float* Wv = (const float*)d_in[8];
    const float* bv = (const float*)d_in[9];
    const float* Wo = (const float*)d_in[10];
    const float* bo = (const float*)d_in[11];
    float* out = (float*)d_out;

    __nv_bfloat16 *ah, *al, *bh, *bl;
    cudaGetSymbolAddress((void**)&ah, g_Ah);
    cudaGetSymbolAddress((void**)&al, g_Al);
    cudaGetSymbolAddress((void**)&bh, g_Bh);
    cudaGetSymbolAddress((void**)&bl, g_Bl);

    static int attr_set = 0;
    if (!attr_set) {
        cudaFuncSetAttribute(qkv_gemm_kernel,
                             cudaFuncAttributeMaxDynamicSharedMemorySize, GEMM_SMEM);
        cudaFuncSetAttribute(oproj_gemm_kernel,
                             cudaFuncAttributeMaxDynamicSharedMemorySize, GEMM_SMEM);
        cudaFuncSetAttribute(attn_mma_kernel,
                             cudaFuncAttributeMaxDynamicSharedMemorySize, ATTN_SMEM);
        attr_set = 1;
    }

    const int n4_act = SZA / 4;

    // 0: split all three inputs -> slots 0..2
    FPtr3 xin; xin.p[0] = query; xin.p[1] = key; xin.p[2] = value;
    dim3 sa_grid((n4_act + 255) / 256, 3);
    split_act3_kernel<<<sa_grid, 256>>>(xin, ah, al, n4_act);

    // 1: split all four weights -> slots 0..3
    FPtr4 win; win.p[0] = Wq; win.p[1] = Wk; win.p[2] = Wv; win.p[3] = Wo;
    dim3 sw_grid(D / 32, D / 32, 4);
    split_wt4_kernel<<<sw_grid, 256>>>(win, bh, bl);

    // 2: batched Q/K/V projections: slots 0..2 -> slots 3..5 (bf16 hi/lo)
    QKVBias qb; qb.p[0] = bq; qb.p[1] = bk; qb.p[2] = bv;
    dim3 qkv_grid(GN / 64, M_ROWS / 128, 3);
    qkv_gemm_kernel<<<qkv_grid, 256, GEMM_SMEM>>>(
        ah, al, bh, bl, qb, ah + (size_t)3 * SZA, al + (size_t)3 * SZA);

    // 3: attention: slots 3..5 -> slot 6 (bf16 hi/lo ctx)
    dim3 attn_grid(S / 128, H, B);
    attn_mma_kernel<<<attn_grid, 256, ATTN_SMEM>>>(
        ah + (size_t)3 * SZA, al + (size_t)3 * SZA,
        ah + (size_t)4 * SZA, al + (size_t)4 * SZA,
        ah + (size_t)5 * SZA, al + (size_t)5 * SZA,
        mask,
        ah + (size_t)6 * SZA, al + (size_t)6 * SZA);

    // 4: output projection: slot 6 @ Wo -> fp32 out
    dim3 gemm_grid(GN / 64, M_ROWS / 128);
    oproj_gemm_kernel<<<gemm_grid, 256, GEMM_SMEM>>>(
        ah + (size_t)6 * SZA, al + (size_t)6 * SZA,
        bh + (size_t)3 * D * D, bl + (size_t)3 * D * D, bo, out);
}

// round 9
// speedup vs baseline: 3.1637x; 1.1026x over previous
#include <cuda_runtime.h>
#include <cuda_bf16.h>
#include <math.h>
#include <stdint.h>

// Problem constants
#define B  2
#define S  2048
#define D  1024
#define H  16
#define DK 64
#define M_ROWS (B * S)   // 4096
#define GK 1024
#define GN 1024
#define SZA (M_ROWS * D)

// ---------------- scratch (device globals: allocation-free) ----------------
__device__ __nv_bfloat16 g_Ah[7][SZA];
__device__ __nv_bfloat16 g_Al[7][SZA];
__device__ __nv_bfloat16 g_Bh[4][D * D];
__device__ __nv_bfloat16 g_Bl[4][D * D];

struct FPtr3 { const float* p[3]; };
struct FPtr4 { const float* p[4]; };

__device__ __forceinline__ uint32_t smem_u32(const void* p) {
    uint32_t a;
    asm("{ .reg .u64 t; cvta.to.shared.u64 t, %1; cvt.u32.u64 %0, t; }"
        : "=r"(a) : "l"(p));
    return a;
}
__device__ __forceinline__ void ldsm_x4(uint32_t (&r)[4], uint32_t addr) {
    asm volatile("ldmatrix.sync.aligned.m8n8.x4.shared.b16 {%0,%1,%2,%3}, [%4];"
                 : "=r"(r[0]), "=r"(r[1]), "=r"(r[2]), "=r"(r[3]) : "r"(addr));
}
__device__ __forceinline__ void ldsm_x4_t(uint32_t (&r)[4], uint32_t addr) {
    asm volatile("ldmatrix.sync.aligned.m8n8.x4.trans.shared.b16 {%0,%1,%2,%3}, [%4];"
                 : "=r"(r[0]), "=r"(r[1]), "=r"(r[2]), "=r"(r[3]) : "r"(addr));
}
__device__ __forceinline__ void mma_bf16(float (&d)[4],
    const uint32_t (&a)[4], uint32_t b0, uint32_t b1)
{
    asm volatile(
        "mma.sync.aligned.m16n8k16.row.col.f32.bf16.bf16.f32 "
        "{%0,%1,%2,%3}, {%4,%5,%6,%7}, {%8,%9}, {%0,%1,%2,%3};"
        : "+f"(d[0]), "+f"(d[1]), "+f"(d[2]), "+f"(d[3])
        : "r"(a[0]), "r"(a[1]), "r"(a[2]), "r"(a[3]), "r"(b0), "r"(b1));
}
__device__ __forceinline__ void cpa16(uint32_t sd, const void* gs) {
    asm volatile("cp.async.cg.shared.global [%0], [%1], 16;" :: "r"(sd), "l"(gs));
}
__device__ __forceinline__ void split2(float f0, float f1, uint32_t& hi, uint32_t& lo) {
    __nv_bfloat16 h0 = __float2bfloat16(f0), h1 = __float2bfloat16(f1);
    __nv_bfloat16 l0 = __float2bfloat16(f0 - __bfloat162float(h0));
    __nv_bfloat16 l1 = __float2bfloat16(f1 - __bfloat162float(h1));
    hi = (uint32_t)*(uint16_t*)&h0 | ((uint32_t)*(uint16_t*)&h1 << 16);
    lo = (uint32_t)*(uint16_t*)&l0 | ((uint32_t)*(uint16_t*)&l1 << 16);
}

// ---------------- batched split kernels ----------------
__global__ __launch_bounds__(256) void split_act3_kernel(
    FPtr3 X, __nv_bfloat16* __restrict__ XhB, __nv_bfloat16* __restrict__ XlB, int n4)
{
    int z = blockIdx.y;
    int i = blockIdx.x * 256 + threadIdx.x;
    if (i >= n4) return;
    float4 v = ((const float4*)X.p[z])[i];
    __nv_bfloat16* Xh = XhB + (size_t)z * SZA;
    __nv_bfloat16* Xl = XlB + (size_t)z * SZA;
    float f[4] = {v.x, v.y, v.z, v.w};
    __nv_bfloat16 h[4], l[4];
#pragma unroll
    for (int j = 0; j < 4; j++) {
        h[j] = __float2bfloat16(f[j]);
        l[j] = __float2bfloat16(f[j] - __bfloat162float(h[j]));
    }
    *(__nv_bfloat162*)&Xh[i * 4 + 0] = __nv_bfloat162(h[0], h[1]);
    *(__nv_bfloat162*)&Xh[i * 4 + 2] = __nv_bfloat162(h[2], h[3]);
    *(__nv_bfloat162*)&Xl[i * 4 + 0] = __nv_bfloat162(l[0], l[1]);
    *(__nv_bfloat162*)&Xl[i * 4 + 2] = __nv_bfloat162(l[2], l[3]);
}

__global__ __launch_bounds__(256) void split_wt4_kernel(
    FPtr4 W, __nv_bfloat16* __restrict__ WthB, __nv_bfloat16* __restrict__ WtlB)
{
    __shared__ float t[32][33];
    int z = blockIdx.z;
    int k0 = blockIdx.y * 32, n0 = blockIdx.x * 32;
    int tx = threadIdx.x & 31, ty = threadIdx.x >> 5;
    const float* Wp = W.p[z];
    __nv_bfloat16* Wth = WthB + (size_t)z * D * D;
    __nv_bfloat16* Wtl = WtlB + (size_t)z * D * D;
#pragma unroll
    for (int i = 0; i < 4; i++)
        t[ty + i * 8][tx] = Wp[(size_t)(k0 + ty + i * 8) * D + n0 + tx];
    __syncthreads();
#pragma unroll
    for (int i = 0; i < 4; i++) {
        float v = t[tx][ty + i * 8];
        __nv_bfloat16 h = __float2bfloat16(v);
        __nv_bfloat16 l = __float2bfloat16(v - __bfloat162float(h));
        size_t o = (size_t)(n0 + ty + i * 8) * D + k0 + tx;
        Wth[o] = h;
        Wtl[o] = l;
    }
}

// ---------------- bf16x3 GEMM body ----------------
#define BK 32
#define NCH (GK / BK)
#define OFF_AL 10240
#define OFF_BH 20480
#define OFF_BL 25600
#define STAGE_SB 30720
#define GEMM_SMEM (3 * STAGE_SB)

__device__ __forceinline__ void gemm_body(
    const __nv_bfloat16* __restrict__ Ah, const __nv_bfloat16* __restrict__ Al,
    const __nv_bfloat16* __restrict__ Bh, const __nv_bfloat16* __restrict__ Bl,
    const float* __restrict__ bias, float* __restrict__ C,
    __nv_bfloat16* __restrict__ Ch, __nv_bfloat16* __restrict__ Cl,
    char* smem)
{
    const uint32_t sbase = smem_u32(smem);
    const int tid = threadIdx.x;
    const int lane = tid & 31;
    const int wid = tid >> 5;
    const int warp_m = wid & 3;
    const int warp_n = wid >> 2;
    const int m0 = blockIdx.y * 128;
    const int n0 = blockIdx.x * 64;

    const __nv_bfloat16* gAh = Ah + (size_t)m0 * GK;
    const __nv_bfloat16* gAl = Al + (size_t)m0 * GK;
    const __nv_bfloat16* gBh = Bh + (size_t)n0 * GK;
    const __nv_bfloat16* gBl = Bl + (size_t)n0 * GK;

    const int lrow = tid >> 2;
    const int lc   = tid & 3;

    auto load_stage = [&](int stg, int k0) {
        uint32_t sb = sbase + stg * STAGE_SB;
#pragma unroll
        for (int j = 0; j < 2; j++) {
            int row = lrow + j * 64;
            uint32_t so = row * 80 + lc * 16;
            size_t go = (size_t)row * GK + k0 + lc * 8;
            cpa16(sb + so,          gAh + go);
            cpa16(sb + OFF_AL + so, gAl + go);
        }
        {
            uint32_t so = lrow * 80 + lc * 16;
            size_t go = (size_t)lrow * GK + k0 + lc * 8;
            cpa16(sb + OFF_BH + so, gBh + go);
            cpa16(sb + OFF_BL + so, gBl + go);
        }
        asm volatile("cp.async.commit_group;");
    };

    float acc[2][4][4];
#pragma unroll
    for (int i = 0; i < 2; i++)
#pragma unroll
        for (int j = 0; j < 4; j++)
#pragma unroll
            for (int v = 0; v < 4; v++) acc[i][j][v] = 0.f;

    load_stage(0, 0);
    load_stage(1, BK);

    const int a_row = lane & 15;
    const int a_kc  = lane >> 4;
    const int bg    = lane >> 3;
    const int b_row = ((bg >> 1) * 8) + (lane & 7);
    const int b_kc  = bg & 1;

    int stg = 0;
    for (int ch = 0; ch < NCH; ch++) {
        if (ch < NCH - 1) asm volatile("cp.async.wait_group 1;");
        else              asm volatile("cp.async.wait_group 0;");
        __syncthreads();
        if (ch + 2 < NCH) {
            int ns = stg + 2; if (ns >= 3) ns -= 3;
            load_stage(ns, (ch + 2) * BK);
        }
        const uint32_t st = sbase + stg * STAGE_SB;
#pragma unroll
        for (int kc = 0; kc < 2; kc++) {
            uint32_t a_h[2][4], a_l[2][4], b_h[2][4], b_l[2][4];
#pragma unroll
            for (int mt = 0; mt < 2; mt++) {
                uint32_t ro = (warp_m * 32 + mt * 16 + a_row) * 80
                            + (kc * 2 + a_kc) * 16;
                ldsm_x4(a_h[mt], st + ro);
                ldsm_x4(a_l[mt], st + OFF_AL + ro);
            }
#pragma unroll
            for (int ng = 0; ng < 2; ng++) {
                uint32_t ro = (warp_n * 32 + ng * 16 + b_row) * 80
                            + (kc * 2 + b_kc) * 16;
                ldsm_x4(b_h[ng], st + OFF_BH + ro);
                ldsm_x4(b_l[ng], st + OFF_BL + ro);
            }
#pragma unroll
            for (int mt = 0; mt < 2; mt++)
#pragma unroll
                for (int ng = 0; ng < 2; ng++) {
                    mma_bf16(acc[mt][ng * 2 + 0], a_h[mt], b_h[ng][0], b_h[ng][1]);
                    mma_bf16(acc[mt][ng * 2 + 1], a_h[mt], b_h[ng][2], b_h[ng][3]);
                }
#pragma unroll
            for (int mt = 0; mt < 2; mt++)
#pragma unroll
                for (int ng = 0; ng < 2; ng++) {
                    mma_bf16(acc[mt][ng * 2 + 0], a_h[mt], b_l[ng][0], b_l[ng][1]);
                    mma_bf16(acc[mt][ng * 2 + 1], a_h[mt], b_l[ng][2], b_l[ng][3]);
                }
#pragma unroll
            for (int mt = 0; mt < 2; mt++)
#pragma unroll
                for (int ng = 0; ng < 2; ng++) {
                    mma_bf16(acc[mt][ng * 2 + 0], a_l[mt], b_h[ng][0], b_h[ng][1]);
                    mma_bf16(acc[mt][ng * 2 + 1], a_l[mt], b_h[ng][2], b_h[ng][3]);
                }
        }
        __syncthreads();
        if (++stg == 3) stg = 0;
    }

    const int grp = lane >> 2, tg = lane & 3;
#pragma unroll
    for (int mt = 0; mt < 2; mt++) {
        int r0 = m0 + warp_m * 32 + mt * 16 + grp;
#pragma unroll
        for (int nt = 0; nt < 4; nt++) {
            int c = n0 + warp_n * 32 + nt * 8 + tg * 2;
            float2 b2 = *(const float2*)&bias[c];
            float o00 = acc[mt][nt][0] + b2.x;
            float o01 = acc[mt][nt][1] + b2.y;
            float o10 = acc[mt][nt][2] + b2.x;
            float o11 = acc[mt][nt][3] + b2.y;
            if (C) {
                *(float2*)&C[(size_t)r0 * GN + c] = make_float2(o00, o01);
                *(float2*)&C[(size_t)(r0 + 8) * GN + c] = make_float2(o10, o11);
            } else {
                uint32_t h0, l0, h1, l1;
                split2(o00, o01, h0, l0);
                split2(o10, o11, h1, l1);
                *(uint32_t*)&Ch[(size_t)r0 * GN + c] = h0;
                *(uint32_t*)&Cl[(size_t)r0 * GN + c] = l0;
                *(uint32_t*)&Ch[(size_t)(r0 + 8) * GN + c] = h1;
                *(uint32_t*)&Cl[(size_t)(r0 + 8) * GN + c] = l1;
            }
        }
    }
}

struct QKVBias { const float* p[3]; };

__global__ __launch_bounds__(256, 2) void qkv_gemm_kernel(
    const __nv_bfloat16* __restrict__ AhB, const __nv_bfloat16* __restrict__ AlB,
    const __nv_bfloat16* __restrict__ BhB, const __nv_bfloat16* __restrict__ BlB,
    QKVBias bias,
    __nv_bfloat16* __restrict__ ChB, __nv_bfloat16* __restrict__ ClB)
{
    extern __shared__ char smem[];
    const int z = blockIdx.z;
    gemm_body(AhB + (size_t)z * SZA, AlB + (size_t)z * SZA,
              BhB + (size_t)z * D * D, BlB + (size_t)z * D * D,
              bias.p[z], nullptr,
              ChB + (size_t)z * SZA, ClB + (size_t)z * SZA, smem);
}

__global__ __launch_bounds__(256, 2) void oproj_gemm_kernel(
    const __nv_bfloat16* __restrict__ Ah, const __nv_bfloat16* __restrict__ Al,
    const __nv_bfloat16* __restrict__ Bh, const __nv_bfloat16* __restrict__ Bl,
    const float* __restrict__ bias, float* __restrict__ C)
{
    extern __shared__ char smem[];
    gemm_body(Ah, Al, Bh, Bl, bias, C, nullptr, nullptr, smem);
}

// ---------------- Attention via HMMA bf16x3, 2-stage, 2 CTAs/SM ----------
#define ASTG 36864
#define AT_VH 18432
#define AT_VL 27648
#define AMS (2 * ASTG)
#define ATTN_SMEM (2 * ASTG + 2 * 256)   // 74240

__global__ __launch_bounds__(256, 2) void attn_mma_kernel(
    const __nv_bfloat16* __restrict__ Qh, const __nv_bfloat16* __restrict__ Ql,
    const __nv_bfloat16* __restrict__ Kh, const __nv_bfloat16* __restrict__ Kl,
    const __nv_bfloat16* __restrict__ Vh, const __nv_bfloat16* __restrict__ Vl,
    const int* __restrict__ mask,
    __nv_bfloat16* __restrict__ Ch, __nv_bfloat16* __restrict__ Cl)
{
    extern __shared__ char smem[];
    const uint32_t sb = smem_u32(smem);
    const int tid = threadIdx.x, lane = tid & 31, wid = tid >> 5;
    const int b = blockIdx.z, h = blockIdx.y, q0 = blockIdx.x * 128;

    // ---- stage Q tile (hi/lo) into smem once, ldsm to fragments ----
#pragma unroll
    for (int t = 0; t < 8; t++) {
        int idx = tid + t * 256;
        int half = idx >> 10;
        int c = idx & 1023;
        int row = c >> 3, ch = c & 7;
        const __nv_bfloat16* src = (half ? Ql : Qh)
            + (size_t)(b * S + q0 + row) * D + h * DK + ch * 8;
        *(uint4*)(smem + half * 18432 + row * 144 + ch * 16) = *(const uint4*)src;
    }
    __syncthreads();
    uint32_t qfh[4][4], qfl[4][4];
    {
        int r = wid * 16 + (lane & 15);
        int hc = lane >> 4;
#pragma unroll
        for (int c = 0; c < 4; c++) {
            ldsm_x4(qfh[c], sb + r * 144 + (c * 2 + hc) * 16);
            ldsm_x4(qfl[c], sb + 18432 + r * 144 + (c * 2 + hc) * 16);
        }
    }
    __syncthreads();

    auto load_stage = [&](int stg, int kk) {
        uint32_t base = sb + stg * ASTG;
#pragma unroll
        for (int t = 0; t < 8; t++) {
            int idx = tid + t * 256;
            int tile = idx >> 9;
            int c = idx & 511;
            int row = c >> 3, ch = c & 7;
            const __nv_bfloat16* g =
                (tile == 0 ? Kh : tile == 1 ? Kl : tile == 2 ? Vh : Vl)
                + (size_t)(b * S + kk + row) * D + h * DK + ch * 8;
            cpa16(base + tile * 9216 + row * 144 + ch * 16, g);
        }
        if (tid < 16)
            cpa16(sb + AMS + stg * 256 + tid * 16,
                  mask + (size_t)b * S + kk + tid * 4);
        asm volatile("cp.async.commit_group;");
    };

    float acc[8][4];
#pragma unroll
    for (int j = 0; j < 8; j++)
#pragma unroll
        for (int v = 0; v < 4; v++) acc[j][v] = 0.f;
    float m0r = -1e30f, m1r = -1e30f, l0r = 0.f, l1r = 0.f;
    const float scale = 0.125f;

    load_stage(0, 0);
    load_stage(1, 64);

    const int bg    = lane >> 3;
    const int b_row = ((bg >> 1) * 8) + (lane & 7);
    const int b_kc  = bg & 1;
    const int tr    = lane & 15;
    const int tc    = lane >> 4;

    for (int it = 0; it < 32; it++) {
        const int stg = it & 1;
        if (it < 31) asm volatile("cp.async.wait_group 1;");
        else         asm volatile("cp.async.wait_group 0;");
        __syncthreads();

        const uint32_t st = sb + stg * ASTG;
        const int* msp = (const int*)(smem + AMS + stg * 256);

        float s[8][4];
#pragma unroll
        for (int j = 0; j < 8; j++)
#pragma unroll
            for (int v = 0; v < 4; v++) s[j][v] = 0.f;
#pragma unroll
        for (int c = 0; c < 4; c++) {
#pragma unroll
            for (int np = 0; np < 4; np++) {
                uint32_t kbh[4], kbl[4];
                uint32_t ro = (np * 16 + b_row) * 144 + (c * 2 + b_kc) * 16;
                ldsm_x4(kbh, st + ro);
                ldsm_x4(kbl, st + 9216 + ro);
                mma_bf16(s[np * 2 + 0], qfh[c], kbh[0], kbh[1]);
                mma_bf16(s[np * 2 + 1], qfh[c], kbh[2], kbh[3]);
                mma_bf16(s[np * 2 + 0], qfh[c], kbl[0], kbl[1]);
                mma_bf16(s[np * 2 + 1], qfh[c], kbl[2], kbl[3]);
                mma_bf16(s[np * 2 + 0], qfl[c], kbh[0], kbh[1]);
                mma_bf16(s[np * 2 + 1], qfl[c], kbh[2], kbh[3]);
            }
        }

        float mx0 = -1e30f, mx1 = -1e30f;
#pragma unroll
        for (int nt = 0; nt < 8; nt++) {
            int j0 = nt * 8 + (lane & 3) * 2;
            bool k0m = (msp[j0] != 0), k1m = (msp[j0 + 1] != 0);
            s[nt][0] = k0m ? -1e30f : s[nt][0] * scale;
            s[nt][1] = k1m ? -1e30f : s[nt][1] * scale;
            s[nt][2] = k0m ? -1e30f : s[nt][2] * scale;
            s[nt][3] = k1m ? -1e30f : s[nt][3] * scale;
            mx0 = fmaxf(mx0, fmaxf(s[nt][0], s[nt][1]));
            mx1 = fmaxf(mx1, fmaxf(s[nt][2], s[nt][3]));
        }
#pragma unroll
        for (int off = 1; off < 4; off <<= 1) {
            mx0 = fmaxf(mx0, __shfl_xor_sync(0xffffffffu, mx0, off));
            mx1 = fmaxf(mx1, __shfl_xor_sync(0xffffffffu, mx1, off));
        }
        float mn0 = fmaxf(m0r, mx0), mn1 = fmaxf(m1r, mx1);
        float cr0 = __expf(m0r - mn0), cr1 = __expf(m1r - mn1);
        float sum0 = 0.f, sum1 = 0.f;
#pragma unroll
        for (int nt = 0; nt < 8; nt++) {
            float p0 = (s[nt][0] > -5e29f) ? __expf(s[nt][0] - mn0) : 0.f;
            float p1 = (s[nt][1] > -5e29f) ? __expf(s[nt][1] - mn0) : 0.f;
            float p2 = (s[nt][2] > -5e29f) ? __expf(s[nt][2] - mn1) : 0.f;
            float p3 = (s[nt][3] > -5e29f) ? __expf(s[nt][3] - mn1) : 0.f;
            s[nt][0] = p0; s[nt][1] = p1; s[nt][2] = p2; s[nt][3] = p3;
            sum0 += p0 + p1;
            sum1 += p2 + p3;
        }
#pragma unroll
        for (int off = 1; off < 4; off <<= 1) {
            sum0 += __shfl_xor_sync(0xffffffffu, sum0, off);
            sum1 += __shfl_xor_sync(0xffffffffu, sum1, off);
        }
        l0r = l0r * cr0 + sum0;
        l1r = l1r * cr1 + sum1;
        m0r = mn0; m1r = mn1;
#pragma unroll
        for (int nt = 0; nt < 8; nt++) {
            acc[nt][0] *= cr0; acc[nt][1] *= cr0;
            acc[nt][2] *= cr1; acc[nt][3] *= cr1;
        }

        uint32_t pah[4][4], pal[4][4];
#pragma unroll
        for (int c = 0; c < 4; c++) {
            split2(s[2 * c][0],     s[2 * c][1],     pah[c][0], pal[c][0]);
            split2(s[2 * c][2],     s[2 * c][3],     pah[c][1], pal[c][1]);
            split2(s[2 * c + 1][0], s[2 * c + 1][1], pah[c][2], pal[c][2]);
            split2(s[2 * c + 1][2], s[2 * c + 1][3], pah[c][3], pal[c][3]);
        }

#pragma unroll
        for (int c = 0; c < 4; c++) {
#pragma unroll
            for (int np = 0; np < 4; np++) {
                uint32_t vbh[4], vbl[4];
                uint32_t ro = (c * 16 + tr) * 144 + np * 32 + tc * 16;
                ldsm_x4_t(vbh, st + AT_VH + ro);
                ldsm_x4_t(vbl, st + AT_VL + ro);
                mma_bf16(acc[np * 2 + 0], pah[c], vbh[0], vbh[1]);
                mma_bf16(acc[np * 2 + 1], pah[c], vbh[2], vbh[3]);
                mma_bf16(acc[np * 2 + 0], pah[c], vbl[0], vbl[1]);
                mma_bf16(acc[np * 2 + 1], pah[c], vbl[2], vbl[3]);
                mma_bf16(acc[np * 2 + 0], pal[c], vbh[0], vbh[1]);
                mma_bf16(acc[np * 2 + 1], pal[c], vbh[2], vbh[3]);
            }
        }
        __syncthreads();
        // 2-stage: refill this stage slot for chunk it+2 (overlaps it+1 compute)
        if (it + 2 < 32) load_stage(stg, (it + 2) * 64);
    }

    // ---- epilogue: write context as bf16 hi/lo directly ----
    float inv0 = (l0r > 0.f) ? (1.f / l0r) : 0.f;
    float inv1 = (l1r > 0.f) ? (1.f / l1r) : 0.f;
    int r0 = q0 + wid * 16 + (lane >> 2);
#pragma unroll
    for (int nt = 0; nt < 8; nt++) {
        int c = h * DK + nt * 8 + (lane & 3) * 2;
        uint32_t h0, l0, h1, l1;
        split2(acc[nt][0] * inv0, acc[nt][1] * inv0, h0, l0);
        split2(acc[nt][2] * inv1, acc[nt][3] * inv1, h1, l1);
        size_t o0 = (size_t)(b * S + r0) * D + c;
        size_t o1 = (size_t)(b * S + r0 + 8) * D + c;
        *(uint32_t*)&Ch[o0] = h0;
        *(uint32_t*)&Cl[o0] = l0;
        *(uint32_t*)&Ch[o1] = h1;
        *(uint32_t*)&Cl[o1] = l1;
    }
}

// ---------------- launch ----------------
extern "C" void kernel_launch(void* const* d_in, const int* in_sizes, int n_in,
                              void* d_out, int out_size)
{
    const float* query = (const float*)d_in[0];
    const float* key   = (const float*)d_in[1];
    const float* value = (const float*)d_in[2];
    const int*   mask  = (const int*)d_in[3];
    const float* Wq = (const float*)d_in[4];
    const float* bq = (const float*)d_in[5];
    const float* Wk = (const float*)d_in[6];
    const float* bk = (const float*)d_in[7];
    const float* Wv = (const float*)d_in[8];
    const float* bv = (const float*)d_in[9];
    const float* Wo = (const float*)d_in[10];
    const float* bo = (const float*)d_in[11];
    float* out = (float*)d_out;

    __nv_bfloat16 *ah, *al, *bh, *bl;
    cudaGetSymbolAddress((void**)&ah, g_Ah);
    cudaGetSymbolAddress((void**)&al, g_Al);
    cudaGetSymbolAddress((void**)&bh, g_Bh);
    cudaGetSymbolAddress((void**)&bl, g_Bl);

    static int attr_set = 0;
    if (!attr_set) {
        cudaFuncSetAttribute(qkv_gemm_kernel,
                             cudaFuncAttributeMaxDynamicSharedMemorySize, GEMM_SMEM);
        cudaFuncSetAttribute(oproj_gemm_kernel,
                             cudaFuncAttributeMaxDynamicSharedMemorySize, GEMM_SMEM);
        cudaFuncSetAttribute(attn_mma_kernel,
                             cudaFuncAttributeMaxDynamicSharedMemorySize, ATTN_SMEM);
        attr_set = 1;
    }

    const int n4_act = SZA / 4;

    FPtr3 xin; xin.p[0] = query; xin.p[1] = key; xin.p[2] = value;
    dim3 sa_grid((n4_act + 255) / 256, 3);
    split_act3_kernel<<<sa_grid, 256>>>(xin, ah, al, n4_act);

    FPtr4 win; win.p[0] = Wq; win.p[1] = Wk; win.p[2] = Wv; win.p[3] = Wo;
    dim3 sw_grid(D / 32, D / 32, 4);
    split_wt4_kernel<<<sw_grid, 256>>>(win, bh, bl);

    QKVBias qb; qb.p[0] = bq; qb.p[1] = bk; qb.p[2] = bv;
    dim3 qkv_grid(GN / 64, M_ROWS / 128, 3);
    qkv_gemm_kernel<<<qkv_grid, 256, GEMM_SMEM>>>(
        ah, al, bh, bl, qb, ah + (size_t)3 * SZA, al + (size_t)3 * SZA);

    dim3 attn_grid(S / 128, H, B);
    attn_mma_kernel<<<attn_grid, 256, ATTN_SMEM>>>(
        ah + (size_t)3 * SZA, al + (size_t)3 * SZA,
        ah + (size_t)4 * SZA, al + (size_t)4 * SZA,
        ah + (size_t)5 * SZA, al + (size_t)5 * SZA,
        mask,
        ah + (size_t)6 * SZA, al + (size_t)6 * SZA);

    dim3 gemm_grid(GN / 64, M_ROWS / 128);
    oproj_gemm_kernel<<<gemm_grid, 256, GEMM_SMEM>>>(
        ah + (size_t)6 * SZA, al + (size_t)6 * SZA,
        bh + (size_t)3 * D * D, bl + (size_t)3 * D * D, bo, out);
}

// round 10
// speedup vs baseline: 3.9327x; 1.2431x over previous
#include <cuda_runtime.h>
#include <cuda_bf16.h>
#include <math.h>
#include <stdint.h>

// Problem constants
#define B  2
#define S  2048
#define D  1024
#define H  16
#define DK 64
#define M_ROWS (B * S)   // 4096
#define GK 1024
#define GN 1024
#define SZA (M_ROWS * D)

// ---------------- scratch (device globals: allocation-free) ----------------
// slots: 0..2 split inputs; 3..5 projected q,k,v; 6 ctx; 7 compact K; 8 compact V
__device__ __nv_bfloat16 g_Ah[9][SZA];
__device__ __nv_bfloat16 g_Al[9][SZA];
__device__ __nv_bfloat16 g_Bh[4][D * D];
__device__ __nv_bfloat16 g_Bl[4][D * D];
__device__ int g_gidx[B * S];
__device__ int g_cnt[B];

struct FPtr3 { const float* p[3]; };
struct FPtr4 { const float* p[4]; };

__device__ __forceinline__ uint32_t smem_u32(const void* p) {
    uint32_t a;
    asm("{ .reg .u64 t; cvta.to.shared.u64 t, %1; cvt.u32.u64 %0, t; }"
        : "=r"(a) : "l"(p));
    return a;
}
__device__ __forceinline__ void ldsm_x4(uint32_t (&r)[4], uint32_t addr) {
    asm volatile("ldmatrix.sync.aligned.m8n8.x4.shared.b16 {%0,%1,%2,%3}, [%4];"
                 : "=r"(r[0]), "=r"(r[1]), "=r"(r[2]), "=r"(r[3]) : "r"(addr));
}
__device__ __forceinline__ void ldsm_x4_t(uint32_t (&r)[4], uint32_t addr) {
    asm volatile("ldmatrix.sync.aligned.m8n8.x4.trans.shared.b16 {%0,%1,%2,%3}, [%4];"
                 : "=r"(r[0]), "=r"(r[1]), "=r"(r[2]), "=r"(r[3]) : "r"(addr));
}
__device__ __forceinline__ void mma_bf16(float (&d)[4],
    const uint32_t (&a)[4], uint32_t b0, uint32_t b1)
{
    asm volatile(
        "mma.sync.aligned.m16n8k16.row.col.f32.bf16.bf16.f32 "
        "{%0,%1,%2,%3}, {%4,%5,%6,%7}, {%8,%9}, {%0,%1,%2,%3};"
        : "+f"(d[0]), "+f"(d[1]), "+f"(d[2]), "+f"(d[3])
        : "r"(a[0]), "r"(a[1]), "r"(a[2]), "r"(a[3]), "r"(b0), "r"(b1));
}
__device__ __forceinline__ void cpa16(uint32_t sd, const void* gs) {
    asm volatile("cp.async.cg.shared.global [%0], [%1], 16;" :: "r"(sd), "l"(gs));
}
__device__ __forceinline__ void split2(float f0, float f1, uint32_t& hi, uint32_t& lo) {
    __nv_bfloat16 h0 = __float2bfloat16(f0), h1 = __float2bfloat16(f1);
    __nv_bfloat16 l0 = __float2bfloat16(f0 - __bfloat162float(h0));
    __nv_bfloat16 l1 = __float2bfloat16(f1 - __bfloat162float(h1));
    hi = (uint32_t)*(uint16_t*)&h0 | ((uint32_t)*(uint16_t*)&h1 << 16);
    lo = (uint32_t)*(uint16_t*)&l0 | ((uint32_t)*(uint16_t*)&l1 << 16);
}

// ---------------- batched split kernels ----------------
__global__ __launch_bounds__(256) void split_act3_kernel(
    FPtr3 X, __nv_bfloat16* __restrict__ XhB, __nv_bfloat16* __restrict__ XlB, int n4)
{
    int z = blockIdx.y;
    int i = blockIdx.x * 256 + threadIdx.x;
    if (i >= n4) return;
    float4 v = ((const float4*)X.p[z])[i];
    __nv_bfloat16* Xh = XhB + (size_t)z * SZA;
    __nv_bfloat16* Xl = XlB + (size_t)z * SZA;
    float f[4] = {v.x, v.y, v.z, v.w};
    __nv_bfloat16 h[4], l[4];
#pragma unroll
    for (int j = 0; j < 4; j++) {
        h[j] = __float2bfloat16(f[j]);
        l[j] = __float2bfloat16(f[j] - __bfloat162float(h[j]));
    }
    *(__nv_bfloat162*)&Xh[i * 4 + 0] = __nv_bfloat162(h[0], h[1]);
    *(__nv_bfloat162*)&Xh[i * 4 + 2] = __nv_bfloat162(h[2], h[3]);
    *(__nv_bfloat162*)&Xl[i * 4 + 0] = __nv_bfloat162(l[0], l[1]);
    *(__nv_bfloat162*)&Xl[i * 4 + 2] = __nv_bfloat162(l[2], l[3]);
}

__global__ __launch_bounds__(256) void split_wt4_kernel(
    FPtr4 W, __nv_bfloat16* __restrict__ WthB, __nv_bfloat16* __restrict__ WtlB)
{
    __shared__ float t[32][33];
    int z = blockIdx.z;
    int k0 = blockIdx.y * 32, n0 = blockIdx.x * 32;
    int tx = threadIdx.x & 31, ty = threadIdx.x >> 5;
    const float* Wp = W.p[z];
    __nv_bfloat16* Wth = WthB + (size_t)z * D * D;
    __nv_bfloat16* Wtl = WtlB + (size_t)z * D * D;
#pragma unroll
    for (int i = 0; i < 4; i++)
        t[ty + i * 8][tx] = Wp[(size_t)(k0 + ty + i * 8) * D + n0 + tx];
    __syncthreads();
#pragma unroll
    for (int i = 0; i < 4; i++) {
        float v = t[tx][ty + i * 8];
        __nv_bfloat16 h = __float2bfloat16(v);
        __nv_bfloat16 l = __float2bfloat16(v - __bfloat162float(h));
        size_t o = (size_t)(n0 + ty + i * 8) * D + k0 + tx;
        Wth[o] = h;
        Wtl[o] = l;
    }
}

// ---------------- mask compaction: per-batch prefix scan ----------------
__global__ __launch_bounds__(256) void compact_mask_kernel(
    const int* __restrict__ mask, int* __restrict__ gidx, int* __restrict__ cnt)
{
    __shared__ int wsum[8];
    const int b = blockIdx.x;
    const int tid = threadIdx.x, lane = tid & 31, wid = tid >> 5;
    int keep[8], local = 0;
#pragma unroll
    for (int i = 0; i < 8; i++) {
        keep[i] = (mask[b * S + tid * 8 + i] == 0);
        local += keep[i];
    }
    int v = local;
#pragma unroll
    for (int off = 1; off < 32; off <<= 1) {
        int n = __shfl_up_sync(0xffffffffu, v, off);
        if (lane >= off) v += n;
    }
    int excl = v - local;
    if (lane == 31) wsum[wid] = v;
    __syncthreads();
    if (wid == 0 && lane < 8) {
        int w = wsum[lane];
        int wv = w;
#pragma unroll
        for (int off = 1; off < 8; off <<= 1) {
            int n = __shfl_up_sync(0xffu, wv, off);
            if (lane >= off) wv += n;
        }
        wsum[lane] = wv - w;
        if (lane == 7) cnt[b] = wv;
    }
    __syncthreads();
    int base = wsum[wid] + excl;
#pragma unroll
    for (int i = 0; i < 8; i++)
        if (keep[i]) gidx[b * S + base++] = tid * 8 + i;
}

// gather unmasked K/V rows into compact buffers; zero-pad to 64 multiple
__global__ __launch_bounds__(128) void gather_kv_kernel(
    const __nv_bfloat16* __restrict__ Kh, const __nv_bfloat16* __restrict__ Kl,
    const __nv_bfloat16* __restrict__ Vh, const __nv_bfloat16* __restrict__ Vl,
    const int* __restrict__ gidx, const int* __restrict__ cnt,
    __nv_bfloat16* __restrict__ oKh, __nv_bfloat16* __restrict__ oKl,
    __nv_bfloat16* __restrict__ oVh, __nv_bfloat16* __restrict__ oVl)
{
    const int b = blockIdx.y, pos = blockIdx.x, tid = threadIdx.x;
    const int c = cnt[b];
    const int cpad = (c + 63) & ~63;
    if (pos >= cpad) return;
    const size_t dst = (size_t)(b * S + pos) * D + tid * 8;
    if (pos < c) {
        const size_t src = (size_t)(b * S + gidx[b * S + pos]) * D + tid * 8;
        *(uint4*)&oKh[dst] = *(const uint4*)&Kh[src];
        *(uint4*)&oKl[dst] = *(const uint4*)&Kl[src];
        *(uint4*)&oVh[dst] = *(const uint4*)&Vh[src];
        *(uint4*)&oVl[dst] = *(const uint4*)&Vl[src];
    } else {
        uint4 z = make_uint4(0, 0, 0, 0);
        *(uint4*)&oKh[dst] = z;
        *(uint4*)&oKl[dst] = z;
        *(uint4*)&oVh[dst] = z;
        *(uint4*)&oVl[dst] = z;
    }
}

// ---------------- bf16x3 GEMM body ----------------
#define BK 32
#define NCH (GK / BK)
#define OFF_AL 10240
#define OFF_BH 20480
#define OFF_BL 25600
#define STAGE_SB 30720
#define GEMM_SMEM (3 * STAGE_SB)

__device__ __forceinline__ void gemm_body(
    const __nv_bfloat16* __restrict__ Ah, const __nv_bfloat16* __restrict__ Al,
    const __nv_bfloat16* __restrict__ Bh, const __nv_bfloat16* __restrict__ Bl,
    const float* __restrict__ bias, float* __restrict__ C,
    __nv_bfloat16* __restrict__ Ch, __nv_bfloat16* __restrict__ Cl,
    char* smem)
{
    const uint32_t sbase = smem_u32(smem);
    const int tid = threadIdx.x;
    const int lane = tid & 31;
    const int wid = tid >> 5;
    const int warp_m = wid & 3;
    const int warp_n = wid >> 2;
    const int m0 = blockIdx.y * 128;
    const int n0 = blockIdx.x * 64;

    const __nv_bfloat16* gAh = Ah + (size_t)m0 * GK;
    const __nv_bfloat16* gAl = Al + (size_t)m0 * GK;
    const __nv_bfloat16* gBh = Bh + (size_t)n0 * GK;
    const __nv_bfloat16* gBl = Bl + (size_t)n0 * GK;

    const int lrow = tid >> 2;
    const int lc   = tid & 3;

    auto load_stage = [&](int stg, int k0) {
        uint32_t sb = sbase + stg * STAGE_SB;
#pragma unroll
        for (int j = 0; j < 2; j++) {
            int row = lrow + j * 64;
            uint32_t so = row * 80 + lc * 16;
            size_t go = (size_t)row * GK + k0 + lc * 8;
            cpa16(sb + so,          gAh + go);
            cpa16(sb + OFF_AL + so, gAl + go);
        }
        {
            uint32_t so = lrow * 80 + lc * 16;
            size_t go = (size_t)lrow * GK + k0 + lc * 8;
            cpa16(sb + OFF_BH + so, gBh + go);
            cpa16(sb + OFF_BL + so, gBl + go);
        }
        asm volatile("cp.async.commit_group;");
    };

    float acc[2][4][4];
#pragma unroll
    for (int i = 0; i < 2; i++)
#pragma unroll
        for (int j = 0; j < 4; j++)
#pragma unroll
            for (int v = 0; v < 4; v++) acc[i][j][v] = 0.f;

    load_stage(0, 0);
    load_stage(1, BK);

    const int a_row = lane & 15;
    const int a_kc  = lane >> 4;
    const int bg    = lane >> 3;
    const int b_row = ((bg >> 1) * 8) + (lane & 7);
    const int b_kc  = bg & 1;

    int stg = 0;
    for (int ch = 0; ch < NCH; ch++) {
        if (ch < NCH - 1) asm volatile("cp.async.wait_group 1;");
        else              asm volatile("cp.async.wait_group 0;");
        __syncthreads();
        if (ch + 2 < NCH) {
            int ns = stg + 2; if (ns >= 3) ns -= 3;
            load_stage(ns, (ch + 2) * BK);
        }
        const uint32_t st = sbase + stg * STAGE_SB;
#pragma unroll
        for (int kc = 0; kc < 2; kc++) {
            uint32_t a_h[2][4], a_l[2][4], b_h[2][4], b_l[2][4];
#pragma unroll
            for (int mt = 0; mt < 2; mt++) {
                uint32_t ro = (warp_m * 32 + mt * 16 + a_row) * 80
                            + (kc * 2 + a_kc) * 16;
                ldsm_x4(a_h[mt], st + ro);
                ldsm_x4(a_l[mt], st + OFF_AL + ro);
            }
#pragma unroll
            for (int ng = 0; ng < 2; ng++) {
                uint32_t ro = (warp_n * 32 + ng * 16 + b_row) * 80
                            + (kc * 2 + b_kc) * 16;
                ldsm_x4(b_h[ng], st + OFF_BH + ro);
                ldsm_x4(b_l[ng], st + OFF_BL + ro);
            }
#pragma unroll
            for (int mt = 0; mt < 2; mt++)
#pragma unroll
                for (int ng = 0; ng < 2; ng++) {
                    mma_bf16(acc[mt][ng * 2 + 0], a_h[mt], b_h[ng][0], b_h[ng][1]);
                    mma_bf16(acc[mt][ng * 2 + 1], a_h[mt], b_h[ng][2], b_h[ng][3]);
                }
#pragma unroll
            for (int mt = 0; mt < 2; mt++)
#pragma unroll
                for (int ng = 0; ng < 2; ng++) {
                    mma_bf16(acc[mt][ng * 2 + 0], a_h[mt], b_l[ng][0], b_l[ng][1]);
                    mma_bf16(acc[mt][ng * 2 + 1], a_h[mt], b_l[ng][2], b_l[ng][3]);
                }
#pragma unroll
            for (int mt = 0; mt < 2; mt++)
#pragma unroll
                for (int ng = 0; ng < 2; ng++) {
                    mma_bf16(acc[mt][ng * 2 + 0], a_l[mt], b_h[ng][0], b_h[ng][1]);
                    mma_bf16(acc[mt][ng * 2 + 1], a_l[mt], b_h[ng][2], b_h[ng][3]);
                }
        }
        __syncthreads();
        if (++stg == 3) stg = 0;
    }

    const int grp = lane >> 2, tg = lane & 3;
#pragma unroll
    for (int mt = 0; mt < 2; mt++) {
        int r0 = m0 + warp_m * 32 + mt * 16 + grp;
#pragma unroll
        for (int nt = 0; nt < 4; nt++) {
            int c = n0 + warp_n * 32 + nt * 8 + tg * 2;
            float2 b2 = *(const float2*)&bias[c];
            float o00 = acc[mt][nt][0] + b2.x;
            float o01 = acc[mt][nt][1] + b2.y;
            float o10 = acc[mt][nt][2] + b2.x;
            float o11 = acc[mt][nt][3] + b2.y;
            if (C) {
                *(float2*)&C[(size_t)r0 * GN + c] = make_float2(o00, o01);
                *(float2*)&C[(size_t)(r0 + 8) * GN + c] = make_float2(o10, o11);
            } else {
                uint32_t h0, l0, h1, l1;
                split2(o00, o01, h0, l0);
                split2(o10, o11, h1, l1);
                *(uint32_t*)&Ch[(size_t)r0 * GN + c] = h0;
                *(uint32_t*)&Cl[(size_t)r0 * GN + c] = l0;
                *(uint32_t*)&Ch[(size_t)(r0 + 8) * GN + c] = h1;
                *(uint32_t*)&Cl[(size_t)(r0 + 8) * GN + c] = l1;
            }
        }
    }
}

struct QKVBias { const float* p[3]; };

__global__ __launch_bounds__(256, 2) void qkv_gemm_kernel(
    const __nv_bfloat16* __restrict__ AhB, const __nv_bfloat16* __restrict__ AlB,
    const __nv_bfloat16* __restrict__ BhB, const __nv_bfloat16* __restrict__ BlB,
    QKVBias bias,
    __nv_bfloat16* __restrict__ ChB, __nv_bfloat16* __restrict__ ClB)
{
    extern __shared__ char smem[];
    const int z = blockIdx.z;
    gemm_body(AhB + (size_t)z * SZA, AlB + (size_t)z * SZA,
              BhB + (size_t)z * D * D, BlB + (size_t)z * D * D,
              bias.p[z], nullptr,
              ChB + (size_t)z * SZA, ClB + (size_t)z * SZA, smem);
}

__global__ __launch_bounds__(256, 2) void oproj_gemm_kernel(
    const __nv_bfloat16* __restrict__ Ah, const __nv_bfloat16* __restrict__ Al,
    const __nv_bfloat16* __restrict__ Bh, const __nv_bfloat16* __restrict__ Bl,
    const float* __restrict__ bias, float* __restrict__ C)
{
    extern __shared__ char smem[];
    gemm_body(Ah, Al, Bh, Bl, bias, C, nullptr, nullptr, smem);
}

// ---------------- Attention: HMMA bf16x3, compacted keys, 2-stage --------
#define ASTG 36864
#define AT_VH 18432
#define AT_VL 27648
#define ATTN_SMEM (2 * ASTG)   // 73728

__global__ __launch_bounds__(256, 2) void attn_mma_kernel(
    const __nv_bfloat16* __restrict__ Qh, const __nv_bfloat16* __restrict__ Ql,
    const __nv_bfloat16* __restrict__ Kh, const __nv_bfloat16* __restrict__ Kl,
    const __nv_bfloat16* __restrict__ Vh, const __nv_bfloat16* __restrict__ Vl,
    const int* __restrict__ cnt,
    __nv_bfloat16* __restrict__ Ch, __nv_bfloat16* __restrict__ Cl)
{
    extern __shared__ char smem[];
    const uint32_t sb = smem_u32(smem);
    const int tid = threadIdx.x, lane = tid & 31, wid = tid >> 5;
    const int b = blockIdx.z, h = blockIdx.y, q0 = blockIdx.x * 128;
    const int cn = cnt[b];
    const int nch = (cn + 63) >> 6;

    // ---- stage Q tile (hi/lo) into smem once, ldsm to fragments ----
#pragma unroll
    for (int t = 0; t < 8; t++) {
        int idx = tid + t * 256;
        int half = idx >> 10;
        int c = idx & 1023;
        int row = c >> 3, ch = c & 7;
        const __nv_bfloat16* src = (half ? Ql : Qh)
            + (size_t)(b * S + q0 + row) * D + h * DK + ch * 8;
        *(uint4*)(smem + half * 18432 + row * 144 + ch * 16) = *(const uint4*)src;
    }
    __syncthreads();
    uint32_t qfh[4][4], qfl[4][4];
    {
        int r = wid * 16 + (lane & 15);
        int hc = lane >> 4;
#pragma unroll
        for (int c = 0; c < 4; c++) {
            ldsm_x4(qfh[c], sb + r * 144 + (c * 2 + hc) * 16);
            ldsm_x4(qfl[c], sb + 18432 + r * 144 + (c * 2 + hc) * 16);
        }
    }
    __syncthreads();

    auto load_stage = [&](int stg, int kk) {
        uint32_t base = sb + stg * ASTG;
#pragma unroll
        for (int t = 0; t < 8; t++) {
            int idx = tid + t * 256;
            int tile = idx >> 9;
            int c = idx & 511;
            int row = c >> 3, ch = c & 7;
            const __nv_bfloat16* g =
                (tile == 0 ? Kh : tile == 1 ? Kl : tile == 2 ? Vh : Vl)
                + (size_t)(b * S + kk + row) * D + h * DK + ch * 8;
            cpa16(base + tile * 9216 + row * 144 + ch * 16, g);
        }
        asm volatile("cp.async.commit_group;");
    };

    float acc[8][4];
#pragma unroll
    for (int j = 0; j < 8; j++)
#pragma unroll
        for (int v = 0; v < 4; v++) acc[j][v] = 0.f;
    float m0r = -1e30f, m1r = -1e30f, l0r = 0.f, l1r = 0.f;
    const float scale = 0.125f;

    if (nch >= 1) load_stage(0, 0);
    if (nch >= 2) load_stage(1, 64);

    const int bg    = lane >> 3;
    const int b_row = ((bg >> 1) * 8) + (lane & 7);
    const int b_kc  = bg & 1;
    const int tr    = lane & 15;
    const int tc    = lane >> 4;
    const int jlane = (lane & 3) * 2;

    for (int it = 0; it < nch; it++) {
        const int stg = it & 1;
        if (it < nch - 1) asm volatile("cp.async.wait_group 1;");
        else              asm volatile("cp.async.wait_group 0;");
        __syncthreads();

        const uint32_t st = sb + stg * ASTG;

        float s[8][4];
#pragma unroll
        for (int j = 0; j < 8; j++)
#pragma unroll
            for (int v = 0; v < 4; v++) s[j][v] = 0.f;
#pragma unroll
        for (int c = 0; c < 4; c++) {
#pragma unroll
            for (int np = 0; np < 4; np++) {
                uint32_t kbh[4], kbl[4];
                uint32_t ro = (np * 16 + b_row) * 144 + (c * 2 + b_kc) * 16;
                ldsm_x4(kbh, st + ro);
                ldsm_x4(kbl, st + 9216 + ro);
                mma_bf16(s[np * 2 + 0], qfh[c], kbh[0], kbh[1]);
                mma_bf16(s[np * 2 + 1], qfh[c], kbh[2], kbh[3]);
                mma_bf16(s[np * 2 + 0], qfh[c], kbl[0], kbl[1]);
                mma_bf16(s[np * 2 + 1], qfh[c], kbl[2], kbl[3]);
                mma_bf16(s[np * 2 + 0], qfl[c], kbh[0], kbh[1]);
                mma_bf16(s[np * 2 + 1], qfl[c], kbh[2], kbh[3]);
            }
        }

        // online softmax; tail columns (j >= cn) masked by index compare
        const int jbase = it * 64 + jlane;
        float mx0 = -1e30f, mx1 = -1e30f;
#pragma unroll
        for (int nt = 0; nt < 8; nt++) {
            int j0 = jbase + nt * 8;
            bool k0m = (j0 >= cn), k1m = (j0 + 1 >= cn);
            s[nt][0] = k0m ? -1e30f : s[nt][0] * scale;
            s[nt][1] = k1m ? -1e30f : s[nt][1] * scale;
            s[nt][2] = k0m ? -1e30f : s[nt][2] * scale;
            s[nt][3] = k1m ? -1e30f : s[nt][3] * scale;
            mx0 = fmaxf(mx0, fmaxf(s[nt][0], s[nt][1]));
            mx1 = fmaxf(mx1, fmaxf(s[nt][2], s[nt][3]));
        }
#pragma unroll
        for (int off = 1; off < 4; off <<= 1) {
            mx0 = fmaxf(mx0, __shfl_xor_sync(0xffffffffu, mx0, off));
            mx1 = fmaxf(mx1, __shfl_xor_sync(0xffffffffu, mx1, off));
        }
        float mn0 = fmaxf(m0r, mx0), mn1 = fmaxf(m1r, mx1);
        float cr0 = __expf(m0r - mn0), cr1 = __expf(m1r - mn1);
        float sum0 = 0.f, sum1 = 0.f;
#pragma unroll
        for (int nt = 0; nt < 8; nt++) {
            float p0 = (s[nt][0] > -5e29f) ? __expf(s[nt][0] - mn0) : 0.f;
            float p1 = (s[nt][1] > -5e29f) ? __expf(s[nt][1] - mn0) : 0.f;
            float p2 = (s[nt][2] > -5e29f) ? __expf(s[nt][2] - mn1) : 0.f;
            float p3 = (s[nt][3] > -5e29f) ? __expf(s[nt][3] - mn1) : 0.f;
            s[nt][0] = p0; s[nt][1] = p1; s[nt][2] = p2; s[nt][3] = p3;
            sum0 += p0 + p1;
            sum1 += p2 + p3;
        }
#pragma unroll
        for (int off = 1; off < 4; off <<= 1) {
            sum0 += __shfl_xor_sync(0xffffffffu, sum0, off);
            sum1 += __shfl_xor_sync(0xffffffffu, sum1, off);
        }
        l0r = l0r * cr0 + sum0;
        l1r = l1r * cr1 + sum1;
        m0r = mn0; m1r = mn1;
#pragma unroll
        for (int nt = 0; nt < 8; nt++) {
            acc[nt][0] *= cr0; acc[nt][1] *= cr0;
            acc[nt][2] *= cr1; acc[nt][3] *= cr1;
        }

        uint32_t pah[4][4], pal[4][4];
#pragma unroll
        for (int c = 0; c < 4; c++) {
            split2(s[2 * c][0],     s[2 * c][1],     pah[c][0], pal[c][0]);
            split2(s[2 * c][2],     s[2 * c][3],     pah[c][1], pal[c][1]);
            split2(s[2 * c + 1][0], s[2 * c + 1][1], pah[c][2], pal[c][2]);
            split2(s[2 * c + 1][2], s[2 * c + 1][3], pah[c][3], pal[c][3]);
        }

#pragma unroll
        for (int c = 0; c < 4; c++) {
#pragma unroll
            for (int np = 0; np < 4; np++) {
                uint32_t vbh[4], vbl[4];
                uint32_t ro = (c * 16 + tr) * 144 + np * 32 + tc * 16;
                ldsm_x4_t(vbh, st + AT_VH + ro);
                ldsm_x4_t(vbl, st + AT_VL + ro);
                mma_bf16(acc[np * 2 + 0], pah[c], vbh[0], vbh[1]);
                mma_bf16(acc[np * 2 + 1], pah[c], vbh[2], vbh[3]);
                mma_bf16(acc[np * 2 + 0], pah[c], vbl[0], vbl[1]);
                mma_bf16(acc[np * 2 + 1], pah[c], vbl[2], vbl[3]);
                mma_bf16(acc[np * 2 + 0], pal[c], vbh[0], vbh[1]);
                mma_bf16(acc[np * 2 + 1], pal[c], vbh[2], vbh[3]);
            }
        }
        __syncthreads();
        if (it + 2 < nch) load_stage(stg, (it + 2) * 64);
    }

    // ---- epilogue: write context as bf16 hi/lo directly ----
    float inv0 = (l0r > 0.f) ? (1.f / l0r) : 0.f;
    float inv1 = (l1r > 0.f) ? (1.f / l1r) : 0.f;
    int r0 = q0 + wid * 16 + (lane >> 2);
#pragma unroll
    for (int nt = 0; nt < 8; nt++) {
        int c = h * DK + nt * 8 + (lane & 3) * 2;
        uint32_t h0, l0, h1, l1;
        split2(acc[nt][0] * inv0, acc[nt][1] * inv0, h0, l0);
        split2(acc[nt][2] * inv1, acc[nt][3] * inv1, h1, l1);
        size_t o0 = (size_t)(b * S + r0) * D + c;
        size_t o1 = (size_t)(b * S + r0 + 8) * D + c;
        *(uint32_t*)&Ch[o0] = h0;
        *(uint32_t*)&Cl[o0] = l0;
        *(uint32_t*)&Ch[o1] = h1;
        *(uint32_t*)&Cl[o1] = l1;
    }
}

// ---------------- launch ----------------
extern "C" void kernel_launch(void* const* d_in, const int* in_sizes, int n_in,
                              void* d_out, int out_size)
{
    const float* query = (const float*)d_in[0];
    const float* key   = (const float*)d_in[1];
    const float* value = (const float*)d_in[2];
    const int*   mask  = (const int*)d_in[3];
    const float* Wq = (const float*)d_in[4];
    const float* bq = (const float*)d_in[5];
    const float* Wk = (const float*)d_in[6];
    const float* bk = (const float*)d_in[7];
    const float* Wv = (const float*)d_in[8];
    const float* bv = (const float*)d_in[9];
    const float* Wo = (const float*)d_in[10];
    const float* bo = (const float*)d_in[11];
    float* out = (float*)d_out;

    __nv_bfloat16 *ah, *al, *bh, *bl;
    int *gidx, *cnt;
    cudaGetSymbolAddress((void**)&ah, g_Ah);
    cudaGetSymbolAddress((void**)&al, g_Al);
    cudaGetSymbolAddress((void**)&bh, g_Bh);
    cudaGetSymbolAddress((void**)&bl, g_Bl);
    cudaGetSymbolAddress((void**)&gidx, g_gidx);
    cudaGetSymbolAddress((void**)&cnt, g_cnt);

    static int attr_set = 0;
    if (!attr_set) {
        cudaFuncSetAttribute(qkv_gemm_kernel,
                             cudaFuncAttributeMaxDynamicSharedMemorySize, GEMM_SMEM);
        cudaFuncSetAttribute(oproj_gemm_kernel,
                             cudaFuncAttributeMaxDynamicSharedMemorySize, GEMM_SMEM);
        cudaFuncSetAttribute(attn_mma_kernel,
                             cudaFuncAttributeMaxDynamicSharedMemorySize, ATTN_SMEM);
        attr_set = 1;
    }

    const int n4_act = SZA / 4;

    FPtr3 xin; xin.p[0] = query; xin.p[1] = key; xin.p[2] = value;
    dim3 sa_grid((n4_act + 255) / 256, 3);
    split_act3_kernel<<<sa_grid, 256>>>(xin, ah, al, n4_act);

    FPtr4 win; win.p[0] = Wq; win.p[1] = Wk; win.p[2] = Wv; win.p[3] = Wo;
    dim3 sw_grid(D / 32, D / 32, 4);
    split_wt4_kernel<<<sw_grid, 256>>>(win, bh, bl);

    // mask compaction (overlaps with splits/GEMM on the same stream order)
    compact_mask_kernel<<<B, 256>>>(mask, gidx, cnt);

    QKVBias qb; qb.p[0] = bq; qb.p[1] = bk; qb.p[2] = bv;
    dim3 qkv_grid(GN / 64, M_ROWS / 128, 3);
    qkv_gemm_kernel<<<qkv_grid, 256, GEMM_SMEM>>>(
        ah, al, bh, bl, qb, ah + (size_t)3 * SZA, al + (size_t)3 * SZA);

    // gather unmasked K/V rows into compact buffers (slots 7, 8)
    dim3 g_grid(S, B);
    gather_kv_kernel<<<g_grid, 128>>>(
        ah + (size_t)4 * SZA, al + (size_t)4 * SZA,
        ah + (size_t)5 * SZA, al + (size_t)5 * SZA,
        gidx, cnt,
        ah + (size_t)7 * SZA, al + (size_t)7 * SZA,
        ah + (size_t)8 * SZA, al + (size_t)8 * SZA);

    dim3 attn_grid(S / 128, H, B);
    attn_mma_kernel<<<attn_grid, 256, ATTN_SMEM>>>(
        ah + (size_t)3 * SZA, al + (size_t)3 * SZA,
        ah + (size_t)7 * SZA, al + (size_t)7 * SZA,
        ah + (size_t)8 * SZA, al + (size_t)8 * SZA,
        cnt,
        ah + (size_t)6 * SZA, al + (size_t)6 * SZA);

    dim3 gemm_grid(GN / 64, M_ROWS / 128);
    oproj_gemm_kernel<<<gemm_grid, 256, GEMM_SMEM>>>(
        ah + (size_t)6 * SZA, al + (size_t)6 * SZA,
        bh + (size_t)3 * D * D, bl + (size_t)3 * D * D, bo, out);
}

// round 11
// speedup vs baseline: 4.7486x; 1.2075x over previous
#include <cuda_runtime.h>
#include <cuda_bf16.h>
#include <math.h>
#include <stdint.h>

// Problem constants
#define B  2
#define S  2048
#define D  1024
#define H  16
#define DK 64
#define M_ROWS (B * S)   // 4096
#define GK 1024
#define GN 1024
#define SZA (M_ROWS * D)

// ---------------- scratch (device globals: allocation-free) ----------------
// slots: 0 = split q input; 1,2 = gathered compact k,v inputs;
//        3..5 = projected q, k(compact), v(compact); 6 = ctx
__device__ __nv_bfloat16 g_Ah[7][SZA];
__device__ __nv_bfloat16 g_Al[7][SZA];
__device__ __nv_bfloat16 g_Bh[4][D * D];
__device__ __nv_bfloat16 g_Bl[4][D * D];
__device__ int g_gidx[B * S];
__device__ int g_cnt[B];

struct FPtr4 { const float* p[4]; };

__device__ __forceinline__ uint32_t smem_u32(const void* p) {
    uint32_t a;
    asm("{ .reg .u64 t; cvta.to.shared.u64 t, %1; cvt.u32.u64 %0, t; }"
        : "=r"(a) : "l"(p));
    return a;
}
__device__ __forceinline__ void ldsm_x4(uint32_t (&r)[4], uint32_t addr) {
    asm volatile("ldmatrix.sync.aligned.m8n8.x4.shared.b16 {%0,%1,%2,%3}, [%4];"
                 : "=r"(r[0]), "=r"(r[1]), "=r"(r[2]), "=r"(r[3]) : "r"(addr));
}
__device__ __forceinline__ void ldsm_x4_t(uint32_t (&r)[4], uint32_t addr) {
    asm volatile("ldmatrix.sync.aligned.m8n8.x4.trans.shared.b16 {%0,%1,%2,%3}, [%4];"
                 : "=r"(r[0]), "=r"(r[1]), "=r"(r[2]), "=r"(r[3]) : "r"(addr));
}
__device__ __forceinline__ void mma_bf16(float (&d)[4],
    const uint32_t (&a)[4], uint32_t b0, uint32_t b1)
{
    asm volatile(
        "mma.sync.aligned.m16n8k16.row.col.f32.bf16.bf16.f32 "
        "{%0,%1,%2,%3}, {%4,%5,%6,%7}, {%8,%9}, {%0,%1,%2,%3};"
        : "+f"(d[0]), "+f"(d[1]), "+f"(d[2]), "+f"(d[3])
        : "r"(a[0]), "r"(a[1]), "r"(a[2]), "r"(a[3]), "r"(b0), "r"(b1));
}
__device__ __forceinline__ void cpa16(uint32_t sd, const void* gs) {
    asm volatile("cp.async.cg.shared.global [%0], [%1], 16;" :: "r"(sd), "l"(gs));
}
__device__ __forceinline__ void split2(float f0, float f1, uint32_t& hi, uint32_t& lo) {
    __nv_bfloat16 h0 = __float2bfloat16(f0), h1 = __float2bfloat16(f1);
    __nv_bfloat16 l0 = __float2bfloat16(f0 - __bfloat162float(h0));
    __nv_bfloat16 l1 = __float2bfloat16(f1 - __bfloat162float(h1));
    hi = (uint32_t)*(uint16_t*)&h0 | ((uint32_t)*(uint16_t*)&h1 << 16);
    lo = (uint32_t)*(uint16_t*)&l0 | ((uint32_t)*(uint16_t*)&l1 << 16);
}

// ---------------- mask compaction: per-batch prefix scan ----------------
__global__ __launch_bounds__(256) void compact_mask_kernel(
    const int* __restrict__ mask, int* __restrict__ gidx, int* __restrict__ cnt)
{
    __shared__ int wsum[8];
    const int b = blockIdx.x;
    const int tid = threadIdx.x, lane = tid & 31, wid = tid >> 5;
    int keep[8], local = 0;
#pragma unroll
    for (int i = 0; i < 8; i++) {
        keep[i] = (mask[b * S + tid * 8 + i] == 0);
        local += keep[i];
    }
    int v = local;
#pragma unroll
    for (int off = 1; off < 32; off <<= 1) {
        int n = __shfl_up_sync(0xffffffffu, v, off);
        if (lane >= off) v += n;
    }
    int excl = v - local;
    if (lane == 31) wsum[wid] = v;
    __syncthreads();
    if (wid == 0 && lane < 8) {
        int w = wsum[lane];
        int wv = w;
#pragma unroll
        for (int off = 1; off < 8; off <<= 1) {
            int n = __shfl_up_sync(0xffu, wv, off);
            if (lane >= off) wv += n;
        }
        wsum[lane] = wv - w;
        if (lane == 7) cnt[b] = wv;
    }
    __syncthreads();
    int base = wsum[wid] + excl;
#pragma unroll
    for (int i = 0; i < 8; i++)
        if (keep[i]) gidx[b * S + base++] = tid * 8 + i;
}

// ---------------- split q input (fp32 -> bf16 hi/lo) ----------------
__global__ __launch_bounds__(256) void split_q_kernel(
    const float* __restrict__ X, __nv_bfloat16* __restrict__ Xh,
    __nv_bfloat16* __restrict__ Xl, int n4)
{
    int i = blockIdx.x * 256 + threadIdx.x;
    if (i >= n4) return;
    float4 v = ((const float4*)X)[i];
    float f[4] = {v.x, v.y, v.z, v.w};
    __nv_bfloat16 h[4], l[4];
#pragma unroll
    for (int j = 0; j < 4; j++) {
        h[j] = __float2bfloat16(f[j]);
        l[j] = __float2bfloat16(f[j] - __bfloat162float(h[j]));
    }
    *(__nv_bfloat162*)&Xh[i * 4 + 0] = __nv_bfloat162(h[0], h[1]);
    *(__nv_bfloat162*)&Xh[i * 4 + 2] = __nv_bfloat162(h[2], h[3]);
    *(__nv_bfloat162*)&Xl[i * 4 + 0] = __nv_bfloat162(l[0], l[1]);
    *(__nv_bfloat162*)&Xl[i * 4 + 2] = __nv_bfloat162(l[2], l[3]);
}

// gather unmasked input rows of key/value + split to bf16 hi/lo; zero-pad
// grid (S, B), 128 threads (8 elems each)
__global__ __launch_bounds__(128) void gather_split_kv_kernel(
    const float* __restrict__ keyIn, const float* __restrict__ valIn,
    const int* __restrict__ gidx, const int* __restrict__ cnt,
    __nv_bfloat16* __restrict__ Kh, __nv_bfloat16* __restrict__ Kl,
    __nv_bfloat16* __restrict__ Vh, __nv_bfloat16* __restrict__ Vl)
{
    const int b = blockIdx.y, pos = blockIdx.x, tid = threadIdx.x;
    const int c = cnt[b];
    const int cpad = (c + 63) & ~63;
    if (pos >= cpad) return;
    const size_t dst = (size_t)(b * S + pos) * D + tid * 8;
    if (pos < c) {
        const size_t src = (size_t)(b * S + gidx[b * S + pos]) * D + tid * 8;
#pragma unroll
        for (int t = 0; t < 2; t++) {
            const float* in = t ? valIn : keyIn;
            __nv_bfloat16* oh = t ? Vh : Kh;
            __nv_bfloat16* ol = t ? Vl : Kl;
            float4 v0 = *(const float4*)&in[src];
            float4 v1 = *(const float4*)&in[src + 4];
            uint32_t h0, l0, h1, l1, h2, l2, h3, l3;
            split2(v0.x, v0.y, h0, l0);
            split2(v0.z, v0.w, h1, l1);
            split2(v1.x, v1.y, h2, l2);
            split2(v1.z, v1.w, h3, l3);
            *(uint4*)&oh[dst] = make_uint4(h0, h1, h2, h3);
            *(uint4*)&ol[dst] = make_uint4(l0, l1, l2, l3);
        }
    } else {
        uint4 z = make_uint4(0, 0, 0, 0);
        *(uint4*)&Kh[dst] = z;
        *(uint4*)&Kl[dst] = z;
        *(uint4*)&Vh[dst] = z;
        *(uint4*)&Vl[dst] = z;
    }
}

__global__ __launch_bounds__(256) void split_wt4_kernel(
    FPtr4 W, __nv_bfloat16* __restrict__ WthB, __nv_bfloat16* __restrict__ WtlB)
{
    __shared__ float t[32][33];
    int z = blockIdx.z;
    int k0 = blockIdx.y * 32, n0 = blockIdx.x * 32;
    int tx = threadIdx.x & 31, ty = threadIdx.x >> 5;
    const float* Wp = W.p[z];
    __nv_bfloat16* Wth = WthB + (size_t)z * D * D;
    __nv_bfloat16* Wtl = WtlB + (size_t)z * D * D;
#pragma unroll
    for (int i = 0; i < 4; i++)
        t[ty + i * 8][tx] = Wp[(size_t)(k0 + ty + i * 8) * D + n0 + tx];
    __syncthreads();
#pragma unroll
    for (int i = 0; i < 4; i++) {
        float v = t[tx][ty + i * 8];
        __nv_bfloat16 h = __float2bfloat16(v);
        __nv_bfloat16 l = __float2bfloat16(v - __bfloat162float(h));
        size_t o = (size_t)(n0 + ty + i * 8) * D + k0 + tx;
        Wth[o] = h;
        Wtl[o] = l;
    }
}

// ---------------- bf16x3 GEMM body ----------------
#define BK 32
#define NCH (GK / BK)
#define OFF_AL 10240
#define OFF_BH 20480
#define OFF_BL 25600
#define STAGE_SB 30720
#define GEMM_SMEM (3 * STAGE_SB)

__device__ __forceinline__ void gemm_body(
    const __nv_bfloat16* __restrict__ Ah, const __nv_bfloat16* __restrict__ Al,
    const __nv_bfloat16* __restrict__ Bh, const __nv_bfloat16* __restrict__ Bl,
    const float* __restrict__ bias, float* __restrict__ C,
    __nv_bfloat16* __restrict__ Ch, __nv_bfloat16* __restrict__ Cl,
    char* smem)
{
    const uint32_t sbase = smem_u32(smem);
    const int tid = threadIdx.x;
    const int lane = tid & 31;
    const int wid = tid >> 5;
    const int warp_m = wid & 3;
    const int warp_n = wid >> 2;
    const int m0 = blockIdx.y * 128;
    const int n0 = blockIdx.x * 64;

    const __nv_bfloat16* gAh = Ah + (size_t)m0 * GK;
    const __nv_bfloat16* gAl = Al + (size_t)m0 * GK;
    const __nv_bfloat16* gBh = Bh + (size_t)n0 * GK;
    const __nv_bfloat16* gBl = Bl + (size_t)n0 * GK;

    const int lrow = tid >> 2;
    const int lc   = tid & 3;

    auto load_stage = [&](int stg, int k0) {
        uint32_t sb = sbase + stg * STAGE_SB;
#pragma unroll
        for (int j = 0; j < 2; j++) {
            int row = lrow + j * 64;
            uint32_t so = row * 80 + lc * 16;
            size_t go = (size_t)row * GK + k0 + lc * 8;
            cpa16(sb + so,          gAh + go);
            cpa16(sb + OFF_AL + so, gAl + go);
        }
        {
            uint32_t so = lrow * 80 + lc * 16;
            size_t go = (size_t)lrow * GK + k0 + lc * 8;
            cpa16(sb + OFF_BH + so, gBh + go);
            cpa16(sb + OFF_BL + so, gBl + go);
        }
        asm volatile("cp.async.commit_group;");
    };

    float acc[2][4][4];
#pragma unroll
    for (int i = 0; i < 2; i++)
#pragma unroll
        for (int j = 0; j < 4; j++)
#pragma unroll
            for (int v = 0; v < 4; v++) acc[i][j][v] = 0.f;

    load_stage(0, 0);
    load_stage(1, BK);

    const int a_row = lane & 15;
    const int a_kc  = lane >> 4;
    const int bg    = lane >> 3;
    const int b_row = ((bg >> 1) * 8) + (lane & 7);
    const int b_kc  = bg & 1;

    int stg = 0;
    for (int ch = 0; ch < NCH; ch++) {
        if (ch < NCH - 1) asm volatile("cp.async.wait_group 1;");
        else              asm volatile("cp.async.wait_group 0;");
        __syncthreads();
        if (ch + 2 < NCH) {
            int ns = stg + 2; if (ns >= 3) ns -= 3;
            load_stage(ns, (ch + 2) * BK);
        }
        const uint32_t st = sbase + stg * STAGE_SB;
#pragma unroll
        for (int kc = 0; kc < 2; kc++) {
            uint32_t a_h[2][4], a_l[2][4], b_h[2][4], b_l[2][4];
#pragma unroll
            for (int mt = 0; mt < 2; mt++) {
                uint32_t ro = (warp_m * 32 + mt * 16 + a_row) * 80
                            + (kc * 2 + a_kc) * 16;
                ldsm_x4(a_h[mt], st + ro);
                ldsm_x4(a_l[mt], st + OFF_AL + ro);
            }
#pragma unroll
            for (int ng = 0; ng < 2; ng++) {
                uint32_t ro = (warp_n * 32 + ng * 16 + b_row) * 80
                            + (kc * 2 + b_kc) * 16;
                ldsm_x4(b_h[ng], st + OFF_BH + ro);
                ldsm_x4(b_l[ng], st + OFF_BL + ro);
            }
#pragma unroll
            for (int mt = 0; mt < 2; mt++)
#pragma unroll
                for (int ng = 0; ng < 2; ng++) {
                    mma_bf16(acc[mt][ng * 2 + 0], a_h[mt], b_h[ng][0], b_h[ng][1]);
                    mma_bf16(acc[mt][ng * 2 + 1], a_h[mt], b_h[ng][2], b_h[ng][3]);
                }
#pragma unroll
            for (int mt = 0; mt < 2; mt++)
#pragma unroll
                for (int ng = 0; ng < 2; ng++) {
                    mma_bf16(acc[mt][ng * 2 + 0], a_h[mt], b_l[ng][0], b_l[ng][1]);
                    mma_bf16(acc[mt][ng * 2 + 1], a_h[mt], b_l[ng][2], b_l[ng][3]);
                }
#pragma unroll
            for (int mt = 0; mt < 2; mt++)
#pragma unroll
                for (int ng = 0; ng < 2; ng++) {
                    mma_bf16(acc[mt][ng * 2 + 0], a_l[mt], b_h[ng][0], b_h[ng][1]);
                    mma_bf16(acc[mt][ng * 2 + 1], a_l[mt], b_h[ng][2], b_h[ng][3]);
                }
        }
        __syncthreads();
        if (++stg == 3) stg = 0;
    }

    const int grp = lane >> 2, tg = lane & 3;
#pragma unroll
    for (int mt = 0; mt < 2; mt++) {
        int r0 = m0 + warp_m * 32 + mt * 16 + grp;
#pragma unroll
        for (int nt = 0; nt < 4; nt++) {
            int c = n0 + warp_n * 32 + nt * 8 + tg * 2;
            float2 b2 = *(const float2*)&bias[c];
            float o00 = acc[mt][nt][0] + b2.x;
            float o01 = acc[mt][nt][1] + b2.y;
            float o10 = acc[mt][nt][2] + b2.x;
            float o11 = acc[mt][nt][3] + b2.y;
            if (C) {
                *(float2*)&C[(size_t)r0 * GN + c] = make_float2(o00, o01);
                *(float2*)&C[(size_t)(r0 + 8) * GN + c] = make_float2(o10, o11);
            } else {
                uint32_t h0, l0, h1, l1;
                split2(o00, o01, h0, l0);
                split2(o10, o11, h1, l1);
                *(uint32_t*)&Ch[(size_t)r0 * GN + c] = h0;
                *(uint32_t*)&Cl[(size_t)r0 * GN + c] = l0;
                *(uint32_t*)&Ch[(size_t)(r0 + 8) * GN + c] = h1;
                *(uint32_t*)&Cl[(size_t)(r0 + 8) * GN + c] = l1;
            }
        }
    }
}

struct QKVBias { const float* p[3]; };

// batched Q/K/V projection; K/V (z=1,2) blocks beyond compact count exit early
__global__ __launch_bounds__(256, 2) void qkv_gemm_kernel(
    const __nv_bfloat16* __restrict__ AhB, const __nv_bfloat16* __restrict__ AlB,
    const __nv_bfloat16* __restrict__ BhB, const __nv_bfloat16* __restrict__ BlB,
    QKVBias bias, const int* __restrict__ cnt,
    __nv_bfloat16* __restrict__ ChB, __nv_bfloat16* __restrict__ ClB)
{
    extern __shared__ char smem[];
    const int z = blockIdx.z;
    if (z > 0) {
        const int m0 = blockIdx.y * 128;
        const int b = m0 / S;
        const int cpad = (cnt[b] + 63) & ~63;
        if ((m0 % S) >= cpad) return;   // whole block beyond compact rows
    }
    gemm_body(AhB + (size_t)z * SZA, AlB + (size_t)z * SZA,
              BhB + (size_t)z * D * D, BlB + (size_t)z * D * D,
              bias.p[z], nullptr,
              ChB + (size_t)z * SZA, ClB + (size_t)z * SZA, smem);
}

__global__ __launch_bounds__(256, 2) void oproj_gemm_kernel(
    const __nv_bfloat16* __restrict__ Ah, const __nv_bfloat16* __restrict__ Al,
    const __nv_bfloat16* __restrict__ Bh, const __nv_bfloat16* __restrict__ Bl,
    const float* __restrict__ bias, float* __restrict__ C)
{
    extern __shared__ char smem[];
    gemm_body(Ah, Al, Bh, Bl, bias, C, nullptr, nullptr, smem);
}

// ---------------- Attention: HMMA bf16x3, compacted keys, 2-stage --------
#define ASTG 36864
#define AT_VH 18432
#define AT_VL 27648
#define ATTN_SMEM (2 * ASTG)   // 73728

__global__ __launch_bounds__(256, 2) void attn_mma_kernel(
    const __nv_bfloat16* __restrict__ Qh, const __nv_bfloat16* __restrict__ Ql,
    const __nv_bfloat16* __restrict__ Kh, const __nv_bfloat16* __restrict__ Kl,
    const __nv_bfloat16* __restrict__ Vh, const __nv_bfloat16* __restrict__ Vl,
    const int* __restrict__ cnt,
    __nv_bfloat16* __restrict__ Ch, __nv_bfloat16* __restrict__ Cl)
{
    extern __shared__ char smem[];
    const uint32_t sb = smem_u32(smem);
    const int tid = threadIdx.x, lane = tid & 31, wid = tid >> 5;
    const int b = blockIdx.z, h = blockIdx.y, q0 = blockIdx.x * 128;
    const int cn = cnt[b];
    const int nch = (cn + 63) >> 6;

    // ---- stage Q tile (hi/lo) into smem once, ldsm to fragments ----
#pragma unroll
    for (int t = 0; t < 8; t++) {
        int idx = tid + t * 256;
        int half = idx >> 10;
        int c = idx & 1023;
        int row = c >> 3, ch = c & 7;
        const __nv_bfloat16* src = (half ? Ql : Qh)
            + (size_t)(b * S + q0 + row) * D + h * DK + ch * 8;
        *(uint4*)(smem + half * 18432 + row * 144 + ch * 16) = *(const uint4*)src;
    }
    __syncthreads();
    uint32_t qfh[4][4], qfl[4][4];
    {
        int r = wid * 16 + (lane & 15);
        int hc = lane >> 4;
#pragma unroll
        for (int c = 0; c < 4; c++) {
            ldsm_x4(qfh[c], sb + r * 144 + (c * 2 + hc) * 16);
            ldsm_x4(qfl[c], sb + 18432 + r * 144 + (c * 2 + hc) * 16);
        }
    }
    __syncthreads();

    auto load_stage = [&](int stg, int kk) {
        uint32_t base = sb + stg * ASTG;
#pragma unroll
        for (int t = 0; t < 8; t++) {
            int idx = tid + t * 256;
            int tile = idx >> 9;
            int c = idx & 511;
            int row = c >> 3, ch = c & 7;
            const __nv_bfloat16* g =
                (tile == 0 ? Kh : tile == 1 ? Kl : tile == 2 ? Vh : Vl)
                + (size_t)(b * S + kk + row) * D + h * DK + ch * 8;
            cpa16(base + tile * 9216 + row * 144 + ch * 16, g);
        }
        asm volatile("cp.async.commit_group;");
    };

    float acc[8][4];
#pragma unroll
    for (int j = 0; j < 8; j++)
#pragma unroll
        for (int v = 0; v < 4; v++) acc[j][v] = 0.f;
    float m0r = -1e30f, m1r = -1e30f, l0r = 0.f, l1r = 0.f;
    const float scale = 0.125f;

    if (nch >= 1) load_stage(0, 0);
    if (nch >= 2) load_stage(1, 64);

    const int bg    = lane >> 3;
    const int b_row = ((bg >> 1) * 8) + (lane & 7);
    const int b_kc  = bg & 1;
    const int tr    = lane & 15;
    const int tc    = lane >> 4;
    const int jlane = (lane & 3) * 2;

    for (int it = 0; it < nch; it++) {
        const int stg = it & 1;
        if (it < nch - 1) asm volatile("cp.async.wait_group 1;");
        else              asm volatile("cp.async.wait_group 0;");
        __syncthreads();

        const uint32_t st = sb + stg * ASTG;

        float s[8][4];
#pragma unroll
        for (int j = 0; j < 8; j++)
#pragma unroll
            for (int v = 0; v < 4; v++) s[j][v] = 0.f;
#pragma unroll
        for (int c = 0; c < 4; c++) {
#pragma unroll
            for (int np = 0; np < 4; np++) {
                uint32_t kbh[4], kbl[4];
                uint32_t ro = (np * 16 + b_row) * 144 + (c * 2 + b_kc) * 16;
                ldsm_x4(kbh, st + ro);
                ldsm_x4(kbl, st + 9216 + ro);
                mma_bf16(s[np * 2 + 0], qfh[c], kbh[0], kbh[1]);
                mma_bf16(s[np * 2 + 1], qfh[c], kbh[2], kbh[3]);
                mma_bf16(s[np * 2 + 0], qfh[c], kbl[0], kbl[1]);
                mma_bf16(s[np * 2 + 1], qfh[c], kbl[2], kbl[3]);
                mma_bf16(s[np * 2 + 0], qfl[c], kbh[0], kbh[1]);
                mma_bf16(s[np * 2 + 1], qfl[c], kbh[2], kbh[3]);
            }
        }

        // online softmax; tail columns (j >= cn) masked by index compare
        const int jbase = it * 64 + jlane;
        float mx0 = -1e30f, mx1 = -1e30f;
#pragma unroll
        for (int nt = 0; nt < 8; nt++) {
            int j0 = jbase + nt * 8;
            bool k0m = (j0 >= cn), k1m = (j0 + 1 >= cn);
            s[nt][0] = k0m ? -1e30f : s[nt][0] * scale;
            s[nt][1] = k1m ? -1e30f : s[nt][1] * scale;
            s[nt][2] = k0m ? -1e30f : s[nt][2] * scale;
            s[nt][3] = k1m ? -1e30f : s[nt][3] * scale;
            mx0 = fmaxf(mx0, fmaxf(s[nt][0], s[nt][1]));
            mx1 = fmaxf(mx1, fmaxf(s[nt][2], s[nt][3]));
        }
#pragma unroll
        for (int off = 1; off < 4; off <<= 1) {
            mx0 = fmaxf(mx0, __shfl_xor_sync(0xffffffffu, mx0, off));
            mx1 = fmaxf(mx1, __shfl_xor_sync(0xffffffffu, mx1, off));
        }
        float mn0 = fmaxf(m0r, mx0), mn1 = fmaxf(m1r, mx1);
        float cr0 = __expf(m0r - mn0), cr1 = __expf(m1r - mn1);
        float sum0 = 0.f, sum1 = 0.f;
#pragma unroll
        for (int nt = 0; nt < 8; nt++) {
            float p0 = (s[nt][0] > -5e29f) ? __expf(s[nt][0] - mn0) : 0.f;
            float p1 = (s[nt][1] > -5e29f) ? __expf(s[nt][1] - mn0) : 0.f;
            float p2 = (s[nt][2] > -5e29f) ? __expf(s[nt][2] - mn1) : 0.f;
            float p3 = (s[nt][3] > -5e29f) ? __expf(s[nt][3] - mn1) : 0.f;
            s[nt][0] = p0; s[nt][1] = p1; s[nt][2] = p2; s[nt][3] = p3;
            sum0 += p0 + p1;
            sum1 += p2 + p3;
        }
#pragma unroll
        for (int off = 1; off < 4; off <<= 1) {
            sum0 += __shfl_xor_sync(0xffffffffu, sum0, off);
            sum1 += __shfl_xor_sync(0xffffffffu, sum1, off);
        }
        l0r = l0r * cr0 + sum0;
        l1r = l1r * cr1 + sum1;
        m0r = mn0; m1r = mn1;
#pragma unroll
        for (int nt = 0; nt < 8; nt++) {
            acc[nt][0] *= cr0; acc[nt][1] *= cr0;
            acc[nt][2] *= cr1; acc[nt][3] *= cr1;
        }

        uint32_t pah[4][4], pal[4][4];
#pragma unroll
        for (int c = 0; c < 4; c++) {
            split2(s[2 * c][0],     s[2 * c][1],     pah[c][0], pal[c][0]);
            split2(s[2 * c][2],     s[2 * c][3],     pah[c][1], pal[c][1]);
            split2(s[2 * c + 1][0], s[2 * c + 1][1], pah[c][2], pal[c][2]);
            split2(s[2 * c + 1][2], s[2 * c + 1][3], pah[c][3], pal[c][3]);
        }

#pragma unroll
        for (int c = 0; c < 4; c++) {
#pragma unroll
            for (int np = 0; np < 4; np++) {
                uint32_t vbh[4], vbl[4];
                uint32_t ro = (c * 16 + tr) * 144 + np * 32 + tc * 16;
                ldsm_x4_t(vbh, st + AT_VH + ro);
                ldsm_x4_t(vbl, st + AT_VL + ro);
                mma_bf16(acc[np * 2 + 0], pah[c], vbh[0], vbh[1]);
                mma_bf16(acc[np * 2 + 1], pah[c], vbh[2], vbh[3]);
                mma_bf16(acc[np * 2 + 0], pah[c], vbl[0], vbl[1]);
                mma_bf16(acc[np * 2 + 1], pah[c], vbl[2], vbl[3]);
                mma_bf16(acc[np * 2 + 0], pal[c], vbh[0], vbh[1]);
                mma_bf16(acc[np * 2 + 1], pal[c], vbh[2], vbh[3]);
            }
        }
        __syncthreads();
        if (it + 2 < nch) load_stage(stg, (it + 2) * 64);
    }

    // ---- epilogue: write context as bf16 hi/lo directly ----
    float inv0 = (l0r > 0.f) ? (1.f / l0r) : 0.f;
    float inv1 = (l1r > 0.f) ? (1.f / l1r) : 0.f;
    int r0 = q0 + wid * 16 + (lane >> 2);
#pragma unroll
    for (int nt = 0; nt < 8; nt++) {
        int c = h * DK + nt * 8 + (lane & 3) * 2;
        uint32_t h0, l0, h1, l1;
        split2(acc[nt][0] * inv0, acc[nt][1] * inv0, h0, l0);
        split2(acc[nt][2] * inv1, acc[nt][3] * inv1, h1, l1);
        size_t o0 = (size_t)(b * S + r0) * D + c;
        size_t o1 = (size_t)(b * S + r0 + 8) * D + c;
        *(uint32_t*)&Ch[o0] = h0;
        *(uint32_t*)&Cl[o0] = l0;
        *(uint32_t*)&Ch[o1] = h1;
        *(uint32_t*)&Cl[o1] = l1;
    }
}

// ---------------- launch ----------------
extern "C" void kernel_launch(void* const* d_in, const int* in_sizes, int n_in,
                              void* d_out, int out_size)
{
    const float* query = (const float*)d_in[0];
    const float* key   = (const float*)d_in[1];
    const float* value = (const float*)d_in[2];
    const int*   mask  = (const int*)d_in[3];
    const float* Wq = (const float*)d_in[4];
    const float* bq = (const float*)d_in[5];
    const float* Wk = (const float*)d_in[6];
    const float* bk = (const float*)d_in[7];
    const float* Wv = (const float*)d_in[8];
    const float* bv = (const float*)d_in[9];
    const float* Wo = (const float*)d_in[10];
    const float* bo = (const float*)d_in[11];
    float* out = (float*)d_out;

    __nv_bfloat16 *ah, *al, *bh, *bl;
    int *gidx, *cnt;
    cudaGetSymbolAddress((void**)&ah, g_Ah);
    cudaGetSymbolAddress((void**)&al, g_Al);
    cudaGetSymbolAddress((void**)&bh, g_Bh);
    cudaGetSymbolAddress((void**)&bl, g_Bl);
    cudaGetSymbolAddress((void**)&gidx, g_gidx);
    cudaGetSymbolAddress((void**)&cnt, g_cnt);

    static int attr_set = 0;
    if (!attr_set) {
        cudaFuncSetAttribute(qkv_gemm_kernel,
                             cudaFuncAttributeMaxDynamicSharedMemorySize, GEMM_SMEM);
        cudaFuncSetAttribute(oproj_gemm_kernel,
                             cudaFuncAttributeMaxDynamicSharedMemorySize, GEMM_SMEM);
        cudaFuncSetAttribute(attn_mma_kernel,
                             cudaFuncAttributeMaxDynamicSharedMemorySize, ATTN_SMEM);
        attr_set = 1;
    }

    const int n4_act = SZA / 4;

    // 0: mask compaction
    compact_mask_kernel<<<B, 256>>>(mask, gidx, cnt);

    // 1: split q input -> slot 0
    split_q_kernel<<<(n4_act + 255) / 256, 256>>>(query, ah, al, n4_act);

    // 2: gather+split compact k/v inputs -> slots 1, 2
    dim3 g_grid(S, B);
    gather_split_kv_kernel<<<g_grid, 128>>>(
        key, value, gidx, cnt,
        ah + (size_t)1 * SZA, al + (size_t)1 * SZA,
        ah + (size_t)2 * SZA, al + (size_t)2 * SZA);

    // 3: split all four weights
    FPtr4 win; win.p[0] = Wq; win.p[1] = Wk; win.p[2] = Wv; win.p[3] = Wo;
    dim3 sw_grid(D / 32, D / 32, 4);
    split_wt4_kernel<<<sw_grid, 256>>>(win, bh, bl);

    // 4: batched projections (K/V blocks beyond compact rows early-exit)
    QKVBias qb; qb.p[0] = bq; qb.p[1] = bk; qb.p[2] = bv;
    dim3 qkv_grid(GN / 64, M_ROWS / 128, 3);
    qkv_gemm_kernel<<<qkv_grid, 256, GEMM_SMEM>>>(
        ah, al, bh, bl, qb, cnt, ah + (size_t)3 * SZA, al + (size_t)3 * SZA);

    // 5: attention on compact K/V (slots 4, 5), Q (slot 3) -> ctx (slot 6)
    dim3 attn_grid(S / 128, H, B);
    attn_mma_kernel<<<attn_grid, 256, ATTN_SMEM>>>(
        ah + (size_t)3 * SZA, al + (size_t)3 * SZA,
        ah + (size_t)4 * SZA, al + (size_t)4 * SZA,
        ah + (size_t)5 * SZA, al + (size_t)5 * SZA,
        cnt,
        ah + (size_t)6 * SZA, al + (size_t)6 * SZA);

    // 6: output projection
    dim3 gemm_grid(GN / 64, M_ROWS / 128);
    oproj_gemm_kernel<<<gemm_grid, 256, GEMM_SMEM>>>(
        ah + (size_t)6 * SZA, al + (size_t)6 * SZA,
        bh + (size_t)3 * D * D, bl + (size_t)3 * D * D, bo, out);
}

// round 12
// speedup vs baseline: 6.2717x; 1.3207x over previous
#include <cuda_runtime.h>
#include <cuda_fp16.h>
#include <math.h>
#include <stdint.h>

// Problem constants
#define B  2
#define S  2048
#define D  1024
#define H  16
#define DK 64
#define M_ROWS (B * S)   // 4096
#define GK 1024
#define GN 1024
#define SZA (M_ROWS * D)

// ---------------- scratch (device globals: allocation-free) ----------------
// slots: 0 = split q input; 1,2 = gathered compact k,v inputs;
//        3..5 = projected q, k(compact, hi only), v(compact, hi only); 6 = ctx
__device__ __half g_Ah[7][SZA];
__device__ __half g_Al[7][SZA];
__device__ __half g_Bh[4][D * D];   // weights W^T fp16 (hi only)
__device__ int g_gidx[B * S];
__device__ int g_cnt[B];

struct FPtr4 { const float* p[4]; };

__device__ __forceinline__ uint32_t smem_u32(const void* p) {
    uint32_t a;
    asm("{ .reg .u64 t; cvta.to.shared.u64 t, %1; cvt.u32.u64 %0, t; }"
        : "=r"(a) : "l"(p));
    return a;
}
__device__ __forceinline__ void ldsm_x4(uint32_t (&r)[4], uint32_t addr) {
    asm volatile("ldmatrix.sync.aligned.m8n8.x4.shared.b16 {%0,%1,%2,%3}, [%4];"
                 : "=r"(r[0]), "=r"(r[1]), "=r"(r[2]), "=r"(r[3]) : "r"(addr));
}
__device__ __forceinline__ void ldsm_x4_t(uint32_t (&r)[4], uint32_t addr) {
    asm volatile("ldmatrix.sync.aligned.m8n8.x4.trans.shared.b16 {%0,%1,%2,%3}, [%4];"
                 : "=r"(r[0]), "=r"(r[1]), "=r"(r[2]), "=r"(r[3]) : "r"(addr));
}
__device__ __forceinline__ void mma_f16(float (&d)[4],
    const uint32_t (&a)[4], uint32_t b0, uint32_t b1)
{
    asm volatile(
        "mma.sync.aligned.m16n8k16.row.col.f32.f16.f16.f32 "
        "{%0,%1,%2,%3}, {%4,%5,%6,%7}, {%8,%9}, {%0,%1,%2,%3};"
        : "+f"(d[0]), "+f"(d[1]), "+f"(d[2]), "+f"(d[3])
        : "r"(a[0]), "r"(a[1]), "r"(a[2]), "r"(a[3]), "r"(b0), "r"(b1));
}
__device__ __forceinline__ void cpa16(uint32_t sd, const void* gs) {
    asm volatile("cp.async.cg.shared.global [%0], [%1], 16;" :: "r"(sd), "l"(gs));
}
__device__ __forceinline__ uint32_t pack2h(float f0, float f1) {
    __half h0 = __float2half(f0), h1 = __float2half(f1);
    return (uint32_t)*(uint16_t*)&h0 | ((uint32_t)*(uint16_t*)&h1 << 16);
}
__device__ __forceinline__ void split2h(float f0, float f1, uint32_t& hi, uint32_t& lo) {
    __half h0 = __float2half(f0), h1 = __float2half(f1);
    __half l0 = __float2half(f0 - __half2float(h0));
    __half l1 = __float2half(f1 - __half2float(h1));
    hi = (uint32_t)*(uint16_t*)&h0 | ((uint32_t)*(uint16_t*)&h1 << 16);
    lo = (uint32_t)*(uint16_t*)&l0 | ((uint32_t)*(uint16_t*)&l1 << 16);
}

// ---------------- mask compaction: per-batch prefix scan ----------------
__global__ __launch_bounds__(256) void compact_mask_kernel(
    const int* __restrict__ mask, int* __restrict__ gidx, int* __restrict__ cnt)
{
    __shared__ int wsum[8];
    const int b = blockIdx.x;
    const int tid = threadIdx.x, lane = tid & 31, wid = tid >> 5;
    int keep[8], local = 0;
#pragma unroll
    for (int i = 0; i < 8; i++) {
        keep[i] = (mask[b * S + tid * 8 + i] == 0);
        local += keep[i];
    }
    int v = local;
#pragma unroll
    for (int off = 1; off < 32; off <<= 1) {
        int n = __shfl_up_sync(0xffffffffu, v, off);
        if (lane >= off) v += n;
    }
    int excl = v - local;
    if (lane == 31) wsum[wid] = v;
    __syncthreads();
    if (wid == 0 && lane < 8) {
        int w = wsum[lane];
        int wv = w;
#pragma unroll
        for (int off = 1; off < 8; off <<= 1) {
            int n = __shfl_up_sync(0xffu, wv, off);
            if (lane >= off) wv += n;
        }
        wsum[lane] = wv - w;
        if (lane == 7) cnt[b] = wv;
    }
    __syncthreads();
    int base = wsum[wid] + excl;
#pragma unroll
    for (int i = 0; i < 8; i++)
        if (keep[i]) gidx[b * S + base++] = tid * 8 + i;
}

// ---------------- split q input (fp32 -> fp16 hi/lo) ----------------
__global__ __launch_bounds__(256) void split_q_kernel(
    const float* __restrict__ X, __half* __restrict__ Xh,
    __half* __restrict__ Xl, int n4)
{
    int i = blockIdx.x * 256 + threadIdx.x;
    if (i >= n4) return;
    float4 v = ((const float4*)X)[i];
    uint32_t h0, l0, h1, l1;
    split2h(v.x, v.y, h0, l0);
    split2h(v.z, v.w, h1, l1);
    *(uint32_t*)&Xh[i * 4 + 0] = h0;
    *(uint32_t*)&Xh[i * 4 + 2] = h1;
    *(uint32_t*)&Xl[i * 4 + 0] = l0;
    *(uint32_t*)&Xl[i * 4 + 2] = l1;
}

// gather unmasked input rows of key/value + split fp16 hi/lo; zero-pad
__global__ __launch_bounds__(128) void gather_split_kv_kernel(
    const float* __restrict__ keyIn, const float* __restrict__ valIn,
    const int* __restrict__ gidx, const int* __restrict__ cnt,
    __half* __restrict__ Kh, __half* __restrict__ Kl,
    __half* __restrict__ Vh, __half* __restrict__ Vl)
{
    const int b = blockIdx.y, pos = blockIdx.x, tid = threadIdx.x;
    const int c = cnt[b];
    const int cpad = (c + 63) & ~63;
    if (pos >= cpad) return;
    const size_t dst = (size_t)(b * S + pos) * D + tid * 8;
    if (pos < c) {
        const size_t src = (size_t)(b * S + gidx[b * S + pos]) * D + tid * 8;
#pragma unroll
        for (int t = 0; t < 2; t++) {
            const float* in = t ? valIn : keyIn;
            __half* oh = t ? Vh : Kh;
            __half* ol = t ? Vl : Kl;
            float4 v0 = *(const float4*)&in[src];
            float4 v1 = *(const float4*)&in[src + 4];
            uint32_t h0, l0, h1, l1, h2, l2, h3, l3;
            split2h(v0.x, v0.y, h0, l0);
            split2h(v0.z, v0.w, h1, l1);
            split2h(v1.x, v1.y, h2, l2);
            split2h(v1.z, v1.w, h3, l3);
            *(uint4*)&oh[dst] = make_uint4(h0, h1, h2, h3);
            *(uint4*)&ol[dst] = make_uint4(l0, l1, l2, l3);
        }
    } else {
        uint4 z = make_uint4(0, 0, 0, 0);
        *(uint4*)&Kh[dst] = z;
        *(uint4*)&Kl[dst] = z;
        *(uint4*)&Vh[dst] = z;
        *(uint4*)&Vl[dst] = z;
    }
}

// W[k][n] fp32 -> Wt fp16 [n][k] (hi only)
__global__ __launch_bounds__(256) void split_wt4_kernel(
    FPtr4 W, __half* __restrict__ WthB)
{
    __shared__ float t[32][33];
    int z = blockIdx.z;
    int k0 = blockIdx.y * 32, n0 = blockIdx.x * 32;
    int tx = threadIdx.x & 31, ty = threadIdx.x >> 5;
    const float* Wp = W.p[z];
    __half* Wth = WthB + (size_t)z * D * D;
#pragma unroll
    for (int i = 0; i < 4; i++)
        t[ty + i * 8][tx] = Wp[(size_t)(k0 + ty + i * 8) * D + n0 + tx];
    __syncthreads();
#pragma unroll
    for (int i = 0; i < 4; i++) {
        float v = t[tx][ty + i * 8];
        Wth[(size_t)(n0 + ty + i * 8) * D + k0 + tx] = __float2half(v);
    }
}

// ---------------- fp16x2 GEMM body ----------------
// out = (Ah + Al) @ Bh^T + bias ; 2 mma passes per k16.
#define BK 32
#define NCH (GK / BK)
#define OFF_AL 10240
#define OFF_BH 20480
#define STAGE_SB 25600
#define GEMM_SMEM (3 * STAGE_SB)   // 76800

__device__ __forceinline__ void gemm_body(
    const __half* __restrict__ Ah, const __half* __restrict__ Al,
    const __half* __restrict__ Bh,
    const float* __restrict__ bias, float* __restrict__ C,
    __half* __restrict__ Ch, __half* __restrict__ Cl,
    char* smem)
{
    const uint32_t sbase = smem_u32(smem);
    const int tid = threadIdx.x;
    const int lane = tid & 31;
    const int wid = tid >> 5;
    const int warp_m = wid & 3;
    const int warp_n = wid >> 2;
    const int m0 = blockIdx.y * 128;
    const int n0 = blockIdx.x * 64;

    const __half* gAh = Ah + (size_t)m0 * GK;
    const __half* gAl = Al + (size_t)m0 * GK;
    const __half* gBh = Bh + (size_t)n0 * GK;

    const int lrow = tid >> 2;
    const int lc   = tid & 3;

    auto load_stage = [&](int stg, int k0) {
        uint32_t sb = sbase + stg * STAGE_SB;
#pragma unroll
        for (int j = 0; j < 2; j++) {
            int row = lrow + j * 64;
            uint32_t so = row * 80 + lc * 16;
            size_t go = (size_t)row * GK + k0 + lc * 8;
            cpa16(sb + so,          gAh + go);
            cpa16(sb + OFF_AL + so, gAl + go);
        }
        {
            uint32_t so = lrow * 80 + lc * 16;
            size_t go = (size_t)lrow * GK + k0 + lc * 8;
            cpa16(sb + OFF_BH + so, gBh + go);
        }
        asm volatile("cp.async.commit_group;");
    };

    float acc[2][4][4];
#pragma unroll
    for (int i = 0; i < 2; i++)
#pragma unroll
        for (int j = 0; j < 4; j++)
#pragma unroll
            for (int v = 0; v < 4; v++) acc[i][j][v] = 0.f;

    load_stage(0, 0);
    load_stage(1, BK);

    const int a_row = lane & 15;
    const int a_kc  = lane >> 4;
    const int bg    = lane >> 3;
    const int b_row = ((bg >> 1) * 8) + (lane & 7);
    const int b_kc  = bg & 1;

    int stg = 0;
    for (int ch = 0; ch < NCH; ch++) {
        if (ch < NCH - 1) asm volatile("cp.async.wait_group 1;");
        else              asm volatile("cp.async.wait_group 0;");
        __syncthreads();
        if (ch + 2 < NCH) {
            int ns = stg + 2; if (ns >= 3) ns -= 3;
            load_stage(ns, (ch + 2) * BK);
        }
        const uint32_t st = sbase + stg * STAGE_SB;
#pragma unroll
        for (int kc = 0; kc < 2; kc++) {
            uint32_t a_h[2][4], a_l[2][4], b_h[2][4];
#pragma unroll
            for (int mt = 0; mt < 2; mt++) {
                uint32_t ro = (warp_m * 32 + mt * 16 + a_row) * 80
                            + (kc * 2 + a_kc) * 16;
                ldsm_x4(a_h[mt], st + ro);
                ldsm_x4(a_l[mt], st + OFF_AL + ro);
            }
#pragma unroll
            for (int ng = 0; ng < 2; ng++) {
                uint32_t ro = (warp_n * 32 + ng * 16 + b_row) * 80
                            + (kc * 2 + b_kc) * 16;
                ldsm_x4(b_h[ng], st + OFF_BH + ro);
            }
#pragma unroll
            for (int mt = 0; mt < 2; mt++)
#pragma unroll
                for (int ng = 0; ng < 2; ng++) {
                    mma_f16(acc[mt][ng * 2 + 0], a_h[mt], b_h[ng][0], b_h[ng][1]);
                    mma_f16(acc[mt][ng * 2 + 1], a_h[mt], b_h[ng][2], b_h[ng][3]);
                }
#pragma unroll
            for (int mt = 0; mt < 2; mt++)
#pragma unroll
                for (int ng = 0; ng < 2; ng++) {
                    mma_f16(acc[mt][ng * 2 + 0], a_l[mt], b_h[ng][0], b_h[ng][1]);
                    mma_f16(acc[mt][ng * 2 + 1], a_l[mt], b_h[ng][2], b_h[ng][3]);
                }
        }
        // no trailing sync needed: next iteration's top sync orders reads of
        // stage stg before the distance-2 prefetch that overwrites it
        if (++stg == 3) stg = 0;
    }

    const int grp = lane >> 2, tg = lane & 3;
#pragma unroll
    for (int mt = 0; mt < 2; mt++) {
        int r0 = m0 + warp_m * 32 + mt * 16 + grp;
#pragma unroll
        for (int nt = 0; nt < 4; nt++) {
            int c = n0 + warp_n * 32 + nt * 8 + tg * 2;
            float2 b2 = *(const float2*)&bias[c];
            float o00 = acc[mt][nt][0] + b2.x;
            float o01 = acc[mt][nt][1] + b2.y;
            float o10 = acc[mt][nt][2] + b2.x;
            float o11 = acc[mt][nt][3] + b2.y;
            if (C) {
                *(float2*)&C[(size_t)r0 * GN + c] = make_float2(o00, o01);
                *(float2*)&C[(size_t)(r0 + 8) * GN + c] = make_float2(o10, o11);
            } else if (Cl) {
                uint32_t h0, l0, h1, l1;
                split2h(o00, o01, h0, l0);
                split2h(o10, o11, h1, l1);
                *(uint32_t*)&Ch[(size_t)r0 * GN + c] = h0;
                *(uint32_t*)&Cl[(size_t)r0 * GN + c] = l0;
                *(uint32_t*)&Ch[(size_t)(r0 + 8) * GN + c] = h1;
                *(uint32_t*)&Cl[(size_t)(r0 + 8) * GN + c] = l1;
            } else {
                *(uint32_t*)&Ch[(size_t)r0 * GN + c] = pack2h(o00, o01);
                *(uint32_t*)&Ch[(size_t)(r0 + 8) * GN + c] = pack2h(o10, o11);
            }
        }
    }
}

struct QKVBias { const float* p[3]; };

// batched Q/K/V projection; K/V blocks beyond compact count exit early;
// Q (z=0) writes hi/lo, K/V (z=1,2) write hi only (attention B-operands)
__global__ __launch_bounds__(256, 2) void qkv_gemm_kernel(
    const __half* __restrict__ AhB, const __half* __restrict__ AlB,
    const __half* __restrict__ BhB,
    QKVBias bias, const int* __restrict__ cnt,
    __half* __restrict__ ChB, __half* __restrict__ ClB)
{
    extern __shared__ char smem[];
    const int z = blockIdx.z;
    if (z > 0) {
        const int m0 = blockIdx.y * 128;
        const int b = m0 / S;
        const int cpad = (cnt[b] + 63) & ~63;
        if ((m0 % S) >= cpad) return;
    }
    gemm_body(AhB + (size_t)z * SZA, AlB + (size_t)z * SZA,
              BhB + (size_t)z * D * D,
              bias.p[z], nullptr,
              ChB + (size_t)z * SZA,
              (z == 0) ? (ClB + (size_t)z * SZA) : nullptr, smem);
}

__global__ __launch_bounds__(256, 2) void oproj_gemm_kernel(
    const __half* __restrict__ Ah, const __half* __restrict__ Al,
    const __half* __restrict__ Bh,
    const float* __restrict__ bias, float* __restrict__ C)
{
    extern __shared__ char smem[];
    gemm_body(Ah, Al, Bh, bias, C, nullptr, nullptr, smem);
}

// ---------------- Attention: fp16x2 HMMA, compacted keys, 2-stage --------
// stage: Kh tile (64x144B = 9216) + Vh tile (9216) = 18432
#define ASTG 18432
#define AT_VH 9216
#define ATTN_SMEM (2 * ASTG)   // 36864

__global__ __launch_bounds__(256, 2) void attn_mma_kernel(
    const __half* __restrict__ Qh, const __half* __restrict__ Ql,
    const __half* __restrict__ Kh, const __half* __restrict__ Vh,
    const int* __restrict__ cnt,
    __half* __restrict__ Ch, __half* __restrict__ Cl)
{
    extern __shared__ char smem[];
    const uint32_t sb = smem_u32(smem);
    const int tid = threadIdx.x, lane = tid & 31, wid = tid >> 5;
    const int b = blockIdx.z, h = blockIdx.y, q0 = blockIdx.x * 128;
    const int cn = cnt[b];
    const int nch = (cn + 63) >> 6;

    // ---- stage Q tile (hi/lo) into smem once, ldsm to fragments ----
    // Q hi at [0, 18432), Q lo at [18432, 36864) — reused by K/V stages after
#pragma unroll
    for (int t = 0; t < 8; t++) {
        int idx = tid + t * 256;
        int half_ = idx >> 10;
        int c = idx & 1023;
        int row = c >> 3, ch = c & 7;
        const __half* src = (half_ ? Ql : Qh)
            + (size_t)(b * S + q0 + row) * D + h * DK + ch * 8;
        *(uint4*)(smem + half_ * 18432 + row * 144 + ch * 16) = *(const uint4*)src;
    }
    __syncthreads();
    uint32_t qfh[4][4], qfl[4][4];
    {
        int r = wid * 16 + (lane & 15);
        int hc = lane >> 4;
#pragma unroll
        for (int c = 0; c < 4; c++) {
            ldsm_x4(qfh[c], sb + r * 144 + (c * 2 + hc) * 16);
            ldsm_x4(qfl[c], sb + 18432 + r * 144 + (c * 2 + hc) * 16);
        }
    }
    __syncthreads();

    auto load_stage = [&](int stg, int kk) {
        uint32_t base = sb + stg * ASTG;
#pragma unroll
        for (int t = 0; t < 4; t++) {
            int idx = tid + t * 256;       // 0..1023
            int tile = idx >> 9;           // 0..1 (Kh, Vh)
            int c = idx & 511;
            int row = c >> 3, ch = c & 7;
            const __half* g = (tile == 0 ? Kh : Vh)
                + (size_t)(b * S + kk + row) * D + h * DK + ch * 8;
            cpa16(base + tile * 9216 + row * 144 + ch * 16, g);
        }
        asm volatile("cp.async.commit_group;");
    };

    float acc[8][4];
#pragma unroll
    for (int j = 0; j < 8; j++)
#pragma unroll
        for (int v = 0; v < 4; v++) acc[j][v] = 0.f;
    float m0r = -1e30f, m1r = -1e30f, l0r = 0.f, l1r = 0.f;
    const float scale = 0.125f;

    if (nch >= 1) load_stage(0, 0);
    if (nch >= 2) load_stage(1, 64);

    const int bg    = lane >> 3;
    const int b_row = ((bg >> 1) * 8) + (lane & 7);
    const int b_kc  = bg & 1;
    const int tr    = lane & 15;
    const int tc    = lane >> 4;
    const int jlane = (lane & 3) * 2;

    for (int it = 0; it < nch; it++) {
        const int stg = it & 1;
        if (it < nch - 1) asm volatile("cp.async.wait_group 1;");
        else              asm volatile("cp.async.wait_group 0;");
        __syncthreads();

        const uint32_t st = sb + stg * ASTG;

        float s[8][4];
#pragma unroll
        for (int j = 0; j < 8; j++)
#pragma unroll
            for (int v = 0; v < 4; v++) s[j][v] = 0.f;
#pragma unroll
        for (int c = 0; c < 4; c++) {
#pragma unroll
            for (int np = 0; np < 4; np++) {
                uint32_t kbh[4];
                uint32_t ro = (np * 16 + b_row) * 144 + (c * 2 + b_kc) * 16;
                ldsm_x4(kbh, st + ro);
                mma_f16(s[np * 2 + 0], qfh[c], kbh[0], kbh[1]);
                mma_f16(s[np * 2 + 1], qfh[c], kbh[2], kbh[3]);
                mma_f16(s[np * 2 + 0], qfl[c], kbh[0], kbh[1]);
                mma_f16(s[np * 2 + 1], qfl[c], kbh[2], kbh[3]);
            }
        }

        // online softmax; tail columns (j >= cn) masked by index compare
        const int jbase = it * 64 + jlane;
        float mx0 = -1e30f, mx1 = -1e30f;
#pragma unroll
        for (int nt = 0; nt < 8; nt++) {
            int j0 = jbase + nt * 8;
            bool k0m = (j0 >= cn), k1m = (j0 + 1 >= cn);
            s[nt][0] = k0m ? -1e30f : s[nt][0] * scale;
            s[nt][1] = k1m ? -1e30f : s[nt][1] * scale;
            s[nt][2] = k0m ? -1e30f : s[nt][2] * scale;
            s[nt][3] = k1m ? -1e30f : s[nt][3] * scale;
            mx0 = fmaxf(mx0, fmaxf(s[nt][0], s[nt][1]));
            mx1 = fmaxf(mx1, fmaxf(s[nt][2], s[nt][3]));
        }
#pragma unroll
        for (int off = 1; off < 4; off <<= 1) {
            mx0 = fmaxf(mx0, __shfl_xor_sync(0xffffffffu, mx0, off));
            mx1 = fmaxf(mx1, __shfl_xor_sync(0xffffffffu, mx1, off));
        }
        float mn0 = fmaxf(m0r, mx0), mn1 = fmaxf(m1r, mx1);
        float cr0 = __expf(m0r - mn0), cr1 = __expf(m1r - mn1);
        float sum0 = 0.f, sum1 = 0.f;
#pragma unroll
        for (int nt = 0; nt < 8; nt++) {
            float p0 = (s[nt][0] > -5e29f) ? __expf(s[nt][0] - mn0) : 0.f;
            float p1 = (s[nt][1] > -5e29f) ? __expf(s[nt][1] - mn0) : 0.f;
            float p2 = (s[nt][2] > -5e29f) ? __expf(s[nt][2] - mn1) : 0.f;
            float p3 = (s[nt][3] > -5e29f) ? __expf(s[nt][3] - mn1) : 0.f;
            s[nt][0] = p0; s[nt][1] = p1; s[nt][2] = p2; s[nt][3] = p3;
            sum0 += p0 + p1;
            sum1 += p2 + p3;
        }
#pragma unroll
        for (int off = 1; off < 4; off <<= 1) {
            sum0 += __shfl_xor_sync(0xffffffffu, sum0, off);
            sum1 += __shfl_xor_sync(0xffffffffu, sum1, off);
        }
        l0r = l0r * cr0 + sum0;
        l1r = l1r * cr1 + sum1;
        m0r = mn0; m1r = mn1;
#pragma unroll
        for (int nt = 0; nt < 8; nt++) {
            acc[nt][0] *= cr0; acc[nt][1] *= cr0;
            acc[nt][2] *= cr1; acc[nt][3] *= cr1;
        }

        // P fragments hi/lo (A-operand compensated; V single-rounded)
        uint32_t pah[4][4], pal[4][4];
#pragma unroll
        for (int c = 0; c < 4; c++) {
            split2h(s[2 * c][0],     s[2 * c][1],     pah[c][0], pal[c][0]);
            split2h(s[2 * c][2],     s[2 * c][3],     pah[c][1], pal[c][1]);
            split2h(s[2 * c + 1][0], s[2 * c + 1][1], pah[c][2], pal[c][2]);
            split2h(s[2 * c + 1][2], s[2 * c + 1][3], pah[c][3], pal[c][3]);
        }

#pragma unroll
        for (int c = 0; c < 4; c++) {
#pragma unroll
            for (int np = 0; np < 4; np++) {
                uint32_t vbh[4];
                uint32_t ro = (c * 16 + tr) * 144 + np * 32 + tc * 16;
                ldsm_x4_t(vbh, st + AT_VH + ro);
                mma_f16(acc[np * 2 + 0], pah[c], vbh[0], vbh[1]);
                mma_f16(acc[np * 2 + 1], pah[c], vbh[2], vbh[3]);
                mma_f16(acc[np * 2 + 0], pal[c], vbh[0], vbh[1]);
                mma_f16(acc[np * 2 + 1], pal[c], vbh[2], vbh[3]);
            }
        }
        __syncthreads();   // required: next prefetch rewrites this stage
        if (it + 2 < nch) load_stage(stg, (it + 2) * 64);
    }

    // ---- epilogue: write context as fp16 hi/lo (oproj A-operand) ----
    float inv0 = (l0r > 0.f) ? (1.f / l0r) : 0.f;
    float inv1 = (l1r > 0.f) ? (1.f / l1r) : 0.f;
    int r0 = q0 + wid * 16 + (lane >> 2);
#pragma unroll
    for (int nt = 0; nt < 8; nt++) {
        int c = h * DK + nt * 8 + (lane & 3) * 2;
        uint32_t h0, l0, h1, l1;
        split2h(acc[nt][0] * inv0, acc[nt][1] * inv0, h0, l0);
        split2h(acc[nt][2] * inv1, acc[nt][3] * inv1, h1, l1);
        size_t o0 = (size_t)(b * S + r0) * D + c;
        size_t o1 = (size_t)(b * S + r0 + 8) * D + c;
        *(uint32_t*)&Ch[o0] = h0;
        *(uint32_t*)&Cl[o0] = l0;
        *(uint32_t*)&Ch[o1] = h1;
        *(uint32_t*)&Cl[o1] = l1;
    }
}

// ---------------- launch ----------------
extern "C" void kernel_launch(void* const* d_in, const int* in_sizes, int n_in,
                              void* d_out, int out_size)
{
    const float* query = (const float*)d_in[0];
    const float* key   = (const float*)d_in[1];
    const float* value = (const float*)d_in[2];
    const int*   mask  = (const int*)d_in[3];
    const float* Wq = (const float*)d_in[4];
    const float* bq = (const float*)d_in[5];
    const float* Wk = (const float*)d_in[6];
    const float* bk = (const float*)d_in[7];
    const float* Wv = (const float*)d_in[8];
    const float* bv = (const float*)d_in[9];
    const float* Wo = (const float*)d_in[10];
    const float* bo = (const float*)d_in[11];
    float* out = (float*)d_out;

    __half *ah, *al, *bh;
    int *gidx, *cnt;
    cudaGetSymbolAddress((void**)&ah, g_Ah);
    cudaGetSymbolAddress((void**)&al, g_Al);
    cudaGetSymbolAddress((void**)&bh, g_Bh);
    cudaGetSymbolAddress((void**)&gidx, g_gidx);
    cudaGetSymbolAddress((void**)&cnt, g_cnt);

    static int attr_set = 0;
    if (!attr_set) {
        cudaFuncSetAttribute(qkv_gemm_kernel,
                             cudaFuncAttributeMaxDynamicSharedMemorySize, GEMM_SMEM);
        cudaFuncSetAttribute(oproj_gemm_kernel,
                             cudaFuncAttributeMaxDynamicSharedMemorySize, GEMM_SMEM);
        cudaFuncSetAttribute(attn_mma_kernel,
                             cudaFuncAttributeMaxDynamicSharedMemorySize, ATTN_SMEM);
        attr_set = 1;
    }

    const int n4_act = SZA / 4;

    // 0: mask compaction
    compact_mask_kernel<<<B, 256>>>(mask, gidx, cnt);

    // 1: split q input -> slot 0
    split_q_kernel<<<(n4_act + 255) / 256, 256>>>(query, ah, al, n4_act);

    // 2: gather+split compact k/v inputs -> slots 1, 2
    dim3 g_grid(S, B);
    gather_split_kv_kernel<<<g_grid, 128>>>(
        key, value, gidx, cnt,
        ah + (size_t)1 * SZA, al + (size_t)1 * SZA,
        ah + (size_t)2 * SZA, al + (size_t)2 * SZA);

    // 3: split all four weights (fp16, hi only)
    FPtr4 win; win.p[0] = Wq; win.p[1] = Wk; win.p[2] = Wv; win.p[3] = Wo;
    dim3 sw_grid(D / 32, D / 32, 4);
    split_wt4_kernel<<<sw_grid, 256>>>(win, bh);

    // 4: batched projections (K/V early-exit past compact rows)
    QKVBias qb; qb.p[0] = bq; qb.p[1] = bk; qb.p[2] = bv;
    dim3 qkv_grid(GN / 64, M_ROWS / 128, 3);
    qkv_gemm_kernel<<<qkv_grid, 256, GEMM_SMEM>>>(
        ah, al, bh, qb, cnt, ah + (size_t)3 * SZA, al + (size_t)3 * SZA);

    // 5: attention: Q (slot 3 hi/lo), K (slot 4 hi), V (slot 5 hi) -> ctx slot 6
    dim3 attn_grid(S / 128, H, B);
    attn_mma_kernel<<<attn_grid, 256, ATTN_SMEM>>>(
        ah + (size_t)3 * SZA, al + (size_t)3 * SZA,
        ah + (size_t)4 * SZA,
        ah + (size_t)5 * SZA,
        cnt,
        ah + (size_t)6 * SZA, al + (size_t)6 * SZA);

    // 6: output projection (fp32 out)
    dim3 gemm_grid(GN / 64, M_ROWS / 128);
    oproj_gemm_kernel<<<gemm_grid, 256, GEMM_SMEM>>>(
        ah + (size_t)6 * SZA, al + (size_t)6 * SZA,
        bh + (size_t)3 * D * D, bo, out);
}

// round 13
// speedup vs baseline: 8.0392x; 1.2818x over previous
#include <cuda_runtime.h>
#include <cuda_fp16.h>
#include <math.h>
#include <stdint.h>

// Problem constants
#define B  2
#define S  2048
#define D  1024
#define H  16
#define DK 64
#define M_ROWS (B * S)   // 4096
#define GK 1024
#define GN 1024
#define SZA (M_ROWS * D)

// ---------------- scratch (device globals: allocation-free) ----------------
// slots: 0 = split q input; 1,2 = gathered compact k,v inputs;
//        3..5 = projected q, k(compact), v(compact); 6 = ctx (hi only)
__device__ __half g_Ah[7][SZA];
__device__ __half g_Al[7][SZA];
__device__ __half g_Wh[4][D * D];   // weights fp16, layout [k][n] (NO transpose)
__device__ int g_gidx[B * S];
__device__ int g_cnt[B];

struct FPtr4 { const float* p[4]; };

__device__ __forceinline__ uint32_t smem_u32(const void* p) {
    uint32_t a;
    asm("{ .reg .u64 t; cvta.to.shared.u64 t, %1; cvt.u32.u64 %0, t; }"
        : "=r"(a) : "l"(p));
    return a;
}
__device__ __forceinline__ void ldsm_x4(uint32_t (&r)[4], uint32_t addr) {
    asm volatile("ldmatrix.sync.aligned.m8n8.x4.shared.b16 {%0,%1,%2,%3}, [%4];"
                 : "=r"(r[0]), "=r"(r[1]), "=r"(r[2]), "=r"(r[3]) : "r"(addr));
}
__device__ __forceinline__ void ldsm_x4_t(uint32_t (&r)[4], uint32_t addr) {
    asm volatile("ldmatrix.sync.aligned.m8n8.x4.trans.shared.b16 {%0,%1,%2,%3}, [%4];"
                 : "=r"(r[0]), "=r"(r[1]), "=r"(r[2]), "=r"(r[3]) : "r"(addr));
}
__device__ __forceinline__ void mma_f16(float (&d)[4],
    const uint32_t (&a)[4], uint32_t b0, uint32_t b1)
{
    asm volatile(
        "mma.sync.aligned.m16n8k16.row.col.f32.f16.f16.f32 "
        "{%0,%1,%2,%3}, {%4,%5,%6,%7}, {%8,%9}, {%0,%1,%2,%3};"
        : "+f"(d[0]), "+f"(d[1]), "+f"(d[2]), "+f"(d[3])
        : "r"(a[0]), "r"(a[1]), "r"(a[2]), "r"(a[3]), "r"(b0), "r"(b1));
}
__device__ __forceinline__ void cpa16(uint32_t sd, const void* gs) {
    asm volatile("cp.async.cg.shared.global [%0], [%1], 16;" :: "r"(sd), "l"(gs));
}
__device__ __forceinline__ uint32_t pack2h(float f0, float f1) {
    __half h0 = __float2half(f0), h1 = __float2half(f1);
    return (uint32_t)*(uint16_t*)&h0 | ((uint32_t)*(uint16_t*)&h1 << 16);
}
__device__ __forceinline__ void split2h(float f0, float f1, uint32_t& hi, uint32_t& lo) {
    __half h0 = __float2half(f0), h1 = __float2half(f1);
    __half l0 = __float2half(f0 - __half2float(h0));
    __half l1 = __float2half(f1 - __half2float(h1));
    hi = (uint32_t)*(uint16_t*)&h0 | ((uint32_t)*(uint16_t*)&h1 << 16);
    lo = (uint32_t)*(uint16_t*)&l0 | ((uint32_t)*(uint16_t*)&l1 << 16);
}

// ---------------- mask compaction: per-batch prefix scan ----------------
__global__ __launch_bounds__(256) void compact_mask_kernel(
    const int* __restrict__ mask, int* __restrict__ gidx, int* __restrict__ cnt)
{
    __shared__ int wsum[8];
    const int b = blockIdx.x;
    const int tid = threadIdx.x, lane = tid & 31, wid = tid >> 5;
    int keep[8], local = 0;
#pragma unroll
    for (int i = 0; i < 8; i++) {
        keep[i] = (mask[b * S + tid * 8 + i] == 0);
        local += keep[i];
    }
    int v = local;
#pragma unroll
    for (int off = 1; off < 32; off <<= 1) {
        int n = __shfl_up_sync(0xffffffffu, v, off);
        if (lane >= off) v += n;
    }
    int excl = v - local;
    if (lane == 31) wsum[wid] = v;
    __syncthreads();
    if (wid == 0 && lane < 8) {
        int w = wsum[lane];
        int wv = w;
#pragma unroll
        for (int off = 1; off < 8; off <<= 1) {
            int n = __shfl_up_sync(0xffu, wv, off);
            if (lane >= off) wv += n;
        }
        wsum[lane] = wv - w;
        if (lane == 7) cnt[b] = wv;
    }
    __syncthreads();
    int base = wsum[wid] + excl;
#pragma unroll
    for (int i = 0; i < 8; i++)
        if (keep[i]) gidx[b * S + base++] = tid * 8 + i;
}

// ---------------- split q input (fp32 -> fp16 hi/lo) ----------------
__global__ __launch_bounds__(256) void split_q_kernel(
    const float* __restrict__ X, __half* __restrict__ Xh,
    __half* __restrict__ Xl, int n4)
{
    int i = blockIdx.x * 256 + threadIdx.x;
    if (i >= n4) return;
    float4 v = ((const float4*)X)[i];
    uint32_t h0, l0, h1, l1;
    split2h(v.x, v.y, h0, l0);
    split2h(v.z, v.w, h1, l1);
    *(uint32_t*)&Xh[i * 4 + 0] = h0;
    *(uint32_t*)&Xh[i * 4 + 2] = h1;
    *(uint32_t*)&Xl[i * 4 + 0] = l0;
    *(uint32_t*)&Xl[i * 4 + 2] = l1;
}

// gather unmasked input rows of key/value + split fp16 hi/lo; zero-pad
__global__ __launch_bounds__(128) void gather_split_kv_kernel(
    const float* __restrict__ keyIn, const float* __restrict__ valIn,
    const int* __restrict__ gidx, const int* __restrict__ cnt,
    __half* __restrict__ Kh, __half* __restrict__ Kl,
    __half* __restrict__ Vh, __half* __restrict__ Vl)
{
    const int b = blockIdx.y, pos = blockIdx.x, tid = threadIdx.x;
    const int c = cnt[b];
    const int cpad = (c + 63) & ~63;
    if (pos >= cpad) return;
    const size_t dst = (size_t)(b * S + pos) * D + tid * 8;
    if (pos < c) {
        const size_t src = (size_t)(b * S + gidx[b * S + pos]) * D + tid * 8;
#pragma unroll
        for (int t = 0; t < 2; t++) {
            const float* in = t ? valIn : keyIn;
            __half* oh = t ? Vh : Kh;
            __half* ol = t ? Vl : Kl;
            float4 v0 = *(const float4*)&in[src];
            float4 v1 = *(const float4*)&in[src + 4];
            uint32_t h0, l0, h1, l1, h2, l2, h3, l3;
            split2h(v0.x, v0.y, h0, l0);
            split2h(v0.z, v0.w, h1, l1);
            split2h(v1.x, v1.y, h2, l2);
            split2h(v1.z, v1.w, h3, l3);
            *(uint4*)&oh[dst] = make_uint4(h0, h1, h2, h3);
            *(uint4*)&ol[dst] = make_uint4(l0, l1, l2, l3);
        }
    } else {
        uint4 z = make_uint4(0, 0, 0, 0);
        *(uint4*)&Kh[dst] = z;
        *(uint4*)&Kl[dst] = z;
        *(uint4*)&Vh[dst] = z;
        *(uint4*)&Vl[dst] = z;
    }
}

// streaming weight convert fp32 -> fp16, layout preserved [k][n]
__global__ __launch_bounds__(256) void convert_w4_kernel(
    FPtr4 W, __half* __restrict__ WhB)
{
    int z = blockIdx.y;
    int i = blockIdx.x * 256 + threadIdx.x;
    if (i >= D * D / 4) return;
    float4 v = ((const float4*)W.p[z])[i];
    __half* Wh = WhB + (size_t)z * D * D;
    *(uint32_t*)&Wh[i * 4 + 0] = pack2h(v.x, v.y);
    *(uint32_t*)&Wh[i * 4 + 2] = pack2h(v.z, v.w);
}

// ---------------- fp16 GEMM body: B from row-major W[k][n] via ldsm.trans --
#define BK 32
#define NCH (GK / BK)
#define OFF_AL 10240
#define OFF_B  20480
#define STAGE_SB 25088           // 2*10240 + 32*144
#define GEMM_SMEM (3 * STAGE_SB) // 75264

template<bool USE_AL>
__device__ __forceinline__ void gemm_body(
    const __half* __restrict__ Ah, const __half* __restrict__ Al,
    const __half* __restrict__ W,   // [GK][GN] fp16
    const float* __restrict__ bias, float* __restrict__ C,
    __half* __restrict__ Ch, __half* __restrict__ Cl,
    char* smem)
{
    const uint32_t sbase = smem_u32(smem);
    const int tid = threadIdx.x;
    const int lane = tid & 31;
    const int wid = tid >> 5;
    const int warp_m = wid & 3;
    const int warp_n = wid >> 2;
    const int m0 = blockIdx.y * 128;
    const int n0 = blockIdx.x * 64;

    const __half* gAh = Ah + (size_t)m0 * GK;
    const __half* gAl = Al + (size_t)m0 * GK;

    const int lrow = tid >> 2;
    const int lc   = tid & 3;
    const int browb = tid >> 3;      // B row 0..31
    const int bchb  = tid & 7;       // B 16B chunk 0..7

    auto load_stage = [&](int stg, int k0) {
        uint32_t sb = sbase + stg * STAGE_SB;
#pragma unroll
        for (int j = 0; j < 2; j++) {
            int row = lrow + j * 64;
            uint32_t so = row * 80 + lc * 16;
            size_t go = (size_t)row * GK + k0 + lc * 8;
            cpa16(sb + so, gAh + go);
            if (USE_AL) cpa16(sb + OFF_AL + so, gAl + go);
        }
        cpa16(sb + OFF_B + browb * 144 + bchb * 16,
              W + (size_t)(k0 + browb) * GN + n0 + bchb * 8);
        asm volatile("cp.async.commit_group;");
    };

    float acc[2][4][4];
#pragma unroll
    for (int i = 0; i < 2; i++)
#pragma unroll
        for (int j = 0; j < 4; j++)
#pragma unroll
            for (int v = 0; v < 4; v++) acc[i][j][v] = 0.f;

    load_stage(0, 0);
    load_stage(1, BK);

    const int a_row = lane & 15;
    const int a_kc  = lane >> 4;
    const int tr    = lane & 15;
    const int tc    = lane >> 4;

    int stg = 0;
    for (int ch = 0; ch < NCH; ch++) {
        if (ch < NCH - 1) asm volatile("cp.async.wait_group 1;");
        else              asm volatile("cp.async.wait_group 0;");
        __syncthreads();
        if (ch + 2 < NCH) {
            int ns = stg + 2; if (ns >= 3) ns -= 3;
            load_stage(ns, (ch + 2) * BK);
        }
        const uint32_t st = sbase + stg * STAGE_SB;
#pragma unroll
        for (int kc = 0; kc < 2; kc++) {
            uint32_t a_h[2][4], a_l[2][4], b_t[2][4];
#pragma unroll
            for (int mt = 0; mt < 2; mt++) {
                uint32_t ro = (warp_m * 32 + mt * 16 + a_row) * 80
                            + (kc * 2 + a_kc) * 16;
                ldsm_x4(a_h[mt], st + ro);
                if (USE_AL) ldsm_x4(a_l[mt], st + OFF_AL + ro);
            }
#pragma unroll
            for (int ng = 0; ng < 2; ng++) {
                uint32_t ro = (kc * 16 + tr) * 144
                            + warp_n * 64 + ng * 32 + tc * 16;
                ldsm_x4_t(b_t[ng], st + OFF_B + ro);
            }
#pragma unroll
            for (int mt = 0; mt < 2; mt++)
#pragma unroll
                for (int ng = 0; ng < 2; ng++) {
                    mma_f16(acc[mt][ng * 2 + 0], a_h[mt], b_t[ng][0], b_t[ng][1]);
                    mma_f16(acc[mt][ng * 2 + 1], a_h[mt], b_t[ng][2], b_t[ng][3]);
                }
            if (USE_AL) {
#pragma unroll
                for (int mt = 0; mt < 2; mt++)
#pragma unroll
                    for (int ng = 0; ng < 2; ng++) {
                        mma_f16(acc[mt][ng * 2 + 0], a_l[mt], b_t[ng][0], b_t[ng][1]);
                        mma_f16(acc[mt][ng * 2 + 1], a_l[mt], b_t[ng][2], b_t[ng][3]);
                    }
            }
        }
        if (++stg == 3) stg = 0;
    }

    const int grp = lane >> 2, tg = lane & 3;
#pragma unroll
    for (int mt = 0; mt < 2; mt++) {
        int r0 = m0 + warp_m * 32 + mt * 16 + grp;
#pragma unroll
        for (int nt = 0; nt < 4; nt++) {
            int c = n0 + warp_n * 32 + nt * 8 + tg * 2;
            float2 b2 = *(const float2*)&bias[c];
            float o00 = acc[mt][nt][0] + b2.x;
            float o01 = acc[mt][nt][1] + b2.y;
            float o10 = acc[mt][nt][2] + b2.x;
            float o11 = acc[mt][nt][3] + b2.y;
            if (C) {
                *(float2*)&C[(size_t)r0 * GN + c] = make_float2(o00, o01);
                *(float2*)&C[(size_t)(r0 + 8) * GN + c] = make_float2(o10, o11);
            } else if (Cl) {
                uint32_t h0, l0, h1, l1;
                split2h(o00, o01, h0, l0);
                split2h(o10, o11, h1, l1);
                *(uint32_t*)&Ch[(size_t)r0 * GN + c] = h0;
                *(uint32_t*)&Cl[(size_t)r0 * GN + c] = l0;
                *(uint32_t*)&Ch[(size_t)(r0 + 8) * GN + c] = h1;
                *(uint32_t*)&Cl[(size_t)(r0 + 8) * GN + c] = l1;
            } else {
                *(uint32_t*)&Ch[(size_t)r0 * GN + c] = pack2h(o00, o01);
                *(uint32_t*)&Ch[(size_t)(r0 + 8) * GN + c] = pack2h(o10, o11);
            }
        }
    }
}

struct QKVBias { const float* p[3]; };

__global__ __launch_bounds__(256, 2) void qkv_gemm_kernel(
    const __half* __restrict__ AhB, const __half* __restrict__ AlB,
    const __half* __restrict__ WhB,
    QKVBias bias, const int* __restrict__ cnt,
    __half* __restrict__ ChB, __half* __restrict__ ClB)
{
    extern __shared__ char smem[];
    const int z = blockIdx.z;
    if (z > 0) {
        const int m0 = blockIdx.y * 128;
        const int b = m0 / S;
        const int cpad = (cnt[b] + 63) & ~63;
        if ((m0 % S) >= cpad) return;
    }
    gemm_body<true>(AhB + (size_t)z * SZA, AlB + (size_t)z * SZA,
                    WhB + (size_t)z * D * D,
                    bias.p[z], nullptr,
                    ChB + (size_t)z * SZA,
                    (z == 0) ? (ClB + (size_t)z * SZA) : nullptr, smem);
}

// oproj: A = ctx (hi only, single pass), fp32 out
__global__ __launch_bounds__(256, 2) void oproj_gemm_kernel(
    const __half* __restrict__ Ah, const __half* __restrict__ Wh,
    const float* __restrict__ bias, float* __restrict__ C)
{
    extern __shared__ char smem[];
    gemm_body<false>(Ah, nullptr, Wh, bias, C, nullptr, nullptr, smem);
}

// ---------------- Attention: fp16 HMMA, compacted keys, 2-stage ----------
// QK: Qh/Ql x Kh (2 passes). PV: Ph x Vh (1 pass). Tail-only masking.
#define ASTG 18432
#define AT_VH 9216
#define ATTN_SMEM (2 * ASTG)   // 36864

__global__ __launch_bounds__(256, 2) void attn_mma_kernel(
    const __half* __restrict__ Qh, const __half* __restrict__ Ql,
    const __half* __restrict__ Kh, const __half* __restrict__ Vh,
    const int* __restrict__ cnt,
    __half* __restrict__ Ch)
{
    extern __shared__ char smem[];
    const uint32_t sb = smem_u32(smem);
    const int tid = threadIdx.x, lane = tid & 31, wid = tid >> 5;
    const int b = blockIdx.z, h = blockIdx.y, q0 = blockIdx.x * 128;
    const int cn = cnt[b];
    const int nch = (cn + 63) >> 6;

    // ---- stage Q tile (hi/lo) into smem once, ldsm to fragments ----
#pragma unroll
    for (int t = 0; t < 8; t++) {
        int idx = tid + t * 256;
        int half_ = idx >> 10;
        int c = idx & 1023;
        int row = c >> 3, ch = c & 7;
        const __half* src = (half_ ? Ql : Qh)
            + (size_t)(b * S + q0 + row) * D + h * DK + ch * 8;
        *(uint4*)(smem + half_ * 18432 + row * 144 + ch * 16) = *(const uint4*)src;
    }
    __syncthreads();
    uint32_t qfh[4][4], qfl[4][4];
    {
        int r = wid * 16 + (lane & 15);
        int hc = lane >> 4;
#pragma unroll
        for (int c = 0; c < 4; c++) {
            ldsm_x4(qfh[c], sb + r * 144 + (c * 2 + hc) * 16);
            ldsm_x4(qfl[c], sb + 18432 + r * 144 + (c * 2 + hc) * 16);
        }
    }
    __syncthreads();

    auto load_stage = [&](int stg, int kk) {
        uint32_t base = sb + stg * ASTG;
#pragma unroll
        for (int t = 0; t < 4; t++) {
            int idx = tid + t * 256;
            int tile = idx >> 9;
            int c = idx & 511;
            int row = c >> 3, ch = c & 7;
            const __half* g = (tile == 0 ? Kh : Vh)
                + (size_t)(b * S + kk + row) * D + h * DK + ch * 8;
            cpa16(base + tile * 9216 + row * 144 + ch * 16, g);
        }
        asm volatile("cp.async.commit_group;");
    };

    float acc[8][4];
#pragma unroll
    for (int j = 0; j < 8; j++)
#pragma unroll
        for (int v = 0; v < 4; v++) acc[j][v] = 0.f;
    float m0r = -1e30f, m1r = -1e30f, l0r = 0.f, l1r = 0.f;
    const float scale = 0.125f;

    if (nch >= 1) load_stage(0, 0);
    if (nch >= 2) load_stage(1, 64);

    const int bg    = lane >> 3;
    const int b_row = ((bg >> 1) * 8) + (lane & 7);
    const int b_kc  = bg & 1;
    const int tr    = lane & 15;
    const int tc    = lane >> 4;
    const int jlane = (lane & 3) * 2;

    for (int it = 0; it < nch; it++) {
        const int stg = it & 1;
        if (it < nch - 1) asm volatile("cp.async.wait_group 1;");
        else              asm volatile("cp.async.wait_group 0;");
        __syncthreads();

        const uint32_t st = sb + stg * ASTG;

        float s[8][4];
#pragma unroll
        for (int j = 0; j < 8; j++)
#pragma unroll
            for (int v = 0; v < 4; v++) s[j][v] = 0.f;
#pragma unroll
        for (int c = 0; c < 4; c++) {
#pragma unroll
            for (int np = 0; np < 4; np++) {
                uint32_t kbh[4];
                uint32_t ro = (np * 16 + b_row) * 144 + (c * 2 + b_kc) * 16;
                ldsm_x4(kbh, st + ro);
                mma_f16(s[np * 2 + 0], qfh[c], kbh[0], kbh[1]);
                mma_f16(s[np * 2 + 1], qfh[c], kbh[2], kbh[3]);
                mma_f16(s[np * 2 + 0], qfl[c], kbh[0], kbh[1]);
                mma_f16(s[np * 2 + 1], qfl[c], kbh[2], kbh[3]);
            }
        }

        // ---- online softmax; masking only on the final (tail) chunk ----
        float mx0 = -1e30f, mx1 = -1e30f;
        if (it == nch - 1) {
            const int jbase = it * 64 + jlane;
#pragma unroll
            for (int nt = 0; nt < 8; nt++) {
                int j0 = jbase + nt * 8;
                bool k0m = (j0 >= cn), k1m = (j0 + 1 >= cn);
                s[nt][0] = k0m ? -1e30f : s[nt][0] * scale;
                s[nt][1] = k1m ? -1e30f : s[nt][1] * scale;
                s[nt][2] = k0m ? -1e30f : s[nt][2] * scale;
                s[nt][3] = k1m ? -1e30f : s[nt][3] * scale;
                mx0 = fmaxf(mx0, fmaxf(s[nt][0], s[nt][1]));
                mx1 = fmaxf(mx1, fmaxf(s[nt][2], s[nt][3]));
            }
        } else {
#pragma unroll
            for (int nt = 0; nt < 8; nt++) {
                s[nt][0] *= scale; s[nt][1] *= scale;
                s[nt][2] *= scale; s[nt][3] *= scale;
                mx0 = fmaxf(mx0, fmaxf(s[nt][0], s[nt][1]));
                mx1 = fmaxf(mx1, fmaxf(s[nt][2], s[nt][3]));
            }
        }
#pragma unroll
        for (int off = 1; off < 4; off <<= 1) {
            mx0 = fmaxf(mx0, __shfl_xor_sync(0xffffffffu, mx0, off));
            mx1 = fmaxf(mx1, __shfl_xor_sync(0xffffffffu, mx1, off));
        }
        float mn0 = fmaxf(m0r, mx0), mn1 = fmaxf(m1r, mx1);
        float cr0 = __expf(m0r - mn0), cr1 = __expf(m1r - mn1);
        float sum0 = 0.f, sum1 = 0.f;
        if (it == nch - 1) {
#pragma unroll
            for (int nt = 0; nt < 8; nt++) {
                float p0 = (s[nt][0] > -5e29f) ? __expf(s[nt][0] - mn0) : 0.f;
                float p1 = (s[nt][1] > -5e29f) ? __expf(s[nt][1] - mn0) : 0.f;
                float p2 = (s[nt][2] > -5e29f) ? __expf(s[nt][2] - mn1) : 0.f;
                float p3 = (s[nt][3] > -5e29f) ? __expf(s[nt][3] - mn1) : 0.f;
                s[nt][0] = p0; s[nt][1] = p1; s[nt][2] = p2; s[nt][3] = p3;
                sum0 += p0 + p1;
                sum1 += p2 + p3;
            }
        } else {
#pragma unroll
            for (int nt = 0; nt < 8; nt++) {
                float p0 = __expf(s[nt][0] - mn0);
                float p1 = __expf(s[nt][1] - mn0);
                float p2 = __expf(s[nt][2] - mn1);
                float p3 = __expf(s[nt][3] - mn1);
                s[nt][0] = p0; s[nt][1] = p1; s[nt][2] = p2; s[nt][3] = p3;
                sum0 += p0 + p1;
                sum1 += p2 + p3;
            }
        }
#pragma unroll
        for (int off = 1; off < 4; off <<= 1) {
            sum0 += __shfl_xor_sync(0xffffffffu, sum0, off);
            sum1 += __shfl_xor_sync(0xffffffffu, sum1, off);
        }
        l0r = l0r * cr0 + sum0;
        l1r = l1r * cr1 + sum1;
        m0r = mn0; m1r = mn1;
#pragma unroll
        for (int nt = 0; nt < 8; nt++) {
            acc[nt][0] *= cr0; acc[nt][1] *= cr0;
            acc[nt][2] *= cr1; acc[nt][3] *= cr1;
        }

        // P fragments (single-rounded fp16)
        uint32_t pah[4][4];
#pragma unroll
        for (int c = 0; c < 4; c++) {
            pah[c][0] = pack2h(s[2 * c][0],     s[2 * c][1]);
            pah[c][1] = pack2h(s[2 * c][2],     s[2 * c][3]);
            pah[c][2] = pack2h(s[2 * c + 1][0], s[2 * c + 1][1]);
            pah[c][3] = pack2h(s[2 * c + 1][2], s[2 * c + 1][3]);
        }

#pragma unroll
        for (int c = 0; c < 4; c++) {
#pragma unroll
            for (int np = 0; np < 4; np++) {
                uint32_t vbh[4];
                uint32_t ro = (c * 16 + tr) * 144 + np * 32 + tc * 16;
                ldsm_x4_t(vbh, st + AT_VH + ro);
                mma_f16(acc[np * 2 + 0], pah[c], vbh[0], vbh[1]);
                mma_f16(acc[np * 2 + 1], pah[c], vbh[2], vbh[3]);
            }
        }
        __syncthreads();   // required: next prefetch rewrites this stage
        if (it + 2 < nch) load_stage(stg, (it + 2) * 64);
    }

    // ---- epilogue: ctx as fp16 (hi only) ----
    float inv0 = (l0r > 0.f) ? (1.f / l0r) : 0.f;
    float inv1 = (l1r > 0.f) ? (1.f / l1r) : 0.f;
    int r0 = q0 + wid * 16 + (lane >> 2);
#pragma unroll
    for (int nt = 0; nt < 8; nt++) {
        int c = h * DK + nt * 8 + (lane & 3) * 2;
        size_t o0 = (size_t)(b * S + r0) * D + c;
        size_t o1 = (size_t)(b * S + r0 + 8) * D + c;
        *(uint32_t*)&Ch[o0] = pack2h(acc[nt][0] * inv0, acc[nt][1] * inv0);
        *(uint32_t*)&Ch[o1] = pack2h(acc[nt][2] * inv1, acc[nt][3] * inv1);
    }
}

// ---------------- launch ----------------
extern "C" void kernel_launch(void* const* d_in, const int* in_sizes, int n_in,
                              void* d_out, int out_size)
{
    const float* query = (const float*)d_in[0];
    const float* key   = (const float*)d_in[1];
    const float* value = (const float*)d_in[2];
    const int*   mask  = (const int*)d_in[3];
    const float* Wq = (const float*)d_in[4];
    const float* bq = (const float*)d_in[5];
    const float* Wk = (const float*)d_in[6];
    const float* bk = (const float*)d_in[7];
    const float* Wv = (const float*)d_in[8];
    const float* bv = (const float*)d_in[9];
    const float* Wo = (const float*)d_in[10];
    const float* bo = (const float*)d_in[11];
    float* out = (float*)d_out;

    __half *ah, *al, *wh;
    int *gidx, *cnt;
    cudaGetSymbolAddress((void**)&ah, g_Ah);
    cudaGetSymbolAddress((void**)&al, g_Al);
    cudaGetSymbolAddress((void**)&wh, g_Wh);
    cudaGetSymbolAddress((void**)&gidx, g_gidx);
    cudaGetSymbolAddress((void**)&cnt, g_cnt);

    static int attr_set = 0;
    if (!attr_set) {
        cudaFuncSetAttribute(qkv_gemm_kernel,
                             cudaFuncAttributeMaxDynamicSharedMemorySize, GEMM_SMEM);
        cudaFuncSetAttribute(oproj_gemm_kernel,
                             cudaFuncAttributeMaxDynamicSharedMemorySize, GEMM_SMEM);
        cudaFuncSetAttribute(attn_mma_kernel,
                             cudaFuncAttributeMaxDynamicSharedMemorySize, ATTN_SMEM);
        attr_set = 1;
    }

    const int n4_act = SZA / 4;

    // 0: mask compaction
    compact_mask_kernel<<<B, 256>>>(mask, gidx, cnt);

    // 1: split q input -> slot 0
    split_q_kernel<<<(n4_act + 255) / 256, 256>>>(query, ah, al, n4_act);

    // 2: gather+split compact k/v inputs -> slots 1, 2
    dim3 g_grid(S, B);
    gather_split_kv_kernel<<<g_grid, 128>>>(
        key, value, gidx, cnt,
        ah + (size_t)1 * SZA, al + (size_t)1 * SZA,
        ah + (size_t)2 * SZA, al + (size_t)2 * SZA);

    // 3: convert weights fp32 -> fp16 (layout preserved; no transpose)
    FPtr4 win; win.p[0] = Wq; win.p[1] = Wk; win.p[2] = Wv; win.p[3] = Wo;
    dim3 cw_grid((D * D / 4 + 255) / 256, 4);
    convert_w4_kernel<<<cw_grid, 256>>>(win, wh);

    // 4: batched projections (K/V early-exit past compact rows)
    QKVBias qb; qb.p[0] = bq; qb.p[1] = bk; qb.p[2] = bv;
    dim3 qkv_grid(GN / 64, M_ROWS / 128, 3);
    qkv_gemm_kernel<<<qkv_grid, 256, GEMM_SMEM>>>(
        ah, al, wh, qb, cnt, ah + (size_t)3 * SZA, al + (size_t)3 * SZA);

    // 5: attention -> ctx slot 6 (hi only)
    dim3 attn_grid(S / 128, H, B);
    attn_mma_kernel<<<attn_grid, 256, ATTN_SMEM>>>(
        ah + (size_t)3 * SZA, al + (size_t)3 * SZA,
        ah + (size_t)4 * SZA,
        ah + (size_t)5 * SZA,
        cnt,
        ah + (size_t)6 * SZA);

    // 6: output projection (single-pass fp16, fp32 out)
    dim3 gemm_grid(GN / 64, M_ROWS / 128);
    oproj_gemm_kernel<<<gemm_grid, 256, GEMM_SMEM>>>(
        ah + (size_t)6 * SZA, wh + (size_t)3 * D * D, bo, out);
}

// round 14
// speedup vs baseline: 10.9944x; 1.3676x over previous
#include <cuda_runtime.h>
#include <cuda_fp16.h>
#include <math.h>
#include <stdint.h>

// Problem constants
#define B  2
#define S  2048
#define D  1024
#define H  16
#define DK 64
#define M_ROWS (B * S)   // 4096
#define GK 1024
#define GN 1024
#define SZA (M_ROWS * D)

// ---------------- scratch (device globals: allocation-free) ----------------
// slots: 0 = q input fp16; 1,2 = gathered compact k,v inputs;
//        3..5 = projected q, k(compact), v(compact); 6 = ctx
__device__ __half g_Ah[7][SZA];
__device__ __half g_Wh[4][D * D];   // weights fp16, layout [k][n]
__device__ int g_gidx[B * S];
__device__ int g_cnt[B];

struct FPtr5 { const float* p[5]; };

__device__ __forceinline__ uint32_t smem_u32(const void* p) {
    uint32_t a;
    asm("{ .reg .u64 t; cvta.to.shared.u64 t, %1; cvt.u32.u64 %0, t; }"
        : "=r"(a) : "l"(p));
    return a;
}
__device__ __forceinline__ void ldsm_x4(uint32_t (&r)[4], uint32_t addr) {
    asm volatile("ldmatrix.sync.aligned.m8n8.x4.shared.b16 {%0,%1,%2,%3}, [%4];"
                 : "=r"(r[0]), "=r"(r[1]), "=r"(r[2]), "=r"(r[3]) : "r"(addr));
}
__device__ __forceinline__ void ldsm_x4_t(uint32_t (&r)[4], uint32_t addr) {
    asm volatile("ldmatrix.sync.aligned.m8n8.x4.trans.shared.b16 {%0,%1,%2,%3}, [%4];"
                 : "=r"(r[0]), "=r"(r[1]), "=r"(r[2]), "=r"(r[3]) : "r"(addr));
}
__device__ __forceinline__ void mma_f16(float (&d)[4],
    const uint32_t (&a)[4], uint32_t b0, uint32_t b1)
{
    asm volatile(
        "mma.sync.aligned.m16n8k16.row.col.f32.f16.f16.f32 "
        "{%0,%1,%2,%3}, {%4,%5,%6,%7}, {%8,%9}, {%0,%1,%2,%3};"
        : "+f"(d[0]), "+f"(d[1]), "+f"(d[2]), "+f"(d[3])
        : "r"(a[0]), "r"(a[1]), "r"(a[2]), "r"(a[3]), "r"(b0), "r"(b1));
}
__device__ __forceinline__ void cpa16(uint32_t sd, const void* gs) {
    asm volatile("cp.async.cg.shared.global [%0], [%1], 16;" :: "r"(sd), "l"(gs));
}
__device__ __forceinline__ uint32_t pack2h(float f0, float f1) {
    __half h0 = __float2half(f0), h1 = __float2half(f1);
    return (uint32_t)*(uint16_t*)&h0 | ((uint32_t)*(uint16_t*)&h1 << 16);
}

// ---------------- mask compaction: per-batch prefix scan ----------------
__global__ __launch_bounds__(256) void compact_mask_kernel(
    const int* __restrict__ mask, int* __restrict__ gidx, int* __restrict__ cnt)
{
    __shared__ int wsum[8];
    const int b = blockIdx.x;
    const int tid = threadIdx.x, lane = tid & 31, wid = tid >> 5;
    int keep[8], local = 0;
#pragma unroll
    for (int i = 0; i < 8; i++) {
        keep[i] = (mask[b * S + tid * 8 + i] == 0);
        local += keep[i];
    }
    int v = local;
#pragma unroll
    for (int off = 1; off < 32; off <<= 1) {
        int n = __shfl_up_sync(0xffffffffu, v, off);
        if (lane >= off) v += n;
    }
    int excl = v - local;
    if (lane == 31) wsum[wid] = v;
    __syncthreads();
    if (wid == 0 && lane < 8) {
        int w = wsum[lane];
        int wv = w;
#pragma unroll
        for (int off = 1; off < 8; off <<= 1) {
            int n = __shfl_up_sync(0xffu, wv, off);
            if (lane >= off) wv += n;
        }
        wsum[lane] = wv - w;
        if (lane == 7) cnt[b] = wv;
    }
    __syncthreads();
    int base = wsum[wid] + excl;
#pragma unroll
    for (int i = 0; i < 8; i++)
        if (keep[i]) gidx[b * S + base++] = tid * 8 + i;
}

// ---------------- batched convert fp32->fp16: q input + 4 weights --------
// grid (x, 5): z=0 -> q input (SZA), z=1..4 -> weights (D*D). 4 quads/thread.
__global__ __launch_bounds__(256) void convert5_kernel(
    FPtr5 X, __half* __restrict__ ah, __half* __restrict__ wh)
{
    const int z = blockIdx.y;
    const float* src = X.p[z];
    __half* dst = (z == 0) ? ah : wh + (size_t)(z - 1) * D * D;
    const int n4 = (z == 0) ? SZA / 4 : D * D / 4;
    int i = blockIdx.x * 1024 + threadIdx.x;
#pragma unroll
    for (int t = 0; t < 4; t++, i += 256) {
        if (i < n4) {
            float4 v = ((const float4*)src)[i];
            *(uint32_t*)&dst[i * 4 + 0] = pack2h(v.x, v.y);
            *(uint32_t*)&dst[i * 4 + 2] = pack2h(v.z, v.w);
        }
    }
}

// gather unmasked key/value input rows, convert fp16; zero-pad
__global__ __launch_bounds__(128) void gather_convert_kv_kernel(
    const float* __restrict__ keyIn, const float* __restrict__ valIn,
    const int* __restrict__ gidx, const int* __restrict__ cnt,
    __half* __restrict__ Kh, __half* __restrict__ Vh)
{
    const int b = blockIdx.y, pos = blockIdx.x, tid = threadIdx.x;
    const int c = cnt[b];
    const int cpad = (c + 63) & ~63;
    if (pos >= cpad) return;
    const size_t dst = (size_t)(b * S + pos) * D + tid * 8;
    if (pos < c) {
        const size_t src = (size_t)(b * S + gidx[b * S + pos]) * D + tid * 8;
        float4 k0 = *(const float4*)&keyIn[src];
        float4 k1 = *(const float4*)&keyIn[src + 4];
        float4 v0 = *(const float4*)&valIn[src];
        float4 v1 = *(const float4*)&valIn[src + 4];
        *(uint4*)&Kh[dst] = make_uint4(pack2h(k0.x, k0.y), pack2h(k0.z, k0.w),
                                       pack2h(k1.x, k1.y), pack2h(k1.z, k1.w));
        *(uint4*)&Vh[dst] = make_uint4(pack2h(v0.x, v0.y), pack2h(v0.z, v0.w),
                                       pack2h(v1.x, v1.y), pack2h(v1.z, v1.w));
    } else {
        uint4 z = make_uint4(0, 0, 0, 0);
        *(uint4*)&Kh[dst] = z;
        *(uint4*)&Vh[dst] = z;
    }
}

// ---------------- fp16 single-pass GEMM: B row-major via ldsm.trans ------
#define BK 32
#define NCH (GK / BK)
#define OFF_B  10240
#define STAGE_SB 14848           // 10240 (A) + 4608 (B: 32x144)
#define GEMM_SMEM (3 * STAGE_SB) // 44544

__device__ __forceinline__ void gemm_body(
    const __half* __restrict__ Ah,
    const __half* __restrict__ W,   // [GK][GN] fp16
    const float* __restrict__ bias, float* __restrict__ C,
    __half* __restrict__ Ch,
    char* smem)
{
    const uint32_t sbase = smem_u32(smem);
    const int tid = threadIdx.x;
    const int lane = tid & 31;
    const int wid = tid >> 5;
    const int warp_m = wid & 3;
    const int warp_n = wid >> 2;
    const int m0 = blockIdx.y * 128;
    const int n0 = blockIdx.x * 64;

    const __half* gAh = Ah + (size_t)m0 * GK;
    const int lrow = tid >> 2;
    const int lc   = tid & 3;
    const int browb = tid >> 3;
    const int bchb  = tid & 7;

    auto load_stage = [&](int stg, int k0) {
        uint32_t sb = sbase + stg * STAGE_SB;
#pragma unroll
        for (int j = 0; j < 2; j++) {
            int row = lrow + j * 64;
            cpa16(sb + row * 80 + lc * 16,
                  gAh + (size_t)row * GK + k0 + lc * 8);
        }
        cpa16(sb + OFF_B + browb * 144 + bchb * 16,
              W + (size_t)(k0 + browb) * GN + n0 + bchb * 8);
        asm volatile("cp.async.commit_group;");
    };

    float acc[2][4][4];
#pragma unroll
    for (int i = 0; i < 2; i++)
#pragma unroll
        for (int j = 0; j < 4; j++)
#pragma unroll
            for (int v = 0; v < 4; v++) acc[i][j][v] = 0.f;

    load_stage(0, 0);
    load_stage(1, BK);

    const int a_row = lane & 15;
    const int a_kc  = lane >> 4;
    const int tr    = lane & 15;
    const int tc    = lane >> 4;

    int stg = 0;
    for (int ch = 0; ch < NCH; ch++) {
        if (ch < NCH - 1) asm volatile("cp.async.wait_group 1;");
        else              asm volatile("cp.async.wait_group 0;");
        __syncthreads();
        if (ch + 2 < NCH) {
            int ns = stg + 2; if (ns >= 3) ns -= 3;
            load_stage(ns, (ch + 2) * BK);
        }
        const uint32_t st = sbase + stg * STAGE_SB;
#pragma unroll
        for (int kc = 0; kc < 2; kc++) {
            uint32_t a_h[2][4], b_t[2][4];
#pragma unroll
            for (int mt = 0; mt < 2; mt++) {
                uint32_t ro = (warp_m * 32 + mt * 16 + a_row) * 80
                            + (kc * 2 + a_kc) * 16;
                ldsm_x4(a_h[mt], st + ro);
            }
#pragma unroll
            for (int ng = 0; ng < 2; ng++) {
                uint32_t ro = (kc * 16 + tr) * 144
                            + warp_n * 64 + ng * 32 + tc * 16;
                ldsm_x4_t(b_t[ng], st + OFF_B + ro);
            }
#pragma unroll
            for (int mt = 0; mt < 2; mt++)
#pragma unroll
                for (int ng = 0; ng < 2; ng++) {
                    mma_f16(acc[mt][ng * 2 + 0], a_h[mt], b_t[ng][0], b_t[ng][1]);
                    mma_f16(acc[mt][ng * 2 + 1], a_h[mt], b_t[ng][2], b_t[ng][3]);
                }
        }
        if (++stg == 3) stg = 0;
    }

    const int grp = lane >> 2, tg = lane & 3;
#pragma unroll
    for (int mt = 0; mt < 2; mt++) {
        int r0 = m0 + warp_m * 32 + mt * 16 + grp;
#pragma unroll
        for (int nt = 0; nt < 4; nt++) {
            int c = n0 + warp_n * 32 + nt * 8 + tg * 2;
            float2 b2 = *(const float2*)&bias[c];
            float o00 = acc[mt][nt][0] + b2.x;
            float o01 = acc[mt][nt][1] + b2.y;
            float o10 = acc[mt][nt][2] + b2.x;
            float o11 = acc[mt][nt][3] + b2.y;
            if (C) {
                *(float2*)&C[(size_t)r0 * GN + c] = make_float2(o00, o01);
                *(float2*)&C[(size_t)(r0 + 8) * GN + c] = make_float2(o10, o11);
            } else {
                *(uint32_t*)&Ch[(size_t)r0 * GN + c] = pack2h(o00, o01);
                *(uint32_t*)&Ch[(size_t)(r0 + 8) * GN + c] = pack2h(o10, o11);
            }
        }
    }
}

struct QKVBias { const float* p[3]; };

__global__ __launch_bounds__(256, 3) void qkv_gemm_kernel(
    const __half* __restrict__ AhB, const __half* __restrict__ WhB,
    QKVBias bias, const int* __restrict__ cnt,
    __half* __restrict__ ChB)
{
    extern __shared__ char smem[];
    const int z = blockIdx.z;
    if (z > 0) {
        const int m0 = blockIdx.y * 128;
        const int b = m0 / S;
        const int cpad = (cnt[b] + 63) & ~63;
        if ((m0 % S) >= cpad) return;
    }
    gemm_body(AhB + (size_t)z * SZA, WhB + (size_t)z * D * D,
              bias.p[z], nullptr, ChB + (size_t)z * SZA, smem);
}

__global__ __launch_bounds__(256, 3) void oproj_gemm_kernel(
    const __half* __restrict__ Ah, const __half* __restrict__ Wh,
    const float* __restrict__ bias, float* __restrict__ C)
{
    extern __shared__ char smem[];
    gemm_body(Ah, Wh, bias, C, nullptr, smem);
}

// ---------------- Attention: fp16, single-pass QK + PV, 2-stage ----------
#define ASTG 18432
#define AT_VH 9216
#define ATTN_SMEM (2 * ASTG)   // 36864

__global__ __launch_bounds__(256, 2) void attn_mma_kernel(
    const __half* __restrict__ Qh,
    const __half* __restrict__ Kh, const __half* __restrict__ Vh,
    const int* __restrict__ cnt,
    __half* __restrict__ Ch)
{
    extern __shared__ char smem[];
    const uint32_t sb = smem_u32(smem);
    const int tid = threadIdx.x, lane = tid & 31, wid = tid >> 5;
    const int b = blockIdx.z, h = blockIdx.y, q0 = blockIdx.x * 128;
    const int cn = cnt[b];
    const int nch = (cn + 63) >> 6;

    // ---- stage Q tile into smem once, ldsm to fragments ----
#pragma unroll
    for (int t = 0; t < 4; t++) {
        int idx = tid + t * 256;          // 0..1023
        int row = idx >> 3, ch = idx & 7;
        const __half* src = Qh + (size_t)(b * S + q0 + row) * D + h * DK + ch * 8;
        *(uint4*)(smem + row * 144 + ch * 16) = *(const uint4*)src;
    }
    __syncthreads();
    uint32_t qfh[4][4];
    {
        int r = wid * 16 + (lane & 15);
        int hc = lane >> 4;
#pragma unroll
        for (int c = 0; c < 4; c++)
            ldsm_x4(qfh[c], sb + r * 144 + (c * 2 + hc) * 16);
    }
    __syncthreads();

    auto load_stage = [&](int stg, int kk) {
        uint32_t base = sb + stg * ASTG;
#pragma unroll
        for (int t = 0; t < 4; t++) {
            int idx = tid + t * 256;
            int tile = idx >> 9;
            int c = idx & 511;
            int row = c >> 3, ch = c & 7;
            const __half* g = (tile == 0 ? Kh : Vh)
                + (size_t)(b * S + kk + row) * D + h * DK + ch * 8;
            cpa16(base + tile * 9216 + row * 144 + ch * 16, g);
        }
        asm volatile("cp.async.commit_group;");
    };

    float acc[8][4];
#pragma unroll
    for (int j = 0; j < 8; j++)
#pragma unroll
        for (int v = 0; v < 4; v++) acc[j][v] = 0.f;
    float m0r = -1e30f, m1r = -1e30f, l0r = 0.f, l1r = 0.f;
    const float scale = 0.125f;

    if (nch >= 1) load_stage(0, 0);
    if (nch >= 2) load_stage(1, 64);

    const int bg    = lane >> 3;
    const int b_row = ((bg >> 1) * 8) + (lane & 7);
    const int b_kc  = bg & 1;
    const int tr    = lane & 15;
    const int tc    = lane >> 4;
    const int jlane = (lane & 3) * 2;

    for (int it = 0; it < nch; it++) {
        const int stg = it & 1;
        if (it < nch - 1) asm volatile("cp.async.wait_group 1;");
        else              asm volatile("cp.async.wait_group 0;");
        __syncthreads();

        const uint32_t st = sb + stg * ASTG;

        float s[8][4];
#pragma unroll
        for (int j = 0; j < 8; j++)
#pragma unroll
            for (int v = 0; v < 4; v++) s[j][v] = 0.f;
#pragma unroll
        for (int c = 0; c < 4; c++) {
#pragma unroll
            for (int np = 0; np < 4; np++) {
                uint32_t kbh[4];
                uint32_t ro = (np * 16 + b_row) * 144 + (c * 2 + b_kc) * 16;
                ldsm_x4(kbh, st + ro);
                mma_f16(s[np * 2 + 0], qfh[c], kbh[0], kbh[1]);
                mma_f16(s[np * 2 + 1], qfh[c], kbh[2], kbh[3]);
            }
        }

        // ---- online softmax; masking only on the final (tail) chunk ----
        float mx0 = -1e30f, mx1 = -1e30f;
        if (it == nch - 1) {
            const int jbase = it * 64 + jlane;
#pragma unroll
            for (int nt = 0; nt < 8; nt++) {
                int j0 = jbase + nt * 8;
                bool k0m = (j0 >= cn), k1m = (j0 + 1 >= cn);
                s[nt][0] = k0m ? -1e30f : s[nt][0] * scale;
                s[nt][1] = k1m ? -1e30f : s[nt][1] * scale;
                s[nt][2] = k0m ? -1e30f : s[nt][2] * scale;
                s[nt][3] = k1m ? -1e30f : s[nt][3] * scale;
                mx0 = fmaxf(mx0, fmaxf(s[nt][0], s[nt][1]));
                mx1 = fmaxf(mx1, fmaxf(s[nt][2], s[nt][3]));
            }
        } else {
#pragma unroll
            for (int nt = 0; nt < 8; nt++) {
                s[nt][0] *= scale; s[nt][1] *= scale;
                s[nt][2] *= scale; s[nt][3] *= scale;
                mx0 = fmaxf(mx0, fmaxf(s[nt][0], s[nt][1]));
                mx1 = fmaxf(mx1, fmaxf(s[nt][2], s[nt][3]));
            }
        }
#pragma unroll
        for (int off = 1; off < 4; off <<= 1) {
            mx0 = fmaxf(mx0, __shfl_xor_sync(0xffffffffu, mx0, off));
            mx1 = fmaxf(mx1, __shfl_xor_sync(0xffffffffu, mx1, off));
        }
        float mn0 = fmaxf(m0r, mx0), mn1 = fmaxf(m1r, mx1);
        float cr0 = __expf(m0r - mn0), cr1 = __expf(m1r - mn1);
        float sum0 = 0.f, sum1 = 0.f;
        if (it == nch - 1) {
#pragma unroll
            for (int nt = 0; nt < 8; nt++) {
                float p0 = (s[nt][0] > -5e29f) ? __expf(s[nt][0] - mn0) : 0.f;
                float p1 = (s[nt][1] > -5e29f) ? __expf(s[nt][1] - mn0) : 0.f;
                float p2 = (s[nt][2] > -5e29f) ? __expf(s[nt][2] - mn1) : 0.f;
                float p3 = (s[nt][3] > -5e29f) ? __expf(s[nt][3] - mn1) : 0.f;
                s[nt][0] = p0; s[nt][1] = p1; s[nt][2] = p2; s[nt][3] = p3;
                sum0 += p0 + p1;
                sum1 += p2 + p3;
            }
        } else {
#pragma unroll
            for (int nt = 0; nt < 8; nt++) {
                float p0 = __expf(s[nt][0] - mn0);
                float p1 = __expf(s[nt][1] - mn0);
                float p2 = __expf(s[nt][2] - mn1);
                float p3 = __expf(s[nt][3] - mn1);
                s[nt][0] = p0; s[nt][1] = p1; s[nt][2] = p2; s[nt][3] = p3;
                sum0 += p0 + p1;
                sum1 += p2 + p3;
            }
        }
#pragma unroll
        for (int off = 1; off < 4; off <<= 1) {
            sum0 += __shfl_xor_sync(0xffffffffu, sum0, off);
            sum1 += __shfl_xor_sync(0xffffffffu, sum1, off);
        }
        l0r = l0r * cr0 + sum0;
        l1r = l1r * cr1 + sum1;
        m0r = mn0; m1r = mn1;
#pragma unroll
        for (int nt = 0; nt < 8; nt++) {
            acc[nt][0] *= cr0; acc[nt][1] *= cr0;
            acc[nt][2] *= cr1; acc[nt][3] *= cr1;
        }

        uint32_t pah[4][4];
#pragma unroll
        for (int c = 0; c < 4; c++) {
            pah[c][0] = pack2h(s[2 * c][0],     s[2 * c][1]);
            pah[c][1] = pack2h(s[2 * c][2],     s[2 * c][3]);
            pah[c][2] = pack2h(s[2 * c + 1][0], s[2 * c + 1][1]);
            pah[c][3] = pack2h(s[2 * c + 1][2], s[2 * c + 1][3]);
        }

#pragma unroll
        for (int c = 0; c < 4; c++) {
#pragma unroll
            for (int np = 0; np < 4; np++) {
                uint32_t vbh[4];
                uint32_t ro = (c * 16 + tr) * 144 + np * 32 + tc * 16;
                ldsm_x4_t(vbh, st + AT_VH + ro);
                mma_f16(acc[np * 2 + 0], pah[c], vbh[0], vbh[1]);
                mma_f16(acc[np * 2 + 1], pah[c], vbh[2], vbh[3]);
            }
        }
        __syncthreads();   // required: next prefetch rewrites this stage
        if (it + 2 < nch) load_stage(stg, (it + 2) * 64);
    }

    // ---- epilogue: ctx as fp16 ----
    float inv0 = (l0r > 0.f) ? (1.f / l0r) : 0.f;
    float inv1 = (l1r > 0.f) ? (1.f / l1r) : 0.f;
    int r0 = q0 + wid * 16 + (lane >> 2);
#pragma unroll
    for (int nt = 0; nt < 8; nt++) {
        int c = h * DK + nt * 8 + (lane & 3) * 2;
        size_t o0 = (size_t)(b * S + r0) * D + c;
        size_t o1 = (size_t)(b * S + r0 + 8) * D + c;
        *(uint32_t*)&Ch[o0] = pack2h(acc[nt][0] * inv0, acc[nt][1] * inv0);
        *(uint32_t*)&Ch[o1] = pack2h(acc[nt][2] * inv1, acc[nt][3] * inv1);
    }
}

// ---------------- launch ----------------
extern "C" void kernel_launch(void* const* d_in, const int* in_sizes, int n_in,
                              void* d_out, int out_size)
{
    const float* query = (const float*)d_in[0];
    const float* key   = (const float*)d_in[1];
    const float* value = (const float*)d_in[2];
    const int*   mask  = (const int*)d_in[3];
    const float* Wq = (const float*)d_in[4];
    const float* bq = (const float*)d_in[5];
    const float* Wk = (const float*)d_in[6];
    const float* bk = (const float*)d_in[7];
    const float* Wv = (const float*)d_in[8];
    const float* bv = (const float*)d_in[9];
    const float* Wo = (const float*)d_in[10];
    const float* bo = (const float*)d_in[11];
    float* out = (float*)d_out;

    __half *ah, *wh;
    int *gidx, *cnt;
    cudaGetSymbolAddress((void**)&ah, g_Ah);
    cudaGetSymbolAddress((void**)&wh, g_Wh);
    cudaGetSymbolAddress((void**)&gidx, g_gidx);
    cudaGetSymbolAddress((void**)&cnt, g_cnt);

    static int attr_set = 0;
    if (!attr_set) {
        cudaFuncSetAttribute(qkv_gemm_kernel,
                             cudaFuncAttributeMaxDynamicSharedMemorySize, GEMM_SMEM);
        cudaFuncSetAttribute(oproj_gemm_kernel,
                             cudaFuncAttributeMaxDynamicSharedMemorySize, GEMM_SMEM);
        cudaFuncSetAttribute(attn_mma_kernel,
                             cudaFuncAttributeMaxDynamicSharedMemorySize, ATTN_SMEM);
        attr_set = 1;
    }

    // 0: mask compaction
    compact_mask_kernel<<<B, 256>>>(mask, gidx, cnt);

    // 1: convert q input + 4 weights to fp16 in one launch
    FPtr5 cin;
    cin.p[0] = query; cin.p[1] = Wq; cin.p[2] = Wk; cin.p[3] = Wv; cin.p[4] = Wo;
    dim3 cv_grid((SZA / 4 + 1023) / 1024, 5);
    convert5_kernel<<<cv_grid, 256>>>(cin, ah, wh);

    // 2: gather+convert compact k/v inputs -> slots 1, 2
    dim3 g_grid(S, B);
    gather_convert_kv_kernel<<<g_grid, 128>>>(
        key, value, gidx, cnt,
        ah + (size_t)1 * SZA, ah + (size_t)2 * SZA);

    // 3: batched projections (single-pass; K/V early-exit past compact rows)
    QKVBias qb; qb.p[0] = bq; qb.p[1] = bk; qb.p[2] = bv;
    dim3 qkv_grid(GN / 64, M_ROWS / 128, 3);
    qkv_gemm_kernel<<<qkv_grid, 256, GEMM_SMEM>>>(
        ah, wh, qb, cnt, ah + (size_t)3 * SZA);

    // 4: attention -> ctx slot 6
    dim3 attn_grid(S / 128, H, B);
    attn_mma_kernel<<<attn_grid, 256, ATTN_SMEM>>>(
        ah + (size_t)3 * SZA,
        ah + (size_t)4 * SZA,
        ah + (size_t)5 * SZA,
        cnt,
        ah + (size_t)6 * SZA);

    // 5: output projection (fp32 out)
    dim3 gemm_grid(GN / 64, M_ROWS / 128);
    oproj_gemm_kernel<<<gemm_grid, 256, GEMM_SMEM>>>(
        ah + (size_t)6 * SZA, wh + (size_t)3 * D * D, bo, out);
}

// round 15
// speedup vs baseline: 11.4550x; 1.0419x over previous
#include <cuda_runtime.h>
#include <cuda_fp16.h>
#include <math.h>
#include <stdint.h>

// Problem constants
#define B  2
#define S  2048
#define D  1024
#define H  16
#define DK 64
#define M_ROWS (B * S)   // 4096
#define GK 1024
#define GN 1024
#define SZA (M_ROWS * D)

// ---------------- scratch (device globals: allocation-free) ----------------
// slots: 0 = q input fp16; 1,2 = gathered compact k,v inputs;
//        3..5 = projected q, k(compact), v(compact); 6 = ctx
__device__ __half g_Ah[7][SZA];
__device__ __half g_Wh[4][D * D];   // weights fp16, layout [k][n]
__device__ int g_gidx[B * S];
__device__ int g_cnt[B];

struct FPtr5 { const float* p[5]; };

__device__ __forceinline__ uint32_t smem_u32(const void* p) {
    uint32_t a;
    asm("{ .reg .u64 t; cvta.to.shared.u64 t, %1; cvt.u32.u64 %0, t; }"
        : "=r"(a) : "l"(p));
    return a;
}
__device__ __forceinline__ void ldsm_x4(uint32_t (&r)[4], uint32_t addr) {
    asm volatile("ldmatrix.sync.aligned.m8n8.x4.shared.b16 {%0,%1,%2,%3}, [%4];"
                 : "=r"(r[0]), "=r"(r[1]), "=r"(r[2]), "=r"(r[3]) : "r"(addr));
}
__device__ __forceinline__ void ldsm_x4_t(uint32_t (&r)[4], uint32_t addr) {
    asm volatile("ldmatrix.sync.aligned.m8n8.x4.trans.shared.b16 {%0,%1,%2,%3}, [%4];"
                 : "=r"(r[0]), "=r"(r[1]), "=r"(r[2]), "=r"(r[3]) : "r"(addr));
}
__device__ __forceinline__ void mma_f16(float (&d)[4],
    const uint32_t (&a)[4], uint32_t b0, uint32_t b1)
{
    asm volatile(
        "mma.sync.aligned.m16n8k16.row.col.f32.f16.f16.f32 "
        "{%0,%1,%2,%3}, {%4,%5,%6,%7}, {%8,%9}, {%0,%1,%2,%3};"
        : "+f"(d[0]), "+f"(d[1]), "+f"(d[2]), "+f"(d[3])
        : "r"(a[0]), "r"(a[1]), "r"(a[2]), "r"(a[3]), "r"(b0), "r"(b1));
}
__device__ __forceinline__ void cpa16(uint32_t sd, const void* gs) {
    asm volatile("cp.async.cg.shared.global [%0], [%1], 16;" :: "r"(sd), "l"(gs));
}
__device__ __forceinline__ uint32_t pack2h(float f0, float f1) {
    __half h0 = __float2half(f0), h1 = __float2half(f1);
    return (uint32_t)*(uint16_t*)&h0 | ((uint32_t)*(uint16_t*)&h1 << 16);
}

// ---------------- mask compaction: per-batch prefix scan ----------------
__global__ __launch_bounds__(256) void compact_mask_kernel(
    const int* __restrict__ mask, int* __restrict__ gidx, int* __restrict__ cnt)
{
    __shared__ int wsum[8];
    const int b = blockIdx.x;
    const int tid = threadIdx.x, lane = tid & 31, wid = tid >> 5;
    int keep[8], local = 0;
#pragma unroll
    for (int i = 0; i < 8; i++) {
        keep[i] = (mask[b * S + tid * 8 + i] == 0);
        local += keep[i];
    }
    int v = local;
#pragma unroll
    for (int off = 1; off < 32; off <<= 1) {
        int n = __shfl_up_sync(0xffffffffu, v, off);
        if (lane >= off) v += n;
    }
    int excl = v - local;
    if (lane == 31) wsum[wid] = v;
    __syncthreads();
    if (wid == 0 && lane < 8) {
        int w = wsum[lane];
        int wv = w;
#pragma unroll
        for (int off = 1; off < 8; off <<= 1) {
            int n = __shfl_up_sync(0xffu, wv, off);
            if (lane >= off) wv += n;
        }
        wsum[lane] = wv - w;
        if (lane == 7) cnt[b] = wv;
    }
    __syncthreads();
    int base = wsum[wid] + excl;
#pragma unroll
    for (int i = 0; i < 8; i++)
        if (keep[i]) gidx[b * S + base++] = tid * 8 + i;
}

// ---------------- batched convert fp32->fp16: q input + 4 weights --------
__global__ __launch_bounds__(256) void convert5_kernel(
    FPtr5 X, __half* __restrict__ ah, __half* __restrict__ wh)
{
    const int z = blockIdx.y;
    const float* src = X.p[z];
    __half* dst = (z == 0) ? ah : wh + (size_t)(z - 1) * D * D;
    const int n4 = (z == 0) ? SZA / 4 : D * D / 4;
    int i = blockIdx.x * 1024 + threadIdx.x;
#pragma unroll
    for (int t = 0; t < 4; t++, i += 256) {
        if (i < n4) {
            float4 v = ((const float4*)src)[i];
            *(uint32_t*)&dst[i * 4 + 0] = pack2h(v.x, v.y);
            *(uint32_t*)&dst[i * 4 + 2] = pack2h(v.z, v.w);
        }
    }
}

// gather unmasked key/value input rows, convert fp16; zero-pad
__global__ __launch_bounds__(128) void gather_convert_kv_kernel(
    const float* __restrict__ keyIn, const float* __restrict__ valIn,
    const int* __restrict__ gidx, const int* __restrict__ cnt,
    __half* __restrict__ Kh, __half* __restrict__ Vh)
{
    const int b = blockIdx.y, pos = blockIdx.x, tid = threadIdx.x;
    const int c = cnt[b];
    const int cpad = (c + 63) & ~63;
    if (pos >= cpad) return;
    const size_t dst = (size_t)(b * S + pos) * D + tid * 8;
    if (pos < c) {
        const size_t src = (size_t)(b * S + gidx[b * S + pos]) * D + tid * 8;
        float4 k0 = *(const float4*)&keyIn[src];
        float4 k1 = *(const float4*)&keyIn[src + 4];
        float4 v0 = *(const float4*)&valIn[src];
        float4 v1 = *(const float4*)&valIn[src + 4];
        *(uint4*)&Kh[dst] = make_uint4(pack2h(k0.x, k0.y), pack2h(k0.z, k0.w),
                                       pack2h(k1.x, k1.y), pack2h(k1.z, k1.w));
        *(uint4*)&Vh[dst] = make_uint4(pack2h(v0.x, v0.y), pack2h(v0.z, v0.w),
                                       pack2h(v1.x, v1.y), pack2h(v1.z, v1.w));
    } else {
        uint4 z = make_uint4(0, 0, 0, 0);
        *(uint4*)&Kh[dst] = z;
        *(uint4*)&Vh[dst] = z;
    }
}

// ---------------- fp16 single-pass GEMM: CTA tile 128x128 ----------------
// 8 warps (4m x 2n), warp tile 32x64. B row-major [k][n] via ldsm.trans.
#define BK 32
#define NCH (GK / BK)
#define OFF_B  10240
#define BSTRIDE 272              // 256B data + 16B pad per B k-row
#define STAGE_SB 18944           // 10240 (A) + 8704 (B: 32x272)
#define GEMM_SMEM (3 * STAGE_SB) // 56832

__device__ __forceinline__ void gemm_body(
    const __half* __restrict__ Ah,
    const __half* __restrict__ W,   // [GK][GN] fp16
    const float* __restrict__ bias, float* __restrict__ C,
    __half* __restrict__ Ch,
    char* smem)
{
    const uint32_t sbase = smem_u32(smem);
    const int tid = threadIdx.x;
    const int lane = tid & 31;
    const int wid = tid >> 5;
    const int warp_m = wid & 3;      // 4 x 32 rows
    const int warp_n = wid >> 2;     // 2 x 64 cols
    const int m0 = blockIdx.y * 128;
    const int n0 = blockIdx.x * 128;

    const __half* gAh = Ah + (size_t)m0 * GK;
    const int lrow = tid >> 2;       // A row loader
    const int lc   = tid & 3;
    const int brow = tid >> 4;       // B row 0..15 (x2 iterations)
    const int bch  = tid & 15;       // B 16B chunk 0..15

    auto load_stage = [&](int stg, int k0) {
        uint32_t sb = sbase + stg * STAGE_SB;
#pragma unroll
        for (int j = 0; j < 2; j++) {
            int row = lrow + j * 64;
            cpa16(sb + row * 80 + lc * 16,
                  gAh + (size_t)row * GK + k0 + lc * 8);
        }
#pragma unroll
        for (int j = 0; j < 2; j++) {
            int row = brow + j * 16;
            cpa16(sb + OFF_B + row * BSTRIDE + bch * 16,
                  W + (size_t)(k0 + row) * GN + n0 + bch * 8);
        }
        asm volatile("cp.async.commit_group;");
    };

    float acc[2][8][4];
#pragma unroll
    for (int i = 0; i < 2; i++)
#pragma unroll
        for (int j = 0; j < 8; j++)
#pragma unroll
            for (int v = 0; v < 4; v++) acc[i][j][v] = 0.f;

    load_stage(0, 0);
    load_stage(1, BK);

    const int a_row = lane & 15;
    const int a_kc  = lane >> 4;
    const int tr    = lane & 15;
    const int tc    = lane >> 4;

    int stg = 0;
    for (int ch = 0; ch < NCH; ch++) {
        if (ch < NCH - 1) asm volatile("cp.async.wait_group 1;");
        else              asm volatile("cp.async.wait_group 0;");
        __syncthreads();
        if (ch + 2 < NCH) {
            int ns = stg + 2; if (ns >= 3) ns -= 3;
            load_stage(ns, (ch + 2) * BK);
        }
        const uint32_t st = sbase + stg * STAGE_SB;
#pragma unroll
        for (int kc = 0; kc < 2; kc++) {
            uint32_t a_h[2][4], b_t[4][4];
#pragma unroll
            for (int mt = 0; mt < 2; mt++) {
                uint32_t ro = (warp_m * 32 + mt * 16 + a_row) * 80
                            + (kc * 2 + a_kc) * 16;
                ldsm_x4(a_h[mt], st + ro);
            }
#pragma unroll
            for (int ng = 0; ng < 4; ng++) {
                uint32_t ro = (kc * 16 + tr) * BSTRIDE
                            + warp_n * 128 + ng * 32 + tc * 16;
                ldsm_x4_t(b_t[ng], st + OFF_B + ro);
            }
#pragma unroll
            for (int mt = 0; mt < 2; mt++)
#pragma unroll
                for (int ng = 0; ng < 4; ng++) {
                    mma_f16(acc[mt][ng * 2 + 0], a_h[mt], b_t[ng][0], b_t[ng][1]);
                    mma_f16(acc[mt][ng * 2 + 1], a_h[mt], b_t[ng][2], b_t[ng][3]);
                }
        }
        if (++stg == 3) stg = 0;
    }

    const int grp = lane >> 2, tg = lane & 3;
#pragma unroll
    for (int mt = 0; mt < 2; mt++) {
        int r0 = m0 + warp_m * 32 + mt * 16 + grp;
#pragma unroll
        for (int nt = 0; nt < 8; nt++) {
            int c = n0 + warp_n * 64 + nt * 8 + tg * 2;
            float2 b2 = *(const float2*)&bias[c];
            float o00 = acc[mt][nt][0] + b2.x;
            float o01 = acc[mt][nt][1] + b2.y;
            float o10 = acc[mt][nt][2] + b2.x;
            float o11 = acc[mt][nt][3] + b2.y;
            if (C) {
                *(float2*)&C[(size_t)r0 * GN + c] = make_float2(o00, o01);
                *(float2*)&C[(size_t)(r0 + 8) * GN + c] = make_float2(o10, o11);
            } else {
                *(uint32_t*)&Ch[(size_t)r0 * GN + c] = pack2h(o00, o01);
                *(uint32_t*)&Ch[(size_t)(r0 + 8) * GN + c] = pack2h(o10, o11);
            }
        }
    }
}

struct QKVBias { const float* p[3]; };

__global__ __launch_bounds__(256, 2) void qkv_gemm_kernel(
    const __half* __restrict__ AhB, const __half* __restrict__ WhB,
    QKVBias bias, const int* __restrict__ cnt,
    __half* __restrict__ ChB)
{
    extern __shared__ char smem[];
    const int z = blockIdx.z;
    if (z > 0) {
        const int m0 = blockIdx.y * 128;
        const int b = m0 / S;
        const int cpad = (cnt[b] + 63) & ~63;
        if ((m0 % S) >= cpad) return;
    }
    gemm_body(AhB + (size_t)z * SZA, WhB + (size_t)z * D * D,
              bias.p[z], nullptr, ChB + (size_t)z * SZA, smem);
}

__global__ __launch_bounds__(256, 2) void oproj_gemm_kernel(
    const __half* __restrict__ Ah, const __half* __restrict__ Wh,
    const float* __restrict__ bias, float* __restrict__ C)
{
    extern __shared__ char smem[];
    gemm_body(Ah, Wh, bias, C, nullptr, smem);
}

// ---------------- Attention: fp16, single-pass QK + PV, 2-stage ----------
#define ASTG 18432
#define AT_VH 9216
#define ATTN_SMEM (2 * ASTG)   // 36864

__global__ __launch_bounds__(256, 2) void attn_mma_kernel(
    const __half* __restrict__ Qh,
    const __half* __restrict__ Kh, const __half* __restrict__ Vh,
    const int* __restrict__ cnt,
    __half* __restrict__ Ch)
{
    extern __shared__ char smem[];
    const uint32_t sb = smem_u32(smem);
    const int tid = threadIdx.x, lane = tid & 31, wid = tid >> 5;
    const int b = blockIdx.z, h = blockIdx.y, q0 = blockIdx.x * 128;
    const int cn = cnt[b];
    const int nch = (cn + 63) >> 6;

    // ---- stage Q tile into smem once, ldsm to fragments ----
#pragma unroll
    for (int t = 0; t < 4; t++) {
        int idx = tid + t * 256;
        int row = idx >> 3, ch = idx & 7;
        const __half* src = Qh + (size_t)(b * S + q0 + row) * D + h * DK + ch * 8;
        *(uint4*)(smem + row * 144 + ch * 16) = *(const uint4*)src;
    }
    __syncthreads();
    uint32_t qfh[4][4];
    {
        int r = wid * 16 + (lane & 15);
        int hc = lane >> 4;
#pragma unroll
        for (int c = 0; c < 4; c++)
            ldsm_x4(qfh[c], sb + r * 144 + (c * 2 + hc) * 16);
    }
    __syncthreads();

    auto load_stage = [&](int stg, int kk) {
        uint32_t base = sb + stg * ASTG;
#pragma unroll
        for (int t = 0; t < 4; t++) {
            int idx = tid + t * 256;
            int tile = idx >> 9;
            int c = idx & 511;
            int row = c >> 3, ch = c & 7;
            const __half* g = (tile == 0 ? Kh : Vh)
                + (size_t)(b * S + kk + row) * D + h * DK + ch * 8;
            cpa16(base + tile * 9216 + row * 144 + ch * 16, g);
        }
        asm volatile("cp.async.commit_group;");
    };

    float acc[8][4];
#pragma unroll
    for (int j = 0; j < 8; j++)
#pragma unroll
        for (int v = 0; v < 4; v++) acc[j][v] = 0.f;
    float m0r = -1e30f, m1r = -1e30f, l0r = 0.f, l1r = 0.f;
    const float scale = 0.125f;

    if (nch >= 1) load_stage(0, 0);
    if (nch >= 2) load_stage(1, 64);

    const int bg    = lane >> 3;
    const int b_row = ((bg >> 1) * 8) + (lane & 7);
    const int b_kc  = bg & 1;
    const int tr    = lane & 15;
    const int tc    = lane >> 4;
    const int jlane = (lane & 3) * 2;

    for (int it = 0; it < nch; it++) {
        const int stg = it & 1;
        if (it < nch - 1) asm volatile("cp.async.wait_group 1;");
        else              asm volatile("cp.async.wait_group 0;");
        __syncthreads();

        const uint32_t st = sb + stg * ASTG;

        float s[8][4];
#pragma unroll
        for (int j = 0; j < 8; j++)
#pragma unroll
            for (int v = 0; v < 4; v++) s[j][v] = 0.f;
#pragma unroll
        for (int c = 0; c < 4; c++) {
#pragma unroll
            for (int np = 0; np < 4; np++) {
                uint32_t kbh[4];
                uint32_t ro = (np * 16 + b_row) * 144 + (c * 2 + b_kc) * 16;
                ldsm_x4(kbh, st + ro);
                mma_f16(s[np * 2 + 0], qfh[c], kbh[0], kbh[1]);
                mma_f16(s[np * 2 + 1], qfh[c], kbh[2], kbh[3]);
            }
        }

        // ---- online softmax; masking only on the final (tail) chunk ----
        float mx0 = -1e30f, mx1 = -1e30f;
        if (it == nch - 1) {
            const int jbase = it * 64 + jlane;
#pragma unroll
            for (int nt = 0; nt < 8; nt++) {
                int j0 = jbase + nt * 8;
                bool k0m = (j0 >= cn), k1m = (j0 + 1 >= cn);
                s[nt][0] = k0m ? -1e30f : s[nt][0] * scale;
                s[nt][1] = k1m ? -1e30f : s[nt][1] * scale;
                s[nt][2] = k0m ? -1e30f : s[nt][2] * scale;
                s[nt][3] = k1m ? -1e30f : s[nt][3] * scale;
                mx0 = fmaxf(mx0, fmaxf(s[nt][0], s[nt][1]));
                mx1 = fmaxf(mx1, fmaxf(s[nt][2], s[nt][3]));
            }
        } else {
#pragma unroll
            for (int nt = 0; nt < 8; nt++) {
                s[nt][0] *= scale; s[nt][1] *= scale;
                s[nt][2] *= scale; s[nt][3] *= scale;
                mx0 = fmaxf(mx0, fmaxf(s[nt][0], s[nt][1]));
                mx1 = fmaxf(mx1, fmaxf(s[nt][2], s[nt][3]));
            }
        }
#pragma unroll
        for (int off = 1; off < 4; off <<= 1) {
            mx0 = fmaxf(mx0, __shfl_xor_sync(0xffffffffu, mx0, off));
            mx1 = fmaxf(mx1, __shfl_xor_sync(0xffffffffu, mx1, off));
        }
        float mn0 = fmaxf(m0r, mx0), mn1 = fmaxf(m1r, mx1);
        float cr0 = __expf(m0r - mn0), cr1 = __expf(m1r - mn1);
        float sum0 = 0.f, sum1 = 0.f;
        if (it == nch - 1) {
#pragma unroll
            for (int nt = 0; nt < 8; nt++) {
                float p0 = (s[nt][0] > -5e29f) ? __expf(s[nt][0] - mn0) : 0.f;
                float p1 = (s[nt][1] > -5e29f) ? __expf(s[nt][1] - mn0) : 0.f;
                float p2 = (s[nt][2] > -5e29f) ? __expf(s[nt][2] - mn1) : 0.f;
                float p3 = (s[nt][3] > -5e29f) ? __expf(s[nt][3] - mn1) : 0.f;
                s[nt][0] = p0; s[nt][1] = p1; s[nt][2] = p2; s[nt][3] = p3;
                sum0 += p0 + p1;
                sum1 += p2 + p3;
            }
        } else {
#pragma unroll
            for (int nt = 0; nt < 8; nt++) {
                float p0 = __expf(s[nt][0] - mn0);
                float p1 = __expf(s[nt][1] - mn0);
                float p2 = __expf(s[nt][2] - mn1);
                float p3 = __expf(s[nt][3] - mn1);
                s[nt][0] = p0; s[nt][1] = p1; s[nt][2] = p2; s[nt][3] = p3;
                sum0 += p0 + p1;
                sum1 += p2 + p3;
            }
        }
#pragma unroll
        for (int off = 1; off < 4; off <<= 1) {
            sum0 += __shfl_xor_sync(0xffffffffu, sum0, off);
            sum1 += __shfl_xor_sync(0xffffffffu, sum1, off);
        }
        l0r = l0r * cr0 + sum0;
        l1r = l1r * cr1 + sum1;
        m0r = mn0; m1r = mn1;
#pragma unroll
        for (int nt = 0; nt < 8; nt++) {
            acc[nt][0] *= cr0; acc[nt][1] *= cr0;
            acc[nt][2] *= cr1; acc[nt][3] *= cr1;
        }

        uint32_t pah[4][4];
#pragma unroll
        for (int c = 0; c < 4; c++) {
            pah[c][0] = pack2h(s[2 * c][0],     s[2 * c][1]);
            pah[c][1] = pack2h(s[2 * c][2],     s[2 * c][3]);
            pah[c][2] = pack2h(s[2 * c + 1][0], s[2 * c + 1][1]);
            pah[c][3] = pack2h(s[2 * c + 1][2], s[2 * c + 1][3]);
        }

#pragma unroll
        for (int c = 0; c < 4; c++) {
#pragma unroll
            for (int np = 0; np < 4; np++) {
                uint32_t vbh[4];
                uint32_t ro = (c * 16 + tr) * 144 + np * 32 + tc * 16;
                ldsm_x4_t(vbh, st + AT_VH + ro);
                mma_f16(acc[np * 2 + 0], pah[c], vbh[0], vbh[1]);
                mma_f16(acc[np * 2 + 1], pah[c], vbh[2], vbh[3]);
            }
        }
        __syncthreads();   // required: next prefetch rewrites this stage
        if (it + 2 < nch) load_stage(stg, (it + 2) * 64);
    }

    // ---- epilogue: ctx as fp16 ----
    float inv0 = (l0r > 0.f) ? (1.f / l0r) : 0.f;
    float inv1 = (l1r > 0.f) ? (1.f / l1r) : 0.f;
    int r0 = q0 + wid * 16 + (lane >> 2);
#pragma unroll
    for (int nt = 0; nt < 8; nt++) {
        int c = h * DK + nt * 8 + (lane & 3) * 2;
        size_t o0 = (size_t)(b * S + r0) * D + c;
        size_t o1 = (size_t)(b * S + r0 + 8) * D + c;
        *(uint32_t*)&Ch[o0] = pack2h(acc[nt][0] * inv0, acc[nt][1] * inv0);
        *(uint32_t*)&Ch[o1] = pack2h(acc[nt][2] * inv1, acc[nt][3] * inv1);
    }
}

// ---------------- launch ----------------
extern "C" void kernel_launch(void* const* d_in, const int* in_sizes, int n_in,
                              void* d_out, int out_size)
{
    const float* query = (const float*)d_in[0];
    const float* key   = (const float*)d_in[1];
    const float* value = (const float*)d_in[2];
    const int*   mask  = (const int*)d_in[3];
    const float* Wq = (const float*)d_in[4];
    const float* bq = (const float*)d_in[5];
    const float* Wk = (const float*)d_in[6];
    const float* bk = (const float*)d_in[7];
    const float* Wv = (const float*)d_in[8];
    const float* bv = (const float*)d_in[9];
    const float* Wo = (const float*)d_in[10];
    const float* bo = (const float*)d_in[11];
    float* out = (float*)d_out;

    __half *ah, *wh;
    int *gidx, *cnt;
    cudaGetSymbolAddress((void**)&ah, g_Ah);
    cudaGetSymbolAddress((void**)&wh, g_Wh);
    cudaGetSymbolAddress((void**)&gidx, g_gidx);
    cudaGetSymbolAddress((void**)&cnt, g_cnt);

    static int attr_set = 0;
    if (!attr_set) {
        cudaFuncSetAttribute(qkv_gemm_kernel,
                             cudaFuncAttributeMaxDynamicSharedMemorySize, GEMM_SMEM);
        cudaFuncSetAttribute(oproj_gemm_kernel,
                             cudaFuncAttributeMaxDynamicSharedMemorySize, GEMM_SMEM);
        cudaFuncSetAttribute(attn_mma_kernel,
                             cudaFuncAttributeMaxDynamicSharedMemorySize, ATTN_SMEM);
        attr_set = 1;
    }

    // 0: mask compaction
    compact_mask_kernel<<<B, 256>>>(mask, gidx, cnt);

    // 1: convert q input + 4 weights to fp16 in one launch
    FPtr5 cin;
    cin.p[0] = query; cin.p[1] = Wq; cin.p[2] = Wk; cin.p[3] = Wv; cin.p[4] = Wo;
    dim3 cv_grid((SZA / 4 + 1023) / 1024, 5);
    convert5_kernel<<<cv_grid, 256>>>(cin, ah, wh);

    // 2: gather+convert compact k/v inputs -> slots 1, 2
    dim3 g_grid(S, B);
    gather_convert_kv_kernel<<<g_grid, 128>>>(
        key, value, gidx, cnt,
        ah + (size_t)1 * SZA, ah + (size_t)2 * SZA);

    // 3: batched projections (single-pass; K/V early-exit past compact rows)
    QKVBias qb; qb.p[0] = bq; qb.p[1] = bk; qb.p[2] = bv;
    dim3 qkv_grid(GN / 128, M_ROWS / 128, 3);   // (8, 32, 3)
    qkv_gemm_kernel<<<qkv_grid, 256, GEMM_SMEM>>>(
        ah, wh, qb, cnt, ah + (size_t)3 * SZA);

    // 4: attention -> ctx slot 6
    dim3 attn_grid(S / 128, H, B);
    attn_mma_kernel<<<attn_grid, 256, ATTN_SMEM>>>(
        ah + (size_t)3 * SZA,
        ah + (size_t)4 * SZA,
        ah + (size_t)5 * SZA,
        cnt,
        ah + (size_t)6 * SZA);

    // 5: output projection (fp32 out, single wave)
    dim3 gemm_grid(GN / 128, M_ROWS / 128);     // (8, 32) = 256 CTAs
    oproj_gemm_kernel<<<gemm_grid, 256, GEMM_SMEM>>>(
        ah + (size_t)6 * SZA, wh + (size_t)3 * D * D, bo, out);
}

// round 16
// speedup vs baseline: 12.0689x; 1.0536x over previous
#include <cuda_runtime.h>
#include <cuda_fp16.h>
#include <math.h>
#include <stdint.h>

// Problem constants
#define B  2
#define S  2048
#define D  1024
#define H  16
#define DK 64
#define M_ROWS (B * S)   // 4096
#define GK 1024
#define GN 1024
#define SZA (M_ROWS * D)

// ---------------- scratch (device globals: allocation-free) ----------------
__device__ __half g_Ah[7][SZA];
__device__ __half g_Wh[4][D * D];   // weights fp16, layout [k][n]
__device__ int g_gidx[B * S];
__device__ int g_cnt[B];

struct FPtr5 { const float* p[5]; };

__device__ __forceinline__ uint32_t smem_u32(const void* p) {
    uint32_t a;
    asm("{ .reg .u64 t; cvta.to.shared.u64 t, %1; cvt.u32.u64 %0, t; }"
        : "=r"(a) : "l"(p));
    return a;
}
__device__ __forceinline__ void ldsm_x4(uint32_t (&r)[4], uint32_t addr) {
    asm volatile("ldmatrix.sync.aligned.m8n8.x4.shared.b16 {%0,%1,%2,%3}, [%4];"
                 : "=r"(r[0]), "=r"(r[1]), "=r"(r[2]), "=r"(r[3]) : "r"(addr));
}
__device__ __forceinline__ void ldsm_x4_t(uint32_t (&r)[4], uint32_t addr) {
    asm volatile("ldmatrix.sync.aligned.m8n8.x4.trans.shared.b16 {%0,%1,%2,%3}, [%4];"
                 : "=r"(r[0]), "=r"(r[1]), "=r"(r[2]), "=r"(r[3]) : "r"(addr));
}
__device__ __forceinline__ void mma_f16(float (&d)[4],
    const uint32_t (&a)[4], uint32_t b0, uint32_t b1)
{
    asm volatile(
        "mma.sync.aligned.m16n8k16.row.col.f32.f16.f16.f32 "
        "{%0,%1,%2,%3}, {%4,%5,%6,%7}, {%8,%9}, {%0,%1,%2,%3};"
        : "+f"(d[0]), "+f"(d[1]), "+f"(d[2]), "+f"(d[3])
        : "r"(a[0]), "r"(a[1]), "r"(a[2]), "r"(a[3]), "r"(b0), "r"(b1));
}
__device__ __forceinline__ void cpa16(uint32_t sd, const void* gs) {
    asm volatile("cp.async.cg.shared.global [%0], [%1], 16;" :: "r"(sd), "l"(gs));
}
__device__ __forceinline__ uint32_t pack2h(float f0, float f1) {
    __half h0 = __float2half(f0), h1 = __float2half(f1);
    return (uint32_t)*(uint16_t*)&h0 | ((uint32_t)*(uint16_t*)&h1 << 16);
}

// ---------------- mask compaction: per-batch prefix scan ----------------
__global__ __launch_bounds__(256) void compact_mask_kernel(
    const int* __restrict__ mask, int* __restrict__ gidx, int* __restrict__ cnt)
{
    __shared__ int wsum[8];
    const int b = blockIdx.x;
    const int tid = threadIdx.x, lane = tid & 31, wid = tid >> 5;
    int keep[8], local = 0;
#pragma unroll
    for (int i = 0; i < 8; i++) {
        keep[i] = (mask[b * S + tid * 8 + i] == 0);
        local += keep[i];
    }
    int v = local;
#pragma unroll
    for (int off = 1; off < 32; off <<= 1) {
        int n = __shfl_up_sync(0xffffffffu, v, off);
        if (lane >= off) v += n;
    }
    int excl = v - local;
    if (lane == 31) wsum[wid] = v;
    __syncthreads();
    if (wid == 0 && lane < 8) {
        int w = wsum[lane];
        int wv = w;
#pragma unroll
        for (int off = 1; off < 8; off <<= 1) {
            int n = __shfl_up_sync(0xffu, wv, off);
            if (lane >= off) wv += n;
        }
        wsum[lane] = wv - w;
        if (lane == 7) cnt[b] = wv;
    }
    __syncthreads();
    int base = wsum[wid] + excl;
#pragma unroll
    for (int i = 0; i < 8; i++)
        if (keep[i]) gidx[b * S + base++] = tid * 8 + i;
}

// ---------------- batched convert fp32->fp16: q input + 4 weights --------
__global__ __launch_bounds__(256) void convert5_kernel(
    FPtr5 X, __half* __restrict__ ah, __half* __restrict__ wh)
{
    const int z = blockIdx.y;
    const float* src = X.p[z];
    __half* dst = (z == 0) ? ah : wh + (size_t)(z - 1) * D * D;
    const int n4 = (z == 0) ? SZA / 4 : D * D / 4;
    int i = blockIdx.x * 1024 + threadIdx.x;
#pragma unroll
    for (int t = 0; t < 4; t++, i += 256) {
        if (i < n4) {
            float4 v = ((const float4*)src)[i];
            *(uint32_t*)&dst[i * 4 + 0] = pack2h(v.x, v.y);
            *(uint32_t*)&dst[i * 4 + 2] = pack2h(v.z, v.w);
        }
    }
}

// gather unmasked key/value input rows, convert fp16; zero-pad
__global__ __launch_bounds__(128) void gather_convert_kv_kernel(
    const float* __restrict__ keyIn, const float* __restrict__ valIn,
    const int* __restrict__ gidx, const int* __restrict__ cnt,
    __half* __restrict__ Kh, __half* __restrict__ Vh)
{
    const int b = blockIdx.y, pos = blockIdx.x, tid = threadIdx.x;
    const int c = cnt[b];
    const int cpad = (c + 63) & ~63;
    if (pos >= cpad) return;
    const size_t dst = (size_t)(b * S + pos) * D + tid * 8;
    if (pos < c) {
        const size_t src = (size_t)(b * S + gidx[b * S + pos]) * D + tid * 8;
        float4 k0 = *(const float4*)&keyIn[src];
        float4 k1 = *(const float4*)&keyIn[src + 4];
        float4 v0 = *(const float4*)&valIn[src];
        float4 v1 = *(const float4*)&valIn[src + 4];
        *(uint4*)&Kh[dst] = make_uint4(pack2h(k0.x, k0.y), pack2h(k0.z, k0.w),
                                       pack2h(k1.x, k1.y), pack2h(k1.z, k1.w));
        *(uint4*)&Vh[dst] = make_uint4(pack2h(v0.x, v0.y), pack2h(v0.z, v0.w),
                                       pack2h(v1.x, v1.y), pack2h(v1.z, v1.w));
    } else {
        uint4 z = make_uint4(0, 0, 0, 0);
        *(uint4*)&Kh[dst] = z;
        *(uint4*)&Vh[dst] = z;
    }
}

// ---------------- fp16 single-pass GEMM: 128x128 tile, BK=64, 3 stages ----
#define BK 64
#define NCH (GK / BK)            // 16
#define ASTRIDE 144              // 128B A data + 16B pad per row
#define BSTRIDE 272              // 256B B data + 16B pad per k-row
#define OFF_B  (128 * ASTRIDE)   // 18432
#define STAGE_SB (OFF_B + 64 * BSTRIDE)  // 35840
#define GEMM_SMEM (3 * STAGE_SB)         // 107520

__device__ __forceinline__ void gemm_body(
    const __half* __restrict__ Ah,
    const __half* __restrict__ W,   // [GK][GN] fp16
    const float* __restrict__ bias, float* __restrict__ C,
    __half* __restrict__ Ch,
    char* smem)
{
    const uint32_t sbase = smem_u32(smem);
    const int tid = threadIdx.x;
    const int lane = tid & 31;
    const int wid = tid >> 5;
    const int warp_m = wid & 3;
    const int warp_n = wid >> 2;
    const int m0 = blockIdx.y * 128;
    const int n0 = blockIdx.x * 128;

    const __half* gAh = Ah + (size_t)m0 * GK;

    auto load_stage = [&](int stg, int k0) {
        uint32_t sb = sbase + stg * STAGE_SB;
        // A: 128 rows x 128B (8 chunks/row) = 1024 chunks, 4/thread
#pragma unroll
        for (int j = 0; j < 4; j++) {
            int idx = tid + j * 256;
            int row = idx >> 3, ch = idx & 7;
            cpa16(sb + row * ASTRIDE + ch * 16,
                  gAh + (size_t)row * GK + k0 + ch * 8);
        }
        // B: 64 rows x 256B (16 chunks/row) = 1024 chunks, 4/thread
#pragma unroll
        for (int j = 0; j < 4; j++) {
            int idx = tid + j * 256;
            int row = idx >> 4, ch = idx & 15;
            cpa16(sb + OFF_B + row * BSTRIDE + ch * 16,
                  W + (size_t)(k0 + row) * GN + n0 + ch * 8);
        }
        asm volatile("cp.async.commit_group;");
    };

    float acc[2][8][4];
#pragma unroll
    for (int i = 0; i < 2; i++)
#pragma unroll
        for (int j = 0; j < 8; j++)
#pragma unroll
            for (int v = 0; v < 4; v++) acc[i][j][v] = 0.f;

    load_stage(0, 0);
    load_stage(1, BK);

    const int a_row = lane & 15;
    const int a_kc  = lane >> 4;
    const int tr    = lane & 15;
    const int tc    = lane >> 4;

    int stg = 0;
    for (int ch = 0; ch < NCH; ch++) {
        if (ch < NCH - 1) asm volatile("cp.async.wait_group 1;");
        else              asm volatile("cp.async.wait_group 0;");
        __syncthreads();
        if (ch + 2 < NCH) {
            int ns = stg + 2; if (ns >= 3) ns -= 3;
            load_stage(ns, (ch + 2) * BK);
        }
        const uint32_t st = sbase + stg * STAGE_SB;
#pragma unroll
        for (int kc = 0; kc < 4; kc++) {
            uint32_t a_h[2][4], b_t[4][4];
#pragma unroll
            for (int mt = 0; mt < 2; mt++) {
                uint32_t ro = (warp_m * 32 + mt * 16 + a_row) * ASTRIDE
                            + (kc * 2 + a_kc) * 16;
                ldsm_x4(a_h[mt], st + ro);
            }
#pragma unroll
            for (int ng = 0; ng < 4; ng++) {
                uint32_t ro = (kc * 16 + tr) * BSTRIDE
                            + warp_n * 128 + ng * 32 + tc * 16;
                ldsm_x4_t(b_t[ng], st + OFF_B + ro);
            }
#pragma unroll
            for (int mt = 0; mt < 2; mt++)
#pragma unroll
                for (int ng = 0; ng < 4; ng++) {
                    mma_f16(acc[mt][ng * 2 + 0], a_h[mt], b_t[ng][0], b_t[ng][1]);
                    mma_f16(acc[mt][ng * 2 + 1], a_h[mt], b_t[ng][2], b_t[ng][3]);
                }
        }
        if (++stg == 3) stg = 0;
    }

    const int grp = lane >> 2, tg = lane & 3;
#pragma unroll
    for (int mt = 0; mt < 2; mt++) {
        int r0 = m0 + warp_m * 32 + mt * 16 + grp;
#pragma unroll
        for (int nt = 0; nt < 8; nt++) {
            int c = n0 + warp_n * 64 + nt * 8 + tg * 2;
            float2 b2 = *(const float2*)&bias[c];
            float o00 = acc[mt][nt][0] + b2.x;
            float o01 = acc[mt][nt][1] + b2.y;
            float o10 = acc[mt][nt][2] + b2.x;
            float o11 = acc[mt][nt][3] + b2.y;
            if (C) {
                *(float2*)&C[(size_t)r0 * GN + c] = make_float2(o00, o01);
                *(float2*)&C[(size_t)(r0 + 8) * GN + c] = make_float2(o10, o11);
            } else {
                *(uint32_t*)&Ch[(size_t)r0 * GN + c] = pack2h(o00, o01);
                *(uint32_t*)&Ch[(size_t)(r0 + 8) * GN + c] = pack2h(o10, o11);
            }
        }
    }
}

struct QKVBias { const float* p[3]; };

__global__ __launch_bounds__(256, 2) void qkv_gemm_kernel(
    const __half* __restrict__ AhB, const __half* __restrict__ WhB,
    QKVBias bias, const int* __restrict__ cnt,
    __half* __restrict__ ChB)
{
    extern __shared__ char smem[];
    const int z = blockIdx.z;
    if (z > 0) {
        const int m0 = blockIdx.y * 128;
        const int b = m0 / S;
        const int cpad = (cnt[b] + 63) & ~63;
        if ((m0 % S) >= cpad) return;
    }
    gemm_body(AhB + (size_t)z * SZA, WhB + (size_t)z * D * D,
              bias.p[z], nullptr, ChB + (size_t)z * SZA, smem);
}

__global__ __launch_bounds__(256, 2) void oproj_gemm_kernel(
    const __half* __restrict__ Ah, const __half* __restrict__ Wh,
    const float* __restrict__ bias, float* __restrict__ C)
{
    extern __shared__ char smem[];
    gemm_body(Ah, Wh, bias, C, nullptr, smem);
}

// ---------------- Attention: fp16, 3-stage, single sync per chunk --------
#define ASTG 18432
#define AT_VH 9216
#define ATTN_SMEM (3 * ASTG)   // 55296

__global__ __launch_bounds__(256, 2) void attn_mma_kernel(
    const __half* __restrict__ Qh,
    const __half* __restrict__ Kh, const __half* __restrict__ Vh,
    const int* __restrict__ cnt,
    __half* __restrict__ Ch)
{
    extern __shared__ char smem[];
    const uint32_t sb = smem_u32(smem);
    const int tid = threadIdx.x, lane = tid & 31, wid = tid >> 5;
    const int b = blockIdx.z, h = blockIdx.y, q0 = blockIdx.x * 128;
    const int cn = cnt[b];
    const int nch = (cn + 63) >> 6;

    // ---- stage Q tile into smem once, ldsm to fragments ----
#pragma unroll
    for (int t = 0; t < 4; t++) {
        int idx = tid + t * 256;
        int row = idx >> 3, ch = idx & 7;
        const __half* src = Qh + (size_t)(b * S + q0 + row) * D + h * DK + ch * 8;
        *(uint4*)(smem + row * 144 + ch * 16) = *(const uint4*)src;
    }
    __syncthreads();
    uint32_t qfh[4][4];
    {
        int r = wid * 16 + (lane & 15);
        int hc = lane >> 4;
#pragma unroll
        for (int c = 0; c < 4; c++)
            ldsm_x4(qfh[c], sb + r * 144 + (c * 2 + hc) * 16);
    }
    __syncthreads();

    auto load_stage = [&](int stg, int kk) {
        uint32_t base = sb + stg * ASTG;
#pragma unroll
        for (int t = 0; t < 4; t++) {
            int idx = tid + t * 256;
            int tile = idx >> 9;
            int c = idx & 511;
            int row = c >> 3, ch = c & 7;
            const __half* g = (tile == 0 ? Kh : Vh)
                + (size_t)(b * S + kk + row) * D + h * DK + ch * 8;
            cpa16(base + tile * 9216 + row * 144 + ch * 16, g);
        }
        asm volatile("cp.async.commit_group;");
    };

    float acc[8][4];
#pragma unroll
    for (int j = 0; j < 8; j++)
#pragma unroll
        for (int v = 0; v < 4; v++) acc[j][v] = 0.f;
    float m0r = -1e30f, m1r = -1e30f, l0r = 0.f, l1r = 0.f;
    const float scale = 0.125f;

    if (nch >= 1) load_stage(0, 0);
    if (nch >= 2) load_stage(1, 64);

    const int bg    = lane >> 3;
    const int b_row = ((bg >> 1) * 8) + (lane & 7);
    const int b_kc  = bg & 1;
    const int tr    = lane & 15;
    const int tc    = lane >> 4;
    const int jlane = (lane & 3) * 2;

    int stg = 0;
    for (int it = 0; it < nch; it++) {
        if (it < nch - 1) asm volatile("cp.async.wait_group 1;");
        else              asm volatile("cp.async.wait_group 0;");
        __syncthreads();
        // distance-2 prefetch into the stage last used at it-1 (safe after sync)
        if (it + 2 < nch) {
            int ns = stg + 2; if (ns >= 3) ns -= 3;
            load_stage(ns, (it + 2) * 64);
        }

        const uint32_t st = sb + stg * ASTG;

        float s[8][4];
#pragma unroll
        for (int j = 0; j < 8; j++)
#pragma unroll
            for (int v = 0; v < 4; v++) s[j][v] = 0.f;
#pragma unroll
        for (int c = 0; c < 4; c++) {
#pragma unroll
            for (int np = 0; np < 4; np++) {
                uint32_t kbh[4];
                uint32_t ro = (np * 16 + b_row) * 144 + (c * 2 + b_kc) * 16;
                ldsm_x4(kbh, st + ro);
                mma_f16(s[np * 2 + 0], qfh[c], kbh[0], kbh[1]);
                mma_f16(s[np * 2 + 1], qfh[c], kbh[2], kbh[3]);
            }
        }

        // ---- online softmax; masking only on the final (tail) chunk ----
        float mx0 = -1e30f, mx1 = -1e30f;
        if (it == nch - 1) {
            const int jbase = it * 64 + jlane;
#pragma unroll
            for (int nt = 0; nt < 8; nt++) {
                int j0 = jbase + nt * 8;
                bool k0m = (j0 >= cn), k1m = (j0 + 1 >= cn);
                s[nt][0] = k0m ? -1e30f : s[nt][0] * scale;
                s[nt][1] = k1m ? -1e30f : s[nt][1] * scale;
                s[nt][2] = k0m ? -1e30f : s[nt][2] * scale;
                s[nt][3] = k1m ? -1e30f : s[nt][3] * scale;
                mx0 = fmaxf(mx0, fmaxf(s[nt][0], s[nt][1]));
                mx1 = fmaxf(mx1, fmaxf(s[nt][2], s[nt][3]));
            }
        } else {
#pragma unroll
            for (int nt = 0; nt < 8; nt++) {
                s[nt][0] *= scale; s[nt][1] *= scale;
                s[nt][2] *= scale; s[nt][3] *= scale;
                mx0 = fmaxf(mx0, fmaxf(s[nt][0], s[nt][1]));
                mx1 = fmaxf(mx1, fmaxf(s[nt][2], s[nt][3]));
            }
        }
#pragma unroll
        for (int off = 1; off < 4; off <<= 1) {
            mx0 = fmaxf(mx0, __shfl_xor_sync(0xffffffffu, mx0, off));
            mx1 = fmaxf(mx1, __shfl_xor_sync(0xffffffffu, mx1, off));
        }
        float mn0 = fmaxf(m0r, mx0), mn1 = fmaxf(m1r, mx1);
        float cr0 = __expf(m0r - mn0), cr1 = __expf(m1r - mn1);
        float sum0 = 0.f, sum1 = 0.f;
        if (it == nch - 1) {
#pragma unroll
            for (int nt = 0; nt < 8; nt++) {
                float p0 = (s[nt][0] > -5e29f) ? __expf(s[nt][0] - mn0) : 0.f;
                float p1 = (s[nt][1] > -5e29f) ? __expf(s[nt][1] - mn0) : 0.f;
                float p2 = (s[nt][2] > -5e29f) ? __expf(s[nt][2] - mn1) : 0.f;
                float p3 = (s[nt][3] > -5e29f) ? __expf(s[nt][3] - mn1) : 0.f;
                s[nt][0] = p0; s[nt][1] = p1; s[nt][2] = p2; s[nt][3] = p3;
                sum0 += p0 + p1;
                sum1 += p2 + p3;
            }
        } else {
#pragma unroll
            for (int nt = 0; nt < 8; nt++) {
                float p0 = __expf(s[nt][0] - mn0);
                float p1 = __expf(s[nt][1] - mn0);
                float p2 = __expf(s[nt][2] - mn1);
                float p3 = __expf(s[nt][3] - mn1);
                s[nt][0] = p0; s[nt][1] = p1; s[nt][2] = p2; s[nt][3] = p3;
                sum0 += p0 + p1;
                sum1 += p2 + p3;
            }
        }
#pragma unroll
        for (int off = 1; off < 4; off <<= 1) {
            sum0 += __shfl_xor_sync(0xffffffffu, sum0, off);
            sum1 += __shfl_xor_sync(0xffffffffu, sum1, off);
        }
        l0r = l0r * cr0 + sum0;
        l1r = l1r * cr1 + sum1;
        m0r = mn0; m1r = mn1;
#pragma unroll
        for (int nt = 0; nt < 8; nt++) {
            acc[nt][0] *= cr0; acc[nt][1] *= cr0;
            acc[nt][2] *= cr1; acc[nt][3] *= cr1;
        }

        uint32_t pah[4][4];
#pragma unroll
        for (int c = 0; c < 4; c++) {
            pah[c][0] = pack2h(s[2 * c][0],     s[2 * c][1]);
            pah[c][1] = pack2h(s[2 * c][2],     s[2 * c][3]);
            pah[c][2] = pack2h(s[2 * c + 1][0], s[2 * c + 1][1]);
            pah[c][3] = pack2h(s[2 * c + 1][2], s[2 * c + 1][3]);
        }

#pragma unroll
        for (int c = 0; c < 4; c++) {
#pragma unroll
            for (int np = 0; np < 4; np++) {
                uint32_t vbh[4];
                uint32_t ro = (c * 16 + tr) * 144 + np * 32 + tc * 16;
                ldsm_x4_t(vbh, st + AT_VH + ro);
                mma_f16(acc[np * 2 + 0], pah[c], vbh[0], vbh[1]);
                mma_f16(acc[np * 2 + 1], pah[c], vbh[2], vbh[3]);
            }
        }
        if (++stg == 3) stg = 0;
    }

    // ---- epilogue: ctx as fp16 ----
    float inv0 = (l0r > 0.f) ? (1.f / l0r) : 0.f;
    float inv1 = (l1r > 0.f) ? (1.f / l1r) : 0.f;
    int r0 = q0 + wid * 16 + (lane >> 2);
#pragma unroll
    for (int nt = 0; nt < 8; nt++) {
        int c = h * DK + nt * 8 + (lane & 3) * 2;
        size_t o0 = (size_t)(b * S + r0) * D + c;
        size_t o1 = (size_t)(b * S + r0 + 8) * D + c;
        *(uint32_t*)&Ch[o0] = pack2h(acc[nt][0] * inv0, acc[nt][1] * inv0);
        *(uint32_t*)&Ch[o1] = pack2h(acc[nt][2] * inv1, acc[nt][3] * inv1);
    }
}

// ---------------- launch ----------------
extern "C" void kernel_launch(void* const* d_in, const int* in_sizes, int n_in,
                              void* d_out, int out_size)
{
    const float* query = (const float*)d_in[0];
    const float* key   = (const float*)d_in[1];
    const float* value = (const float*)d_in[2];
    const int*   mask  = (const int*)d_in[3];
    const float* Wq = (const float*)d_in[4];
    const float* bq = (const float*)d_in[5];
    const float* Wk = (const float*)d_in[6];
    const float* bk = (const float*)d_in[7];
    const float* Wv = (const float*)d_in[8];
    const float* bv = (const float*)d_in[9];
    const float* Wo = (const float*)d_in[10];
    const float* bo = (const float*)d_in[11];
    float* out = (float*)d_out;

    __half *ah, *wh;
    int *gidx, *cnt;
    cudaGetSymbolAddress((void**)&ah, g_Ah);
    cudaGetSymbolAddress((void**)&wh, g_Wh);
    cudaGetSymbolAddress((void**)&gidx, g_gidx);
    cudaGetSymbolAddress((void**)&cnt, g_cnt);

    static int attr_set = 0;
    if (!attr_set) {
        cudaFuncSetAttribute(qkv_gemm_kernel,
                             cudaFuncAttributeMaxDynamicSharedMemorySize, GEMM_SMEM);
        cudaFuncSetAttribute(oproj_gemm_kernel,
                             cudaFuncAttributeMaxDynamicSharedMemorySize, GEMM_SMEM);
        cudaFuncSetAttribute(attn_mma_kernel,
                             cudaFuncAttributeMaxDynamicSharedMemorySize, ATTN_SMEM);
        attr_set = 1;
    }

    // 0: mask compaction
    compact_mask_kernel<<<B, 256>>>(mask, gidx, cnt);

    // 1: convert q input + 4 weights to fp16 in one launch
    FPtr5 cin;
    cin.p[0] = query; cin.p[1] = Wq; cin.p[2] = Wk; cin.p[3] = Wv; cin.p[4] = Wo;
    dim3 cv_grid((SZA / 4 + 1023) / 1024, 5);
    convert5_kernel<<<cv_grid, 256>>>(cin, ah, wh);

    // 2: gather+convert compact k/v inputs -> slots 1, 2
    dim3 g_grid(S, B);
    gather_convert_kv_kernel<<<g_grid, 128>>>(
        key, value, gidx, cnt,
        ah + (size_t)1 * SZA, ah + (size_t)2 * SZA);

    // 3: batched projections (single-pass; K/V early-exit past compact rows)
    QKVBias qb; qb.p[0] = bq; qb.p[1] = bk; qb.p[2] = bv;
    dim3 qkv_grid(GN / 128, M_ROWS / 128, 3);   // (8, 32, 3)
    qkv_gemm_kernel<<<qkv_grid, 256, GEMM_SMEM>>>(
        ah, wh, qb, cnt, ah + (size_t)3 * SZA);

    // 4: attention -> ctx slot 6
    dim3 attn_grid(S / 128, H, B);
    attn_mma_kernel<<<attn_grid, 256, ATTN_SMEM>>>(
        ah + (size_t)3 * SZA,
        ah + (size_t)4 * SZA,
        ah + (size_t)5 * SZA,
        cnt,
        ah + (size_t)6 * SZA);

    // 5: output projection (fp32 out, single wave)
    dim3 gemm_grid(GN / 128, M_ROWS / 128);     // (8, 32) = 256 CTAs
    oproj_gemm_kernel<<<gemm_grid, 256, GEMM_SMEM>>>(
        ah + (size_t)6 * SZA, wh + (size_t)3 * D * D, bo, out);
}